// round 7
// baseline (speedup 1.0000x reference)
#include <cuda_runtime.h>
#include <cuda_bf16.h>
#include <cuda_fp16.h>
#include <math.h>
#include <stdint.h>

#define DIM    768
#define DEPTH  6
#define HEADS  12
#define DHEAD  64
#define INNER  768
#define MLPD   3072
#define BATCH  4
#define SEQ    2048
#define TOK    (BATCH*SEQ)      /* 8192 */
#define QKVD   (3*INNER)        /* 2304 */
#define QSCALE 0.18033688011112042f   /* 0.125 * log2(e) */
#define LSCALE 4096.0f
#define ILSCALE (1.0f/4096.0f)

// ---------------- scratch (device globals; no allocations) ----------------
__device__ float g_x  [(size_t)TOK*DIM];     // residual stream fp32
__device__ __nv_bfloat16 g_qkvh[(size_t)TOK*QKVD];   // attention input hi
__device__ __nv_bfloat16 g_qkvl[(size_t)TOK*QKVD];   // attention input lo
// activations: fp16 hi + interleaved fp8 pair [Al8|Ah8]
__device__ __half    g_lnh[(size_t)TOK*DIM];
__device__ uint16_t  g_ln8[(size_t)TOK*DIM];
__device__ __half    g_cth[(size_t)TOK*DIM];
__device__ uint16_t  g_ct8[(size_t)TOK*DIM];
__device__ __half    g_hh [(size_t)TOK*MLPD];
__device__ uint16_t  g_h8 [(size_t)TOK*MLPD];
// transposed weights [layer][N][K]: fp16 hi + interleaved fp8 pair [Bh8|Bl8]
__device__ __half    g_wqkvt_h[(size_t)DEPTH*QKVD*DIM];
__device__ uint16_t  g_wqkvt_8[(size_t)DEPTH*QKVD*DIM];
__device__ __half    g_woutt_h[(size_t)DEPTH*DIM*INNER];
__device__ uint16_t  g_woutt_8[(size_t)DEPTH*DIM*INNER];
__device__ __half    g_w1t_h [(size_t)DEPTH*MLPD*DIM];
__device__ uint16_t  g_w1t_8 [(size_t)DEPTH*MLPD*DIM];
__device__ __half    g_w2t_h [(size_t)DEPTH*DIM*MLPD];
__device__ uint16_t  g_w2t_8 [(size_t)DEPTH*DIM*MLPD];

// ====================== PTX helpers =======================================
__device__ __forceinline__ uint32_t smem_u32(const void* p){
    uint32_t a;
    asm("{ .reg .u64 t; cvta.to.shared.u64 t, %1; cvt.u32.u64 %0, t; }"
        : "=r"(a) : "l"(p));
    return a;
}
__device__ __forceinline__ void cp16(uint32_t s, const void* g){
    asm volatile("cp.async.cg.shared.global [%0], [%1], 16;" :: "r"(s), "l"(g));
}
#define CP_COMMIT() asm volatile("cp.async.commit_group;" ::: "memory")
#define CP_WAIT1()  asm volatile("cp.async.wait_group 1;" ::: "memory")
#define CP_WAIT0()  asm volatile("cp.async.wait_group 0;" ::: "memory")

__device__ __forceinline__ void ldmx4(uint32_t addr, uint32_t& r0, uint32_t& r1,
                                      uint32_t& r2, uint32_t& r3){
    asm volatile("ldmatrix.sync.aligned.m8n8.x4.shared.b16 {%0,%1,%2,%3}, [%4];"
        : "=r"(r0), "=r"(r1), "=r"(r2), "=r"(r3) : "r"(addr));
}
__device__ __forceinline__ void ldmx4t(uint32_t addr, uint32_t& r0, uint32_t& r1,
                                       uint32_t& r2, uint32_t& r3){
    asm volatile("ldmatrix.sync.aligned.m8n8.x4.trans.shared.b16 {%0,%1,%2,%3}, [%4];"
        : "=r"(r0), "=r"(r1), "=r"(r2), "=r"(r3) : "r"(addr));
}
// bf16 mma (attention)
__device__ __forceinline__ void mma16816(float* c, const uint32_t* a,
                                         uint32_t b0, uint32_t b1){
    asm volatile(
        "mma.sync.aligned.m16n8k16.row.col.f32.bf16.bf16.f32 "
        "{%0,%1,%2,%3}, {%4,%5,%6,%7}, {%8,%9}, {%0,%1,%2,%3};"
        : "+f"(c[0]), "+f"(c[1]), "+f"(c[2]), "+f"(c[3])
        : "r"(a[0]), "r"(a[1]), "r"(a[2]), "r"(a[3]), "r"(b0), "r"(b1));
}
// fp16 mma (GEMM main product)
__device__ __forceinline__ void mma16816h(float* c, const uint32_t* a,
                                          uint32_t b0, uint32_t b1){
    asm volatile(
        "mma.sync.aligned.m16n8k16.row.col.f32.f16.f16.f32 "
        "{%0,%1,%2,%3}, {%4,%5,%6,%7}, {%8,%9}, {%0,%1,%2,%3};"
        : "+f"(c[0]), "+f"(c[1]), "+f"(c[2]), "+f"(c[3])
        : "r"(a[0]), "r"(a[1]), "r"(a[2]), "r"(a[3]), "r"(b0), "r"(b1));
}
// fp8 e4m3 mma (GEMM correction product)
__device__ __forceinline__ void mma16832q(float* c, const uint32_t* a,
                                          uint32_t b0, uint32_t b1){
    asm volatile(
        "mma.sync.aligned.m16n8k32.row.col.f32.e4m3.e4m3.f32 "
        "{%0,%1,%2,%3}, {%4,%5,%6,%7}, {%8,%9}, {%0,%1,%2,%3};"
        : "+f"(c[0]), "+f"(c[1]), "+f"(c[2]), "+f"(c[3])
        : "r"(a[0]), "r"(a[1]), "r"(a[2]), "r"(a[3]), "r"(b0), "r"(b1));
}
// pack two f32 into e4m3x2: upper byte = a, lower byte = b
__device__ __forceinline__ uint16_t cvt_fp8x2(float a_upper, float b_lower){
    uint16_t r;
    asm("cvt.rn.satfinite.e4m3x2.f32 %0, %1, %2;"
        : "=h"(r) : "f"(a_upper), "f"(b_lower));
    return r;
}
// activation pack: [lower=Al8, upper=Ah8]
__device__ __forceinline__ uint16_t pack_act8(float v, float hf){
    return cvt_fp8x2(v, (v - hf) * LSCALE);   // upper = fp8(v)... see note
}
// NOTE on byte order: interleave convention is byte(2k)=lower, byte(2k+1)=upper.
// Activations: lower must be Al8(scaled lo), upper Ah8(full).  -> cvt(a=v, b=lo)
// Weights:     lower must be Bh8(full),      upper Bl8(scaled lo). -> cvt(a=lo, b=v)

// FMA-pipe exp2 (degree-6 Taylor on [-0.5,0.5]); valid for t <= 0
__device__ __forceinline__ float exp2_fast(float t){
    t = fmaxf(t, -120.f);
    float n = rintf(t);
    float f = t - n;
    float p = 1.5403530e-4f;
    p = fmaf(p, f, 1.3333558e-3f);
    p = fmaf(p, f, 9.6181291e-3f);
    p = fmaf(p, f, 5.5504109e-2f);
    p = fmaf(p, f, 2.4022651e-1f);
    p = fmaf(p, f, 6.9314718e-1f);
    p = fmaf(p, f, 1.0f);
    return __int_as_float(__float_as_int(p) + (((int)n) << 23));
}

// ====================== weight transpose + fp16/fp8 split ==================
// W[z][K][N] fp32 -> Wh[z][N][K] fp16, W8[z][N][K] fp8-pair [Bh8|Bl8]
__global__ void transpose_cvt(const float* __restrict__ W,
                              __half* __restrict__ Wh,
                              uint16_t* __restrict__ W8, int K, int N)
{
    __shared__ float tile[32][33];
    const size_t off = (size_t)blockIdx.z * K * N;
    const int n0 = blockIdx.x * 32, k0 = blockIdx.y * 32;
    const int tx = threadIdx.x, ty = threadIdx.y;
#pragma unroll
    for (int i = 0; i < 32; i += 8)
        tile[ty + i][tx] = W[off + (size_t)(k0 + ty + i) * N + n0 + tx];
    __syncthreads();
#pragma unroll
    for (int i = 0; i < 32; i += 8) {
        float v = tile[tx][ty + i];
        __half h = __float2half_rn(v);
        size_t oidx = off + (size_t)(n0 + ty + i) * K + k0 + tx;
        Wh[oidx] = h;
        W8[oidx] = cvt_fp8x2((v - __half2float(h)) * LSCALE, v); // upper=Bl8, lower=Bh8
    }
}

// ====================== LayerNorm ==========================================
template<bool HOUT>
__global__ void ln_kernel(const float* __restrict__ x, const float* __restrict__ g,
                          const float* __restrict__ b, float* __restrict__ y,
                          __half* __restrict__ yh, uint16_t* __restrict__ y8)
{
    int t = blockIdx.x;
    const float* xp = x + (size_t)t * DIM;

    float v[3];
    float s1 = 0.f, s2 = 0.f;
#pragma unroll
    for (int i = 0; i < 3; i++) {
        v[i] = xp[threadIdx.x + i * 256];
        s1 += v[i]; s2 += v[i] * v[i];
    }
#pragma unroll
    for (int o = 16; o > 0; o >>= 1) {
        s1 += __shfl_xor_sync(0xffffffffu, s1, o);
        s2 += __shfl_xor_sync(0xffffffffu, s2, o);
    }
    __shared__ float r1[8], r2[8];
    if ((threadIdx.x & 31) == 0) { r1[threadIdx.x >> 5] = s1; r2[threadIdx.x >> 5] = s2; }
    __syncthreads();
    s1 = 0.f; s2 = 0.f;
#pragma unroll
    for (int i = 0; i < 8; i++) { s1 += r1[i]; s2 += r2[i]; }

    float mu  = s1 * (1.f / DIM);
    float var = s2 * (1.f / DIM) - mu * mu;
    float rs  = rsqrtf(var + 1e-5f);
#pragma unroll
    for (int i = 0; i < 3; i++) {
        int d = threadIdx.x + i * 256;
        float yy = (v[i] - mu) * rs * g[d] + b[d];
        if (HOUT) {
            __half h = __float2half_rn(yy);
            yh[(size_t)t * DIM + d] = h;
            y8[(size_t)t * DIM + d] =
                cvt_fp8x2(yy, (yy - __half2float(h)) * LSCALE); // upper=Ah8, lower=Al8
        } else {
            y[(size_t)t * DIM + d] = yy;
        }
    }
}

// ====================== fp16+fp8 2-product GEMM ============================
// C[M,N] = A[M,K] @ Bt[N,K]^T.  A: fp16 hi + fp8 pair; Bt: fp16 hi + fp8 pair.
// CTA 128x128, BK=32, 3-stage cp.async (r4-proven shape).
// Stage layout: [A16 8K][A8 8K][B16 8K][B8 8K] = 32KB.
// EPI: 0 = qkv out (scale Q cols, bf16 hi/lo to Qh/Ql);
//      1 = +bias, gelu, fp16+fp8 out (Ch/C8);
//      2 = +bias += xres; 3 = += xres.
template<int EPI>
__global__ void __launch_bounds__(256, 1)
gemm_mma(const __half* __restrict__ Ah, const uint16_t* __restrict__ A8,
         const __half* __restrict__ Bh, const uint16_t* __restrict__ B8,
         const float* __restrict__ bias, float* __restrict__ xres,
         __half* __restrict__ Ch, uint16_t* __restrict__ C8,
         __nv_bfloat16* __restrict__ Qh, __nv_bfloat16* __restrict__ Ql,
         int M, int N, int K)
{
    extern __shared__ char smem[];
    const uint32_t sb0 = smem_u32(smem);
    const int tid  = threadIdx.x;
    const int lane = tid & 31, warp = tid >> 5;
    const int wm = warp >> 1, wn = warp & 1;
    const int bn = blockIdx.x, bm = blockIdx.y;
    const int nkt = K >> 5;

    auto load_stage = [&](int kt, int st){
        const uint32_t base = sb0 + (uint32_t)st * 32768u;
        const size_t kof = (size_t)kt * 32;
#pragma unroll
        for (int i = 0; i < 2; i++) {
            const int idx = tid + i * 256;
            const int row = idx >> 2, c = idx & 3;
            const uint32_t so = (uint32_t)(row * 64 + ((c ^ ((row >> 1) & 3)) << 4));
            const size_t ga = (size_t)(bm * 128 + row) * K + kof + c * 8;
            const size_t gb = (size_t)(bn * 128 + row) * K + kof + c * 8;
            cp16(base + so,          Ah + ga);
            cp16(base + 8192u + so,  A8 + ga);
            cp16(base + 16384u + so, Bh + gb);
            cp16(base + 24576u + so, B8 + gb);
        }
    };

    float acc [2][8][4];
    float acc8[2][8][4];
#pragma unroll
    for (int mt = 0; mt < 2; mt++)
#pragma unroll
        for (int nt = 0; nt < 8; nt++)
#pragma unroll
            for (int q = 0; q < 4; q++) { acc[mt][nt][q] = 0.f; acc8[mt][nt][q] = 0.f; }

    load_stage(0, 0); CP_COMMIT();
    load_stage(1, 1); CP_COMMIT();

    const int arow = wm * 32 + (lane & 15);
    const int acs  = lane >> 4;
    const int brow = wn * 64 + (lane & 7) + ((lane >> 4) << 3);
    const int bcs  = (lane >> 3) & 1;

    for (int kt = 0; kt < nkt; kt++) {
        if (kt == nkt - 1) { CP_WAIT0(); } else { CP_WAIT1(); }
        __syncthreads();
        if (kt + 2 < nkt) { load_stage(kt + 2, (kt + 2) % 3); CP_COMMIT(); }

        const uint32_t base = sb0 + (uint32_t)(kt % 3) * 32768u;
#pragma unroll
        for (int ks = 0; ks < 2; ks++) {
            uint32_t ah[2][4], a8[2][4];
#pragma unroll
            for (int mt = 0; mt < 2; mt++) {
                const int r = arow + mt * 16;
                const int c = ks * 2 + acs;
                const uint32_t off = (uint32_t)(r * 64 + ((c ^ ((r >> 1) & 3)) << 4));
                ldmx4(base + off,         ah[mt][0], ah[mt][1], ah[mt][2], ah[mt][3]);
                ldmx4(base + 8192u + off, a8[mt][0], a8[mt][1], a8[mt][2], a8[mt][3]);
            }
#pragma unroll
            for (int bt = 0; bt < 4; bt++) {
                const int r = brow + bt * 16;
                const int c = ks * 2 + bcs;
                const uint32_t off = (uint32_t)(r * 64 + ((c ^ ((r >> 1) & 3)) << 4));
                uint32_t bh[4], b8[4];
                ldmx4(base + 16384u + off, bh[0], bh[1], bh[2], bh[3]);
                ldmx4(base + 24576u + off, b8[0], b8[1], b8[2], b8[3]);
#pragma unroll
                for (int mt = 0; mt < 2; mt++) {
                    mma16816h(acc [mt][2*bt],   ah[mt], bh[0], bh[1]);
                    mma16832q(acc8[mt][2*bt],   a8[mt], b8[0], b8[1]);
                    mma16816h(acc [mt][2*bt+1], ah[mt], bh[2], bh[3]);
                    mma16832q(acc8[mt][2*bt+1], a8[mt], b8[2], b8[3]);
                }
            }
        }
        __syncthreads();
    }

    const int rbase = bm * 128 + wm * 32 + (lane >> 2);
    const int cbase = bn * 128 + wn * 64 + (lane & 3) * 2;
#pragma unroll
    for (int mt = 0; mt < 2; mt++) {
#pragma unroll
        for (int nt = 0; nt < 8; nt++) {
            const int gcol = cbase + nt * 8;
#pragma unroll
            for (int h = 0; h < 2; h++) {
                const int grow = rbase + mt * 16 + h * 8;
                float v0 = acc[mt][nt][2*h]   + acc8[mt][nt][2*h]   * ILSCALE;
                float v1 = acc[mt][nt][2*h+1] + acc8[mt][nt][2*h+1] * ILSCALE;
                const size_t oidx = (size_t)grow * N + gcol;
                if (EPI == 0) {
                    const float sc = (gcol < INNER) ? QSCALE : 1.f;
                    v0 *= sc; v1 *= sc;
                    __nv_bfloat16 h0 = __float2bfloat16(v0), h1 = __float2bfloat16(v1);
                    __nv_bfloat16 l0 = __float2bfloat16(v0 - __bfloat162float(h0));
                    __nv_bfloat16 l1 = __float2bfloat16(v1 - __bfloat162float(h1));
                    *reinterpret_cast<uint32_t*>(Qh + oidx) =
                        (uint32_t)__bfloat16_as_ushort(h0) |
                        ((uint32_t)__bfloat16_as_ushort(h1) << 16);
                    *reinterpret_cast<uint32_t*>(Ql + oidx) =
                        (uint32_t)__bfloat16_as_ushort(l0) |
                        ((uint32_t)__bfloat16_as_ushort(l1) << 16);
                } else if (EPI == 1) {
                    v0 += bias[gcol];     v1 += bias[gcol + 1];
                    v0 = 0.5f * v0 * (1.f + erff(v0 * 0.70710678118654752f));
                    v1 = 0.5f * v1 * (1.f + erff(v1 * 0.70710678118654752f));
                    __half h0 = __float2half_rn(v0), h1 = __float2half_rn(v1);
                    uint16_t q0 = cvt_fp8x2(v0, (v0 - __half2float(h0)) * LSCALE);
                    uint16_t q1 = cvt_fp8x2(v1, (v1 - __half2float(h1)) * LSCALE);
                    *reinterpret_cast<uint32_t*>(Ch + oidx) =
                        (uint32_t)__half_as_ushort(h0) |
                        ((uint32_t)__half_as_ushort(h1) << 16);
                    *reinterpret_cast<uint32_t*>(C8 + oidx) =
                        (uint32_t)q0 | ((uint32_t)q1 << 16);
                } else {
                    float2 xv = *reinterpret_cast<const float2*>(xres + oidx);
                    if (EPI == 2) { v0 += bias[gcol]; v1 += bias[gcol + 1]; }
                    xv.x += v0; xv.y += v1;
                    *reinterpret_cast<float2*>(xres + oidx) = xv;
                }
            }
        }
    }
}

// ====================== HMMA flash attention (bf16, unchanged core) ========
// grid (SEQ/128, HEADS, BATCH), 256 threads (8 warps x 16 query rows).
#define ATTN_SMEM (32768 + 2*32768)
__global__ void __launch_bounds__(256, 1)
attn_mma(const __nv_bfloat16* __restrict__ qg_h, const __nv_bfloat16* __restrict__ qg_l,
         __half* __restrict__ ch, uint16_t* __restrict__ c8)
{
    extern __shared__ char smem[];
    const uint32_t sb = smem_u32(smem);
    const uint32_t QH = sb, QL = sb + 16384u;
    const int tid = threadIdx.x, lane = tid & 31, wid = tid >> 5;
    const int b = blockIdx.z, h = blockIdx.y, qt = blockIdx.x;
    const int tok0 = b * SEQ + qt * 128;

#pragma unroll
    for (int i = 0; i < 4; i++) {
        const int idx = tid + i * 256;
        const int row = idx >> 3, c = idx & 7;
        const uint32_t so = (uint32_t)(row * 128 + ((c ^ (row & 7)) << 4));
        const size_t g = (size_t)(tok0 + row) * QKVD + h * DHEAD + c * 8;
        cp16(QH + so, qg_h + g);
        cp16(QL + so, qg_l + g);
    }

    auto load_kv = [&](int t, int st){
        const uint32_t base = sb + 32768u + (uint32_t)st * 32768u;
        const int kv0 = b * SEQ + t * 64;
#pragma unroll
        for (int i = 0; i < 2; i++) {
            const int idx = tid + i * 256;
            const int row = idx >> 3, c = idx & 7;
            const uint32_t so = (uint32_t)(row * 128 + ((c ^ (row & 7)) << 4));
            const size_t gk = (size_t)(kv0 + row) * QKVD + INNER + h * DHEAD + c * 8;
            const size_t gv = (size_t)(kv0 + row) * QKVD + 2 * INNER + h * DHEAD + c * 8;
            cp16(base + so,          qg_h + gk);
            cp16(base + 8192u  + so, qg_l + gk);
            cp16(base + 16384u + so, qg_h + gv);
            cp16(base + 24576u + so, qg_l + gv);
        }
    };
    load_kv(0, 0); CP_COMMIT();

    float O[8][4];
#pragma unroll
    for (int nt = 0; nt < 8; nt++)
#pragma unroll
        for (int q = 0; q < 4; q++) O[nt][q] = 0.f;
    float m0 = -1e30f, m1 = -1e30f, l0 = 0.f, l1 = 0.f;
    const int m0row = wid * 16;

    const int NT = SEQ / 64;
    for (int t = 0; t < NT; t++) {
        if (t + 1 < NT) { load_kv(t + 1, (t + 1) & 1); CP_COMMIT(); CP_WAIT1(); }
        else            { CP_WAIT0(); }
        __syncthreads();
        const uint32_t kb = sb + 32768u + (uint32_t)(t & 1) * 32768u;

        float S[8][4];
#pragma unroll
        for (int nt = 0; nt < 8; nt++)
#pragma unroll
            for (int q = 0; q < 4; q++) S[nt][q] = 0.f;
#pragma unroll
        for (int ks = 0; ks < 4; ks++) {
            uint32_t ah[4], al_[4];
            {
                const int r = m0row + (lane & 15);
                const int c = ks * 2 + (lane >> 4);
                const uint32_t off = (uint32_t)(r * 128 + ((c ^ (r & 7)) << 4));
                ldmx4(QH + off, ah[0], ah[1], ah[2], ah[3]);
                ldmx4(QL + off, al_[0], al_[1], al_[2], al_[3]);
            }
#pragma unroll
            for (int bt = 0; bt < 4; bt++) {
                const int r = bt * 16 + (lane & 7) + ((lane >> 4) << 3);
                const int c = ks * 2 + ((lane >> 3) & 1);
                const uint32_t off = (uint32_t)(r * 128 + ((c ^ (r & 7)) << 4));
                uint32_t kh[4], kl[4];
                ldmx4(kb + off,         kh[0], kh[1], kh[2], kh[3]);
                ldmx4(kb + 8192u + off, kl[0], kl[1], kl[2], kl[3]);
                mma16816(S[2*bt],   ah,  kh[0], kh[1]);
                mma16816(S[2*bt],   ah,  kl[0], kl[1]);
                mma16816(S[2*bt],   al_, kh[0], kh[1]);
                mma16816(S[2*bt+1], ah,  kh[2], kh[3]);
                mma16816(S[2*bt+1], ah,  kl[2], kl[3]);
                mma16816(S[2*bt+1], al_, kh[2], kh[3]);
            }
        }

        float mt0 = -1e30f, mt1 = -1e30f;
#pragma unroll
        for (int nt = 0; nt < 8; nt++) {
            mt0 = fmaxf(mt0, fmaxf(S[nt][0], S[nt][1]));
            mt1 = fmaxf(mt1, fmaxf(S[nt][2], S[nt][3]));
        }
        mt0 = fmaxf(mt0, __shfl_xor_sync(0xffffffffu, mt0, 1));
        mt0 = fmaxf(mt0, __shfl_xor_sync(0xffffffffu, mt0, 2));
        mt1 = fmaxf(mt1, __shfl_xor_sync(0xffffffffu, mt1, 1));
        mt1 = fmaxf(mt1, __shfl_xor_sync(0xffffffffu, mt1, 2));
        const float mn0 = fmaxf(m0, mt0), mn1 = fmaxf(m1, mt1);
        const float cr0 = exp2_fast(m0 - mn0), cr1 = exp2_fast(m1 - mn1);
        m0 = mn0; m1 = mn1;

        uint32_t phi[4][4], plo[4][4];
        float s0 = 0.f, s1 = 0.f;
#pragma unroll
        for (int nt = 0; nt < 8; nt++) {
            float p0 = exp2_fast(S[nt][0] - m0);
            float p1 = exp2_fast(S[nt][1] - m0);
            float p2 = exp2_fast(S[nt][2] - m1);
            float p3 = exp2_fast(S[nt][3] - m1);
            s0 += p0 + p1; s1 += p2 + p3;
            __nv_bfloat16 h0 = __float2bfloat16(p0), h1 = __float2bfloat16(p1);
            __nv_bfloat16 h2 = __float2bfloat16(p2), h3 = __float2bfloat16(p3);
            const int t2 = nt >> 1, o = (nt & 1) * 2;
            phi[t2][o] = (uint32_t)__bfloat16_as_ushort(h0) |
                         ((uint32_t)__bfloat16_as_ushort(h1) << 16);
            phi[t2][o+1] = (uint32_t)__bfloat16_as_ushort(h2) |
                           ((uint32_t)__bfloat16_as_ushort(h3) << 16);
            __nv_bfloat16 e0 = __float2bfloat16(p0 - __bfloat162float(h0));
            __nv_bfloat16 e1 = __float2bfloat16(p1 - __bfloat162float(h1));
            __nv_bfloat16 e2 = __float2bfloat16(p2 - __bfloat162float(h2));
            __nv_bfloat16 e3 = __float2bfloat16(p3 - __bfloat162float(h3));
            plo[t2][o] = (uint32_t)__bfloat16_as_ushort(e0) |
                         ((uint32_t)__bfloat16_as_ushort(e1) << 16);
            plo[t2][o+1] = (uint32_t)__bfloat16_as_ushort(e2) |
                           ((uint32_t)__bfloat16_as_ushort(e3) << 16);
        }
        s0 += __shfl_xor_sync(0xffffffffu, s0, 1);
        s0 += __shfl_xor_sync(0xffffffffu, s0, 2);
        s1 += __shfl_xor_sync(0xffffffffu, s1, 1);
        s1 += __shfl_xor_sync(0xffffffffu, s1, 2);
        l0 = l0 * cr0 + s0;
        l1 = l1 * cr1 + s1;
#pragma unroll
        for (int nt = 0; nt < 8; nt++) {
            O[nt][0] *= cr0; O[nt][1] *= cr0;
            O[nt][2] *= cr1; O[nt][3] *= cr1;
        }

#pragma unroll
        for (int t2 = 0; t2 < 4; t2++) {
#pragma unroll
            for (int dn = 0; dn < 4; dn++) {
                const int r = t2 * 16 + (lane & 15);
                const int c = dn * 2 + (lane >> 4);
                const uint32_t off = (uint32_t)(r * 128 + ((c ^ (r & 7)) << 4));
                uint32_t vh[4], vl[4];
                ldmx4t(kb + 16384u + off, vh[0], vh[1], vh[2], vh[3]);
                ldmx4t(kb + 24576u + off, vl[0], vl[1], vl[2], vl[3]);
                mma16816(O[2*dn],   phi[t2], vh[0], vh[1]);
                mma16816(O[2*dn],   plo[t2], vh[0], vh[1]);
                mma16816(O[2*dn],   phi[t2], vl[0], vl[1]);
                mma16816(O[2*dn+1], phi[t2], vh[2], vh[3]);
                mma16816(O[2*dn+1], plo[t2], vh[2], vh[3]);
                mma16816(O[2*dn+1], phi[t2], vl[2], vl[3]);
            }
        }
        __syncthreads();
    }

    // ---- epilogue: normalize, write ctx as fp16 + fp8 pair ----
    const float i0 = 1.f / l0, i1 = 1.f / l1;
    const int r0 = tok0 + m0row + (lane >> 2);
#pragma unroll
    for (int nt = 0; nt < 8; nt++) {
        const int col = h * DHEAD + nt * 8 + (lane & 3) * 2;
#pragma unroll
        for (int hh = 0; hh < 2; hh++) {
            const float inv = hh ? i1 : i0;
            float v0 = O[nt][2*hh] * inv, v1 = O[nt][2*hh+1] * inv;
            __half h0 = __float2half_rn(v0), h1 = __float2half_rn(v1);
            uint16_t q0 = cvt_fp8x2(v0, (v0 - __half2float(h0)) * LSCALE);
            uint16_t q1 = cvt_fp8x2(v1, (v1 - __half2float(h1)) * LSCALE);
            const size_t oidx = (size_t)(r0 + hh * 8) * DIM + col;
            *reinterpret_cast<uint32_t*>(ch + oidx) =
                (uint32_t)__half_as_ushort(h0) |
                ((uint32_t)__half_as_ushort(h1) << 16);
            *reinterpret_cast<uint32_t*>(c8 + oidx) =
                (uint32_t)q0 | ((uint32_t)q1 << 16);
        }
    }
}

// ====================== driver =============================================
#define GEMM_SMEM (3 * 32768)

extern "C" void kernel_launch(void* const* d_in, const int* in_sizes, int n_in,
                              void* d_out, int out_size)
{
    const float* x    = (const float*)d_in[0];
    const float* ln1g = (const float*)d_in[1];
    const float* ln1b = (const float*)d_in[2];
    const float* wqkv = (const float*)d_in[3];
    const float* wout = (const float*)d_in[4];
    const float* ln2g = (const float*)d_in[5];
    const float* ln2b = (const float*)d_in[6];
    const float* w1   = (const float*)d_in[7];
    const float* b1   = (const float*)d_in[8];
    const float* w2   = (const float*)d_in[9];
    const float* b2   = (const float*)d_in[10];
    const float* fng  = (const float*)d_in[11];
    const float* fnb  = (const float*)d_in[12];

    float *px;
    __nv_bfloat16 *pqh, *pql;
    __half *plnh, *pcth, *phh;
    uint16_t *pln8, *pct8, *ph8;
    __half *qkvh, *outh, *w1h, *w2h;
    uint16_t *qkv8, *out8, *w1_8, *w2_8;
    cudaGetSymbolAddress((void**)&px,   g_x);
    cudaGetSymbolAddress((void**)&pqh,  g_qkvh);
    cudaGetSymbolAddress((void**)&pql,  g_qkvl);
    cudaGetSymbolAddress((void**)&plnh, g_lnh);
    cudaGetSymbolAddress((void**)&pln8, g_ln8);
    cudaGetSymbolAddress((void**)&pcth, g_cth);
    cudaGetSymbolAddress((void**)&pct8, g_ct8);
    cudaGetSymbolAddress((void**)&phh,  g_hh);
    cudaGetSymbolAddress((void**)&ph8,  g_h8);
    cudaGetSymbolAddress((void**)&qkvh, g_wqkvt_h);
    cudaGetSymbolAddress((void**)&qkv8, g_wqkvt_8);
    cudaGetSymbolAddress((void**)&outh, g_woutt_h);
    cudaGetSymbolAddress((void**)&out8, g_woutt_8);
    cudaGetSymbolAddress((void**)&w1h,  g_w1t_h);
    cudaGetSymbolAddress((void**)&w1_8, g_w1t_8);
    cudaGetSymbolAddress((void**)&w2h,  g_w2t_h);
    cudaGetSymbolAddress((void**)&w2_8, g_w2t_8);

    cudaFuncSetAttribute(gemm_mma<0>, cudaFuncAttributeMaxDynamicSharedMemorySize, GEMM_SMEM);
    cudaFuncSetAttribute(gemm_mma<1>, cudaFuncAttributeMaxDynamicSharedMemorySize, GEMM_SMEM);
    cudaFuncSetAttribute(gemm_mma<2>, cudaFuncAttributeMaxDynamicSharedMemorySize, GEMM_SMEM);
    cudaFuncSetAttribute(gemm_mma<3>, cudaFuncAttributeMaxDynamicSharedMemorySize, GEMM_SMEM);
    cudaFuncSetAttribute(attn_mma, cudaFuncAttributeMaxDynamicSharedMemorySize, ATTN_SMEM);

    {
        dim3 tblk(32, 8);
        transpose_cvt<<<dim3(QKVD/32, DIM/32, DEPTH), tblk>>>(wqkv, qkvh, qkv8, DIM, QKVD);
        transpose_cvt<<<dim3(DIM/32, INNER/32, DEPTH), tblk>>>(wout, outh, out8, INNER, DIM);
        transpose_cvt<<<dim3(MLPD/32, DIM/32, DEPTH), tblk>>>(w1, w1h, w1_8, DIM, MLPD);
        transpose_cvt<<<dim3(DIM/32, MLPD/32, DEPTH), tblk>>>(w2, w2h, w2_8, MLPD, DIM);
    }

    cudaMemcpyAsync(px, x, sizeof(float) * (size_t)TOK * DIM,
                    cudaMemcpyDeviceToDevice, 0);

    const dim3 blk256(256);
    for (int i = 0; i < DEPTH; i++) {
        ln_kernel<true><<<TOK, blk256>>>(px, ln1g + i*DIM, ln1b + i*DIM,
                                         nullptr, plnh, pln8);
        gemm_mma<0><<<dim3(QKVD/128, TOK/128), blk256, GEMM_SMEM>>>(
            plnh, pln8,
            qkvh + (size_t)i*QKVD*DIM, qkv8 + (size_t)i*QKVD*DIM,
            nullptr, nullptr, nullptr, nullptr, pqh, pql, TOK, QKVD, DIM);
        attn_mma<<<dim3(SEQ/128, HEADS, BATCH), blk256, ATTN_SMEM>>>(pqh, pql, pcth, pct8);
        gemm_mma<3><<<dim3(DIM/128, TOK/128), blk256, GEMM_SMEM>>>(
            pcth, pct8,
            outh + (size_t)i*DIM*INNER, out8 + (size_t)i*DIM*INNER,
            nullptr, px, nullptr, nullptr, nullptr, nullptr, TOK, DIM, INNER);

        ln_kernel<true><<<TOK, blk256>>>(px, ln2g + i*DIM, ln2b + i*DIM,
                                         nullptr, plnh, pln8);
        gemm_mma<1><<<dim3(MLPD/128, TOK/128), blk256, GEMM_SMEM>>>(
            plnh, pln8,
            w1h + (size_t)i*MLPD*DIM, w1_8 + (size_t)i*MLPD*DIM,
            b1 + (size_t)i*MLPD, nullptr, phh, ph8, nullptr, nullptr, TOK, MLPD, DIM);
        gemm_mma<2><<<dim3(DIM/128, TOK/128), blk256, GEMM_SMEM>>>(
            phh, ph8,
            w2h + (size_t)i*DIM*MLPD, w2_8 + (size_t)i*DIM*MLPD,
            b2 + (size_t)i*DIM, px, nullptr, nullptr, nullptr, nullptr, TOK, DIM, MLPD);
    }

    ln_kernel<false><<<TOK, blk256>>>(px, fng, fnb, (float*)d_out, nullptr, nullptr);
}

// round 8
// speedup vs baseline: 1.2791x; 1.2791x over previous
#include <cuda_runtime.h>
#include <cuda_bf16.h>
#include <cuda_fp16.h>
#include <math.h>
#include <stdint.h>

#define DIM    768
#define DEPTH  6
#define HEADS  12
#define DHEAD  64
#define INNER  768
#define MLPD   3072
#define BATCH  4
#define SEQ    2048
#define TOK    (BATCH*SEQ)      /* 8192 */
#define QKVD   (3*INNER)        /* 2304 */
#define QSCALE 0.18033688011112042f   /* 0.125 * log2(e) */
#define WLSCALE 256.0f
#define IWLSCALE 0.00390625f

// ---------------- scratch (device globals; no allocations) ----------------
__device__ float g_x  [(size_t)TOK*DIM];     // residual stream fp32
__device__ __nv_bfloat16 g_qkvh[(size_t)TOK*QKVD];   // attention operand hi
__device__ __nv_bfloat16 g_qkvl[(size_t)TOK*QKVD];   // attention operand lo
__device__ __half g_ln16[(size_t)TOK*DIM];   // LN output fp16
__device__ __half g_ct16[(size_t)TOK*DIM];   // attention ctx fp16
__device__ __half g_h16 [(size_t)TOK*MLPD];  // mlp hidden fp16
// transposed fp16 hi/lo weights [layer][N][K]; lo pre-scaled by 256
__device__ __half g_wqkvt_h[(size_t)DEPTH*QKVD*DIM];
__device__ __half g_wqkvt_l[(size_t)DEPTH*QKVD*DIM];
__device__ __half g_woutt_h[(size_t)DEPTH*DIM*INNER];
__device__ __half g_woutt_l[(size_t)DEPTH*DIM*INNER];
__device__ __half g_w1t_h [(size_t)DEPTH*MLPD*DIM];
__device__ __half g_w1t_l [(size_t)DEPTH*MLPD*DIM];
__device__ __half g_w2t_h [(size_t)DEPTH*DIM*MLPD];
__device__ __half g_w2t_l [(size_t)DEPTH*DIM*MLPD];

// ====================== PTX helpers =======================================
__device__ __forceinline__ uint32_t smem_u32(const void* p){
    uint32_t a;
    asm("{ .reg .u64 t; cvta.to.shared.u64 t, %1; cvt.u32.u64 %0, t; }"
        : "=r"(a) : "l"(p));
    return a;
}
__device__ __forceinline__ void cp16(uint32_t s, const void* g){
    asm volatile("cp.async.cg.shared.global [%0], [%1], 16;" :: "r"(s), "l"(g));
}
#define CP_COMMIT() asm volatile("cp.async.commit_group;" ::: "memory")
#define CP_WAIT1()  asm volatile("cp.async.wait_group 1;" ::: "memory")
#define CP_WAIT0()  asm volatile("cp.async.wait_group 0;" ::: "memory")

__device__ __forceinline__ void ldmx4(uint32_t addr, uint32_t& r0, uint32_t& r1,
                                      uint32_t& r2, uint32_t& r3){
    asm volatile("ldmatrix.sync.aligned.m8n8.x4.shared.b16 {%0,%1,%2,%3}, [%4];"
        : "=r"(r0), "=r"(r1), "=r"(r2), "=r"(r3) : "r"(addr));
}
__device__ __forceinline__ void ldmx4t(uint32_t addr, uint32_t& r0, uint32_t& r1,
                                       uint32_t& r2, uint32_t& r3){
    asm volatile("ldmatrix.sync.aligned.m8n8.x4.trans.shared.b16 {%0,%1,%2,%3}, [%4];"
        : "=r"(r0), "=r"(r1), "=r"(r2), "=r"(r3) : "r"(addr));
}
// bf16 mma (attention)
__device__ __forceinline__ void mma16816(float* c, const uint32_t* a,
                                         uint32_t b0, uint32_t b1){
    asm volatile(
        "mma.sync.aligned.m16n8k16.row.col.f32.bf16.bf16.f32 "
        "{%0,%1,%2,%3}, {%4,%5,%6,%7}, {%8,%9}, {%0,%1,%2,%3};"
        : "+f"(c[0]), "+f"(c[1]), "+f"(c[2]), "+f"(c[3])
        : "r"(a[0]), "r"(a[1]), "r"(a[2]), "r"(a[3]), "r"(b0), "r"(b1));
}
// fp16 mma (GEMM)
__device__ __forceinline__ void mma16816h(float* c, const uint32_t* a,
                                          uint32_t b0, uint32_t b1){
    asm volatile(
        "mma.sync.aligned.m16n8k16.row.col.f32.f16.f16.f32 "
        "{%0,%1,%2,%3}, {%4,%5,%6,%7}, {%8,%9}, {%0,%1,%2,%3};"
        : "+f"(c[0]), "+f"(c[1]), "+f"(c[2]), "+f"(c[3])
        : "r"(a[0]), "r"(a[1]), "r"(a[2]), "r"(a[3]), "r"(b0), "r"(b1));
}
// FMA-pipe exp2 (degree-6 Taylor on [-0.5,0.5]); valid for t <= 0
__device__ __forceinline__ float exp2_fast(float t){
    t = fmaxf(t, -120.f);
    float n = rintf(t);
    float f = t - n;
    float p = 1.5403530e-4f;
    p = fmaf(p, f, 1.3333558e-3f);
    p = fmaf(p, f, 9.6181291e-3f);
    p = fmaf(p, f, 5.5504109e-2f);
    p = fmaf(p, f, 2.4022651e-1f);
    p = fmaf(p, f, 6.9314718e-1f);
    p = fmaf(p, f, 1.0f);
    return __int_as_float(__float_as_int(p) + (((int)n) << 23));
}

// ====================== weight transpose + fp16 hi/lo split ================
// W[z][K][N] fp32 -> Wh[z][N][K], Wl[z][N][K] (= (W - Wh) * 256), fp16
__global__ void transpose_cvt(const float* __restrict__ W,
                              __half* __restrict__ Wh,
                              __half* __restrict__ Wl, int K, int N)
{
    __shared__ float tile[32][33];
    const size_t off = (size_t)blockIdx.z * K * N;
    const int n0 = blockIdx.x * 32, k0 = blockIdx.y * 32;
    const int tx = threadIdx.x, ty = threadIdx.y;
#pragma unroll
    for (int i = 0; i < 32; i += 8)
        tile[ty + i][tx] = W[off + (size_t)(k0 + ty + i) * N + n0 + tx];
    __syncthreads();
#pragma unroll
    for (int i = 0; i < 32; i += 8) {
        float v = tile[tx][ty + i];
        __half h = __float2half_rn(v);
        size_t oidx = off + (size_t)(n0 + ty + i) * K + k0 + tx;
        Wh[oidx] = h;
        Wl[oidx] = __float2half_rn((v - __half2float(h)) * WLSCALE);
    }
}

// ====================== LayerNorm ==========================================
template<bool HOUT>
__global__ void ln_kernel(const float* __restrict__ x, const float* __restrict__ g,
                          const float* __restrict__ b, float* __restrict__ y,
                          __half* __restrict__ yh)
{
    int t = blockIdx.x;
    const float* xp = x + (size_t)t * DIM;

    float v[3];
    float s1 = 0.f, s2 = 0.f;
#pragma unroll
    for (int i = 0; i < 3; i++) {
        v[i] = xp[threadIdx.x + i * 256];
        s1 += v[i]; s2 += v[i] * v[i];
    }
#pragma unroll
    for (int o = 16; o > 0; o >>= 1) {
        s1 += __shfl_xor_sync(0xffffffffu, s1, o);
        s2 += __shfl_xor_sync(0xffffffffu, s2, o);
    }
    __shared__ float r1[8], r2[8];
    if ((threadIdx.x & 31) == 0) { r1[threadIdx.x >> 5] = s1; r2[threadIdx.x >> 5] = s2; }
    __syncthreads();
    s1 = 0.f; s2 = 0.f;
#pragma unroll
    for (int i = 0; i < 8; i++) { s1 += r1[i]; s2 += r2[i]; }

    float mu  = s1 * (1.f / DIM);
    float var = s2 * (1.f / DIM) - mu * mu;
    float rs  = rsqrtf(var + 1e-5f);
#pragma unroll
    for (int i = 0; i < 3; i++) {
        int d = threadIdx.x + i * 256;
        float yy = (v[i] - mu) * rs * g[d] + b[d];
        if (HOUT) yh[(size_t)t * DIM + d] = __float2half_rn(yy);
        else      y[(size_t)t * DIM + d] = yy;
    }
}

// ====================== fp16 2-product GEMM ================================
// C[M,N] = A[M,K] @ (Bh + Bl/256)[N,K]^T; A fp16, Bh/Bl fp16, fp32 accum.
// CTA 128x128, warp 32x64, BK=32, 3-stage cp.async (r4-proven shape).
// Stage: [A 8K][Bh 8K][Bl 8K] = 24KB.
// EPI: 0 = qkv out (scale Q cols, bf16 hi/lo to Qh/Ql);
//      1 = +bias, gelu, fp16 out; 2 = +bias += xres; 3 = += xres.
#define STAGE_SZ 24576u
template<int EPI>
__global__ void __launch_bounds__(256, 1)
gemm_mma(const __half* __restrict__ Ah,
         const __half* __restrict__ Bh, const __half* __restrict__ Bl,
         const float* __restrict__ bias, float* __restrict__ xres,
         __half* __restrict__ Ch,
         __nv_bfloat16* __restrict__ Qh, __nv_bfloat16* __restrict__ Ql,
         int M, int N, int K)
{
    extern __shared__ char smem[];
    const uint32_t sb0 = smem_u32(smem);
    const int tid  = threadIdx.x;
    const int lane = tid & 31, warp = tid >> 5;
    const int wm = warp >> 1, wn = warp & 1;
    const int bn = blockIdx.x, bm = blockIdx.y;
    const int nkt = K >> 5;

    auto load_stage = [&](int kt, int st){
        const uint32_t base = sb0 + (uint32_t)st * STAGE_SZ;
        const size_t kof = (size_t)kt * 32;
#pragma unroll
        for (int i = 0; i < 2; i++) {
            const int idx = tid + i * 256;
            const int row = idx >> 2, c = idx & 3;
            const uint32_t so = (uint32_t)(row * 64 + ((c ^ ((row >> 1) & 3)) << 4));
            const size_t ga = (size_t)(bm * 128 + row) * K + kof + c * 8;
            const size_t gb = (size_t)(bn * 128 + row) * K + kof + c * 8;
            cp16(base + so,          Ah + ga);
            cp16(base + 8192u + so,  Bh + gb);
            cp16(base + 16384u + so, Bl + gb);
        }
    };

    float acc [2][8][4];
    float acc2[2][8][4];
#pragma unroll
    for (int mt = 0; mt < 2; mt++)
#pragma unroll
        for (int nt = 0; nt < 8; nt++)
#pragma unroll
            for (int q = 0; q < 4; q++) { acc[mt][nt][q] = 0.f; acc2[mt][nt][q] = 0.f; }

    load_stage(0, 0); CP_COMMIT();
    load_stage(1, 1); CP_COMMIT();

    const int arow = wm * 32 + (lane & 15);
    const int acs  = lane >> 4;
    const int brow = wn * 64 + (lane & 7) + ((lane >> 4) << 3);
    const int bcs  = (lane >> 3) & 1;

    for (int kt = 0; kt < nkt; kt++) {
        if (kt == nkt - 1) { CP_WAIT0(); } else { CP_WAIT1(); }
        __syncthreads();
        if (kt + 2 < nkt) { load_stage(kt + 2, (kt + 2) % 3); CP_COMMIT(); }

        const uint32_t base = sb0 + (uint32_t)(kt % 3) * STAGE_SZ;
#pragma unroll
        for (int ks = 0; ks < 2; ks++) {
            uint32_t ah[2][4];
#pragma unroll
            for (int mt = 0; mt < 2; mt++) {
                const int r = arow + mt * 16;
                const int c = ks * 2 + acs;
                const uint32_t off = (uint32_t)(r * 64 + ((c ^ ((r >> 1) & 3)) << 4));
                ldmx4(base + off, ah[mt][0], ah[mt][1], ah[mt][2], ah[mt][3]);
            }
#pragma unroll
            for (int bt = 0; bt < 4; bt++) {
                const int r = brow + bt * 16;
                const int c = ks * 2 + bcs;
                const uint32_t off = (uint32_t)(r * 64 + ((c ^ ((r >> 1) & 3)) << 4));
                uint32_t bh[4], bl_[4];
                ldmx4(base + 8192u + off,  bh[0],  bh[1],  bh[2],  bh[3]);
                ldmx4(base + 16384u + off, bl_[0], bl_[1], bl_[2], bl_[3]);
#pragma unroll
                for (int mt = 0; mt < 2; mt++) {
                    mma16816h(acc [mt][2*bt],   ah[mt], bh[0],  bh[1]);
                    mma16816h(acc2[mt][2*bt],   ah[mt], bl_[0], bl_[1]);
                    mma16816h(acc [mt][2*bt+1], ah[mt], bh[2],  bh[3]);
                    mma16816h(acc2[mt][2*bt+1], ah[mt], bl_[2], bl_[3]);
                }
            }
        }
        __syncthreads();
    }

    const int rbase = bm * 128 + wm * 32 + (lane >> 2);
    const int cbase = bn * 128 + wn * 64 + (lane & 3) * 2;
#pragma unroll
    for (int mt = 0; mt < 2; mt++) {
#pragma unroll
        for (int nt = 0; nt < 8; nt++) {
            const int gcol = cbase + nt * 8;
#pragma unroll
            for (int h = 0; h < 2; h++) {
                const int grow = rbase + mt * 16 + h * 8;
                float v0 = acc[mt][nt][2*h]   + acc2[mt][nt][2*h]   * IWLSCALE;
                float v1 = acc[mt][nt][2*h+1] + acc2[mt][nt][2*h+1] * IWLSCALE;
                const size_t oidx = (size_t)grow * N + gcol;
                if (EPI == 0) {
                    const float sc = (gcol < INNER) ? QSCALE : 1.f;
                    v0 *= sc; v1 *= sc;
                    __nv_bfloat16 h0 = __float2bfloat16(v0), h1 = __float2bfloat16(v1);
                    __nv_bfloat16 l0 = __float2bfloat16(v0 - __bfloat162float(h0));
                    __nv_bfloat16 l1 = __float2bfloat16(v1 - __bfloat162float(h1));
                    *reinterpret_cast<uint32_t*>(Qh + oidx) =
                        (uint32_t)__bfloat16_as_ushort(h0) |
                        ((uint32_t)__bfloat16_as_ushort(h1) << 16);
                    *reinterpret_cast<uint32_t*>(Ql + oidx) =
                        (uint32_t)__bfloat16_as_ushort(l0) |
                        ((uint32_t)__bfloat16_as_ushort(l1) << 16);
                } else if (EPI == 1) {
                    v0 += bias[gcol];     v1 += bias[gcol + 1];
                    v0 = 0.5f * v0 * (1.f + erff(v0 * 0.70710678118654752f));
                    v1 = 0.5f * v1 * (1.f + erff(v1 * 0.70710678118654752f));
                    __half h0 = __float2half_rn(v0), h1 = __float2half_rn(v1);
                    *reinterpret_cast<uint32_t*>(Ch + oidx) =
                        (uint32_t)__half_as_ushort(h0) |
                        ((uint32_t)__half_as_ushort(h1) << 16);
                } else {
                    float2 xv = *reinterpret_cast<const float2*>(xres + oidx);
                    if (EPI == 2) { v0 += bias[gcol]; v1 += bias[gcol + 1]; }
                    xv.x += v0; xv.y += v1;
                    *reinterpret_cast<float2*>(xres + oidx) = xv;
                }
            }
        }
    }
}

// ====================== HMMA flash attention (bf16 3-product) ==============
// grid (SEQ/128, HEADS, BATCH), 256 threads (8 warps x 16 query rows).
#define ATTN_SMEM (32768 + 2*32768)
__global__ void __launch_bounds__(256, 1)
attn_mma(const __nv_bfloat16* __restrict__ qg_h, const __nv_bfloat16* __restrict__ qg_l,
         __half* __restrict__ ctx)
{
    extern __shared__ char smem[];
    const uint32_t sb = smem_u32(smem);
    const uint32_t QH = sb, QL = sb + 16384u;
    const int tid = threadIdx.x, lane = tid & 31, wid = tid >> 5;
    const int b = blockIdx.z, h = blockIdx.y, qt = blockIdx.x;
    const int tok0 = b * SEQ + qt * 128;

#pragma unroll
    for (int i = 0; i < 4; i++) {
        const int idx = tid + i * 256;
        const int row = idx >> 3, c = idx & 7;
        const uint32_t so = (uint32_t)(row * 128 + ((c ^ (row & 7)) << 4));
        const size_t g = (size_t)(tok0 + row) * QKVD + h * DHEAD + c * 8;
        cp16(QH + so, qg_h + g);
        cp16(QL + so, qg_l + g);
    }

    auto load_kv = [&](int t, int st){
        const uint32_t base = sb + 32768u + (uint32_t)st * 32768u;
        const int kv0 = b * SEQ + t * 64;
#pragma unroll
        for (int i = 0; i < 2; i++) {
            const int idx = tid + i * 256;
            const int row = idx >> 3, c = idx & 7;
            const uint32_t so = (uint32_t)(row * 128 + ((c ^ (row & 7)) << 4));
            const size_t gk = (size_t)(kv0 + row) * QKVD + INNER + h * DHEAD + c * 8;
            const size_t gv = (size_t)(kv0 + row) * QKVD + 2 * INNER + h * DHEAD + c * 8;
            cp16(base + so,          qg_h + gk);
            cp16(base + 8192u  + so, qg_l + gk);
            cp16(base + 16384u + so, qg_h + gv);
            cp16(base + 24576u + so, qg_l + gv);
        }
    };
    load_kv(0, 0); CP_COMMIT();

    float O[8][4];
#pragma unroll
    for (int nt = 0; nt < 8; nt++)
#pragma unroll
        for (int q = 0; q < 4; q++) O[nt][q] = 0.f;
    float m0 = -1e30f, m1 = -1e30f, l0 = 0.f, l1 = 0.f;
    const int m0row = wid * 16;

    const int NT = SEQ / 64;
    for (int t = 0; t < NT; t++) {
        if (t + 1 < NT) { load_kv(t + 1, (t + 1) & 1); CP_COMMIT(); CP_WAIT1(); }
        else            { CP_WAIT0(); }
        __syncthreads();
        const uint32_t kb = sb + 32768u + (uint32_t)(t & 1) * 32768u;

        float S[8][4];
#pragma unroll
        for (int nt = 0; nt < 8; nt++)
#pragma unroll
            for (int q = 0; q < 4; q++) S[nt][q] = 0.f;
#pragma unroll
        for (int ks = 0; ks < 4; ks++) {
            uint32_t ah[4], al_[4];
            {
                const int r = m0row + (lane & 15);
                const int c = ks * 2 + (lane >> 4);
                const uint32_t off = (uint32_t)(r * 128 + ((c ^ (r & 7)) << 4));
                ldmx4(QH + off, ah[0], ah[1], ah[2], ah[3]);
                ldmx4(QL + off, al_[0], al_[1], al_[2], al_[3]);
            }
#pragma unroll
            for (int bt = 0; bt < 4; bt++) {
                const int r = bt * 16 + (lane & 7) + ((lane >> 4) << 3);
                const int c = ks * 2 + ((lane >> 3) & 1);
                const uint32_t off = (uint32_t)(r * 128 + ((c ^ (r & 7)) << 4));
                uint32_t kh[4], kl[4];
                ldmx4(kb + off,         kh[0], kh[1], kh[2], kh[3]);
                ldmx4(kb + 8192u + off, kl[0], kl[1], kl[2], kl[3]);
                mma16816(S[2*bt],   ah,  kh[0], kh[1]);
                mma16816(S[2*bt],   ah,  kl[0], kl[1]);
                mma16816(S[2*bt],   al_, kh[0], kh[1]);
                mma16816(S[2*bt+1], ah,  kh[2], kh[3]);
                mma16816(S[2*bt+1], ah,  kl[2], kl[3]);
                mma16816(S[2*bt+1], al_, kh[2], kh[3]);
            }
        }

        float mt0 = -1e30f, mt1 = -1e30f;
#pragma unroll
        for (int nt = 0; nt < 8; nt++) {
            mt0 = fmaxf(mt0, fmaxf(S[nt][0], S[nt][1]));
            mt1 = fmaxf(mt1, fmaxf(S[nt][2], S[nt][3]));
        }
        mt0 = fmaxf(mt0, __shfl_xor_sync(0xffffffffu, mt0, 1));
        mt0 = fmaxf(mt0, __shfl_xor_sync(0xffffffffu, mt0, 2));
        mt1 = fmaxf(mt1, __shfl_xor_sync(0xffffffffu, mt1, 1));
        mt1 = fmaxf(mt1, __shfl_xor_sync(0xffffffffu, mt1, 2));
        const float mn0 = fmaxf(m0, mt0), mn1 = fmaxf(m1, mt1);
        const float cr0 = exp2_fast(m0 - mn0), cr1 = exp2_fast(m1 - mn1);
        m0 = mn0; m1 = mn1;

        uint32_t phi[4][4], plo[4][4];
        float s0 = 0.f, s1 = 0.f;
#pragma unroll
        for (int nt = 0; nt < 8; nt++) {
            float p0 = exp2_fast(S[nt][0] - m0);
            float p1 = exp2_fast(S[nt][1] - m0);
            float p2 = exp2_fast(S[nt][2] - m1);
            float p3 = exp2_fast(S[nt][3] - m1);
            s0 += p0 + p1; s1 += p2 + p3;
            __nv_bfloat16 h0 = __float2bfloat16(p0), h1 = __float2bfloat16(p1);
            __nv_bfloat16 h2 = __float2bfloat16(p2), h3 = __float2bfloat16(p3);
            const int t2 = nt >> 1, o = (nt & 1) * 2;
            phi[t2][o] = (uint32_t)__bfloat16_as_ushort(h0) |
                         ((uint32_t)__bfloat16_as_ushort(h1) << 16);
            phi[t2][o+1] = (uint32_t)__bfloat16_as_ushort(h2) |
                           ((uint32_t)__bfloat16_as_ushort(h3) << 16);
            __nv_bfloat16 e0 = __float2bfloat16(p0 - __bfloat162float(h0));
            __nv_bfloat16 e1 = __float2bfloat16(p1 - __bfloat162float(h1));
            __nv_bfloat16 e2 = __float2bfloat16(p2 - __bfloat162float(h2));
            __nv_bfloat16 e3 = __float2bfloat16(p3 - __bfloat162float(h3));
            plo[t2][o] = (uint32_t)__bfloat16_as_ushort(e0) |
                         ((uint32_t)__bfloat16_as_ushort(e1) << 16);
            plo[t2][o+1] = (uint32_t)__bfloat16_as_ushort(e2) |
                           ((uint32_t)__bfloat16_as_ushort(e3) << 16);
        }
        s0 += __shfl_xor_sync(0xffffffffu, s0, 1);
        s0 += __shfl_xor_sync(0xffffffffu, s0, 2);
        s1 += __shfl_xor_sync(0xffffffffu, s1, 1);
        s1 += __shfl_xor_sync(0xffffffffu, s1, 2);
        l0 = l0 * cr0 + s0;
        l1 = l1 * cr1 + s1;
#pragma unroll
        for (int nt = 0; nt < 8; nt++) {
            O[nt][0] *= cr0; O[nt][1] *= cr0;
            O[nt][2] *= cr1; O[nt][3] *= cr1;
        }

#pragma unroll
        for (int t2 = 0; t2 < 4; t2++) {
#pragma unroll
            for (int dn = 0; dn < 4; dn++) {
                const int r = t2 * 16 + (lane & 15);
                const int c = dn * 2 + (lane >> 4);
                const uint32_t off = (uint32_t)(r * 128 + ((c ^ (r & 7)) << 4));
                uint32_t vh[4], vl[4];
                ldmx4t(kb + 16384u + off, vh[0], vh[1], vh[2], vh[3]);
                ldmx4t(kb + 24576u + off, vl[0], vl[1], vl[2], vl[3]);
                mma16816(O[2*dn],   phi[t2], vh[0], vh[1]);
                mma16816(O[2*dn],   plo[t2], vh[0], vh[1]);
                mma16816(O[2*dn],   phi[t2], vl[0], vl[1]);
                mma16816(O[2*dn+1], phi[t2], vh[2], vh[3]);
                mma16816(O[2*dn+1], plo[t2], vh[2], vh[3]);
                mma16816(O[2*dn+1], phi[t2], vl[2], vl[3]);
            }
        }
        __syncthreads();
    }

    // ---- epilogue: normalize, write ctx fp16 ----
    const float i0 = 1.f / l0, i1 = 1.f / l1;
    const int r0 = tok0 + m0row + (lane >> 2);
#pragma unroll
    for (int nt = 0; nt < 8; nt++) {
        const int col = h * DHEAD + nt * 8 + (lane & 3) * 2;
#pragma unroll
        for (int hh = 0; hh < 2; hh++) {
            const float inv = hh ? i1 : i0;
            float v0 = O[nt][2*hh] * inv, v1 = O[nt][2*hh+1] * inv;
            __half h0 = __float2half_rn(v0), h1 = __float2half_rn(v1);
            const size_t oidx = (size_t)(r0 + hh * 8) * DIM + col;
            *reinterpret_cast<uint32_t*>(ctx + oidx) =
                (uint32_t)__half_as_ushort(h0) |
                ((uint32_t)__half_as_ushort(h1) << 16);
        }
    }
}

// ====================== driver =============================================
#define GEMM_SMEM (3 * 24576)

extern "C" void kernel_launch(void* const* d_in, const int* in_sizes, int n_in,
                              void* d_out, int out_size)
{
    const float* x    = (const float*)d_in[0];
    const float* ln1g = (const float*)d_in[1];
    const float* ln1b = (const float*)d_in[2];
    const float* wqkv = (const float*)d_in[3];
    const float* wout = (const float*)d_in[4];
    const float* ln2g = (const float*)d_in[5];
    const float* ln2b = (const float*)d_in[6];
    const float* w1   = (const float*)d_in[7];
    const float* b1   = (const float*)d_in[8];
    const float* w2   = (const float*)d_in[9];
    const float* b2   = (const float*)d_in[10];
    const float* fng  = (const float*)d_in[11];
    const float* fnb  = (const float*)d_in[12];

    float *px;
    __nv_bfloat16 *pqh, *pql;
    __half *pln16, *pct16, *ph16;
    __half *qkvh, *qkvl, *outh, *outl, *w1h, *w1l, *w2h, *w2l;
    cudaGetSymbolAddress((void**)&px,    g_x);
    cudaGetSymbolAddress((void**)&pqh,   g_qkvh);
    cudaGetSymbolAddress((void**)&pql,   g_qkvl);
    cudaGetSymbolAddress((void**)&pln16, g_ln16);
    cudaGetSymbolAddress((void**)&pct16, g_ct16);
    cudaGetSymbolAddress((void**)&ph16,  g_h16);
    cudaGetSymbolAddress((void**)&qkvh,  g_wqkvt_h);
    cudaGetSymbolAddress((void**)&qkvl,  g_wqkvt_l);
    cudaGetSymbolAddress((void**)&outh,  g_woutt_h);
    cudaGetSymbolAddress((void**)&outl,  g_woutt_l);
    cudaGetSymbolAddress((void**)&w1h,   g_w1t_h);
    cudaGetSymbolAddress((void**)&w1l,   g_w1t_l);
    cudaGetSymbolAddress((void**)&w2h,   g_w2t_h);
    cudaGetSymbolAddress((void**)&w2l,   g_w2t_l);

    cudaFuncSetAttribute(gemm_mma<0>, cudaFuncAttributeMaxDynamicSharedMemorySize, GEMM_SMEM);
    cudaFuncSetAttribute(gemm_mma<1>, cudaFuncAttributeMaxDynamicSharedMemorySize, GEMM_SMEM);
    cudaFuncSetAttribute(gemm_mma<2>, cudaFuncAttributeMaxDynamicSharedMemorySize, GEMM_SMEM);
    cudaFuncSetAttribute(gemm_mma<3>, cudaFuncAttributeMaxDynamicSharedMemorySize, GEMM_SMEM);
    cudaFuncSetAttribute(attn_mma, cudaFuncAttributeMaxDynamicSharedMemorySize, ATTN_SMEM);

    {
        dim3 tblk(32, 8);
        transpose_cvt<<<dim3(QKVD/32, DIM/32, DEPTH), tblk>>>(wqkv, qkvh, qkvl, DIM, QKVD);
        transpose_cvt<<<dim3(DIM/32, INNER/32, DEPTH), tblk>>>(wout, outh, outl, INNER, DIM);
        transpose_cvt<<<dim3(MLPD/32, DIM/32, DEPTH), tblk>>>(w1, w1h, w1l, DIM, MLPD);
        transpose_cvt<<<dim3(DIM/32, MLPD/32, DEPTH), tblk>>>(w2, w2h, w2l, MLPD, DIM);
    }

    cudaMemcpyAsync(px, x, sizeof(float) * (size_t)TOK * DIM,
                    cudaMemcpyDeviceToDevice, 0);

    const dim3 blk256(256);
    for (int i = 0; i < DEPTH; i++) {
        ln_kernel<true><<<TOK, blk256>>>(px, ln1g + i*DIM, ln1b + i*DIM,
                                         nullptr, pln16);
        gemm_mma<0><<<dim3(QKVD/128, TOK/128), blk256, GEMM_SMEM>>>(
            pln16,
            qkvh + (size_t)i*QKVD*DIM, qkvl + (size_t)i*QKVD*DIM,
            nullptr, nullptr, nullptr, pqh, pql, TOK, QKVD, DIM);
        attn_mma<<<dim3(SEQ/128, HEADS, BATCH), blk256, ATTN_SMEM>>>(pqh, pql, pct16);
        gemm_mma<3><<<dim3(DIM/128, TOK/128), blk256, GEMM_SMEM>>>(
            pct16,
            outh + (size_t)i*DIM*INNER, outl + (size_t)i*DIM*INNER,
            nullptr, px, nullptr, nullptr, nullptr, TOK, DIM, INNER);

        ln_kernel<true><<<TOK, blk256>>>(px, ln2g + i*DIM, ln2b + i*DIM,
                                         nullptr, pln16);
        gemm_mma<1><<<dim3(MLPD/128, TOK/128), blk256, GEMM_SMEM>>>(
            pln16,
            w1h + (size_t)i*MLPD*DIM, w1l + (size_t)i*MLPD*DIM,
            b1 + (size_t)i*MLPD, nullptr, ph16, nullptr, nullptr, TOK, MLPD, DIM);
        gemm_mma<2><<<dim3(DIM/128, TOK/128), blk256, GEMM_SMEM>>>(
            ph16,
            w2h + (size_t)i*DIM*MLPD, w2l + (size_t)i*DIM*MLPD,
            b2 + (size_t)i*DIM, px, nullptr, nullptr, nullptr, TOK, DIM, MLPD);
    }

    ln_kernel<false><<<TOK, blk256>>>(px, fng, fnb, (float*)d_out, nullptr);
}

// round 9
// speedup vs baseline: 1.5036x; 1.1755x over previous
#include <cuda_runtime.h>
#include <cuda_bf16.h>
#include <cuda_fp16.h>
#include <math.h>
#include <stdint.h>

#define DIM    768
#define DEPTH  6
#define HEADS  12
#define DHEAD  64
#define INNER  768
#define MLPD   3072
#define BATCH  4
#define SEQ    2048
#define TOK    (BATCH*SEQ)      /* 8192 */
#define QKVD   (3*INNER)        /* 2304 */
#define QSCALE 0.18033688011112042f   /* 0.125 * log2(e) */
#define WLSCALE 256.0f
#define IWLSCALE 0.00390625f

// ---------------- scratch (device globals; no allocations) ----------------
__device__ float  g_x   [(size_t)TOK*DIM];    // residual stream fp32
__device__ __half g_qkv16[(size_t)TOK*QKVD];  // fused qkv fp16 (Q pre-scaled)
__device__ __half g_ln16[(size_t)TOK*DIM];    // LN output fp16
__device__ __half g_ct16[(size_t)TOK*DIM];    // attention ctx fp16
__device__ __half g_h16 [(size_t)TOK*MLPD];   // mlp hidden fp16
// transposed fp16 hi/lo weights [layer][N][K]; lo pre-scaled by 256
__device__ __half g_wqkvt_h[(size_t)DEPTH*QKVD*DIM];
__device__ __half g_wqkvt_l[(size_t)DEPTH*QKVD*DIM];
__device__ __half g_woutt_h[(size_t)DEPTH*DIM*INNER];
__device__ __half g_woutt_l[(size_t)DEPTH*DIM*INNER];
__device__ __half g_w1t_h [(size_t)DEPTH*MLPD*DIM];
__device__ __half g_w1t_l [(size_t)DEPTH*MLPD*DIM];
__device__ __half g_w2t_h [(size_t)DEPTH*DIM*MLPD];
__device__ __half g_w2t_l [(size_t)DEPTH*DIM*MLPD];

// ====================== PTX helpers =======================================
__device__ __forceinline__ uint32_t smem_u32(const void* p){
    uint32_t a;
    asm("{ .reg .u64 t; cvta.to.shared.u64 t, %1; cvt.u32.u64 %0, t; }"
        : "=r"(a) : "l"(p));
    return a;
}
__device__ __forceinline__ void cp16(uint32_t s, const void* g){
    asm volatile("cp.async.cg.shared.global [%0], [%1], 16;" :: "r"(s), "l"(g));
}
#define CP_COMMIT() asm volatile("cp.async.commit_group;" ::: "memory")
#define CP_WAIT1()  asm volatile("cp.async.wait_group 1;" ::: "memory")
#define CP_WAIT0()  asm volatile("cp.async.wait_group 0;" ::: "memory")

__device__ __forceinline__ void ldmx4(uint32_t addr, uint32_t& r0, uint32_t& r1,
                                      uint32_t& r2, uint32_t& r3){
    asm volatile("ldmatrix.sync.aligned.m8n8.x4.shared.b16 {%0,%1,%2,%3}, [%4];"
        : "=r"(r0), "=r"(r1), "=r"(r2), "=r"(r3) : "r"(addr));
}
__device__ __forceinline__ void ldmx4t(uint32_t addr, uint32_t& r0, uint32_t& r1,
                                       uint32_t& r2, uint32_t& r3){
    asm volatile("ldmatrix.sync.aligned.m8n8.x4.trans.shared.b16 {%0,%1,%2,%3}, [%4];"
        : "=r"(r0), "=r"(r1), "=r"(r2), "=r"(r3) : "r"(addr));
}
// fp16 mma
__device__ __forceinline__ void mma16816h(float* c, const uint32_t* a,
                                          uint32_t b0, uint32_t b1){
    asm volatile(
        "mma.sync.aligned.m16n8k16.row.col.f32.f16.f16.f32 "
        "{%0,%1,%2,%3}, {%4,%5,%6,%7}, {%8,%9}, {%0,%1,%2,%3};"
        : "+f"(c[0]), "+f"(c[1]), "+f"(c[2]), "+f"(c[3])
        : "r"(a[0]), "r"(a[1]), "r"(a[2]), "r"(a[3]), "r"(b0), "r"(b1));
}
// FMA-pipe exp2 (degree-6 Taylor on [-0.5,0.5]); valid for t <= 0
__device__ __forceinline__ float exp2_fast(float t){
    t = fmaxf(t, -120.f);
    float n = rintf(t);
    float f = t - n;
    float p = 1.5403530e-4f;
    p = fmaf(p, f, 1.3333558e-3f);
    p = fmaf(p, f, 9.6181291e-3f);
    p = fmaf(p, f, 5.5504109e-2f);
    p = fmaf(p, f, 2.4022651e-1f);
    p = fmaf(p, f, 6.9314718e-1f);
    p = fmaf(p, f, 1.0f);
    return __int_as_float(__float_as_int(p) + (((int)n) << 23));
}

// ====================== weight transpose + fp16 hi/lo split ================
__global__ void transpose_cvt(const float* __restrict__ W,
                              __half* __restrict__ Wh,
                              __half* __restrict__ Wl, int K, int N)
{
    __shared__ float tile[32][33];
    const size_t off = (size_t)blockIdx.z * K * N;
    const int n0 = blockIdx.x * 32, k0 = blockIdx.y * 32;
    const int tx = threadIdx.x, ty = threadIdx.y;
#pragma unroll
    for (int i = 0; i < 32; i += 8)
        tile[ty + i][tx] = W[off + (size_t)(k0 + ty + i) * N + n0 + tx];
    __syncthreads();
#pragma unroll
    for (int i = 0; i < 32; i += 8) {
        float v = tile[tx][ty + i];
        __half h = __float2half_rn(v);
        size_t oidx = off + (size_t)(n0 + ty + i) * K + k0 + tx;
        Wh[oidx] = h;
        Wl[oidx] = __float2half_rn((v - __half2float(h)) * WLSCALE);
    }
}

// ====================== LayerNorm ==========================================
template<bool HOUT>
__global__ void ln_kernel(const float* __restrict__ x, const float* __restrict__ g,
                          const float* __restrict__ b, float* __restrict__ y,
                          __half* __restrict__ yh)
{
    int t = blockIdx.x;
    const float* xp = x + (size_t)t * DIM;

    float v[3];
    float s1 = 0.f, s2 = 0.f;
#pragma unroll
    for (int i = 0; i < 3; i++) {
        v[i] = xp[threadIdx.x + i * 256];
        s1 += v[i]; s2 += v[i] * v[i];
    }
#pragma unroll
    for (int o = 16; o > 0; o >>= 1) {
        s1 += __shfl_xor_sync(0xffffffffu, s1, o);
        s2 += __shfl_xor_sync(0xffffffffu, s2, o);
    }
    __shared__ float r1[8], r2[8];
    if ((threadIdx.x & 31) == 0) { r1[threadIdx.x >> 5] = s1; r2[threadIdx.x >> 5] = s2; }
    __syncthreads();
    s1 = 0.f; s2 = 0.f;
#pragma unroll
    for (int i = 0; i < 8; i++) { s1 += r1[i]; s2 += r2[i]; }

    float mu  = s1 * (1.f / DIM);
    float var = s2 * (1.f / DIM) - mu * mu;
    float rs  = rsqrtf(var + 1e-5f);
#pragma unroll
    for (int i = 0; i < 3; i++) {
        int d = threadIdx.x + i * 256;
        float yy = (v[i] - mu) * rs * g[d] + b[d];
        if (HOUT) yh[(size_t)t * DIM + d] = __float2half_rn(yy);
        else      y[(size_t)t * DIM + d] = yy;
    }
}

// ====================== fp16 2-product GEMM ================================
// C[M,N] = A[M,K] @ (Bh + Bl/256)[N,K]^T; A fp16, Bh/Bl fp16, fp32 accum.
// CTA 128x128, warp 32x64, BK=32, 3-stage cp.async.
// Stage: [A 8K][Bh 8K][Bl 8K] = 24KB.
// EPI: 0 = qkv out (scale Q cols, fp16); 1 = +bias, gelu, fp16 out;
//      2 = +bias += xres; 3 = += xres.
#define STAGE_SZ 24576u
template<int EPI>
__global__ void __launch_bounds__(256, 1)
gemm_mma(const __half* __restrict__ Ah,
         const __half* __restrict__ Bh, const __half* __restrict__ Bl,
         const float* __restrict__ bias, float* __restrict__ xres,
         __half* __restrict__ Ch, int M, int N, int K)
{
    extern __shared__ char smem[];
    const uint32_t sb0 = smem_u32(smem);
    const int tid  = threadIdx.x;
    const int lane = tid & 31, warp = tid >> 5;
    const int wm = warp >> 1, wn = warp & 1;
    const int bn = blockIdx.x, bm = blockIdx.y;
    const int nkt = K >> 5;

    auto load_stage = [&](int kt, int st){
        const uint32_t base = sb0 + (uint32_t)st * STAGE_SZ;
        const size_t kof = (size_t)kt * 32;
#pragma unroll
        for (int i = 0; i < 2; i++) {
            const int idx = tid + i * 256;
            const int row = idx >> 2, c = idx & 3;
            const uint32_t so = (uint32_t)(row * 64 + ((c ^ ((row >> 1) & 3)) << 4));
            const size_t ga = (size_t)(bm * 128 + row) * K + kof + c * 8;
            const size_t gb = (size_t)(bn * 128 + row) * K + kof + c * 8;
            cp16(base + so,          Ah + ga);
            cp16(base + 8192u + so,  Bh + gb);
            cp16(base + 16384u + so, Bl + gb);
        }
    };

    float acc [2][8][4];
    float acc2[2][8][4];
#pragma unroll
    for (int mt = 0; mt < 2; mt++)
#pragma unroll
        for (int nt = 0; nt < 8; nt++)
#pragma unroll
            for (int q = 0; q < 4; q++) { acc[mt][nt][q] = 0.f; acc2[mt][nt][q] = 0.f; }

    load_stage(0, 0); CP_COMMIT();
    load_stage(1, 1); CP_COMMIT();

    const int arow = wm * 32 + (lane & 15);
    const int acs  = lane >> 4;
    const int brow = wn * 64 + (lane & 7) + ((lane >> 4) << 3);
    const int bcs  = (lane >> 3) & 1;

    for (int kt = 0; kt < nkt; kt++) {
        if (kt == nkt - 1) { CP_WAIT0(); } else { CP_WAIT1(); }
        __syncthreads();
        if (kt + 2 < nkt) { load_stage(kt + 2, (kt + 2) % 3); CP_COMMIT(); }

        const uint32_t base = sb0 + (uint32_t)(kt % 3) * STAGE_SZ;
#pragma unroll
        for (int ks = 0; ks < 2; ks++) {
            uint32_t ah[2][4];
#pragma unroll
            for (int mt = 0; mt < 2; mt++) {
                const int r = arow + mt * 16;
                const int c = ks * 2 + acs;
                const uint32_t off = (uint32_t)(r * 64 + ((c ^ ((r >> 1) & 3)) << 4));
                ldmx4(base + off, ah[mt][0], ah[mt][1], ah[mt][2], ah[mt][3]);
            }
#pragma unroll
            for (int bt = 0; bt < 4; bt++) {
                const int r = brow + bt * 16;
                const int c = ks * 2 + bcs;
                const uint32_t off = (uint32_t)(r * 64 + ((c ^ ((r >> 1) & 3)) << 4));
                uint32_t bh[4], bl_[4];
                ldmx4(base + 8192u + off,  bh[0],  bh[1],  bh[2],  bh[3]);
                ldmx4(base + 16384u + off, bl_[0], bl_[1], bl_[2], bl_[3]);
#pragma unroll
                for (int mt = 0; mt < 2; mt++) {
                    mma16816h(acc [mt][2*bt],   ah[mt], bh[0],  bh[1]);
                    mma16816h(acc2[mt][2*bt],   ah[mt], bl_[0], bl_[1]);
                    mma16816h(acc [mt][2*bt+1], ah[mt], bh[2],  bh[3]);
                    mma16816h(acc2[mt][2*bt+1], ah[mt], bl_[2], bl_[3]);
                }
            }
        }
        __syncthreads();
    }

    const int rbase = bm * 128 + wm * 32 + (lane >> 2);
    const int cbase = bn * 128 + wn * 64 + (lane & 3) * 2;
#pragma unroll
    for (int mt = 0; mt < 2; mt++) {
#pragma unroll
        for (int nt = 0; nt < 8; nt++) {
            const int gcol = cbase + nt * 8;
#pragma unroll
            for (int h = 0; h < 2; h++) {
                const int grow = rbase + mt * 16 + h * 8;
                float v0 = acc[mt][nt][2*h]   + acc2[mt][nt][2*h]   * IWLSCALE;
                float v1 = acc[mt][nt][2*h+1] + acc2[mt][nt][2*h+1] * IWLSCALE;
                const size_t oidx = (size_t)grow * N + gcol;
                if (EPI == 0 || EPI == 1) {
                    if (EPI == 0) {
                        const float sc = (gcol < INNER) ? QSCALE : 1.f;
                        v0 *= sc; v1 *= sc;
                    } else {
                        v0 += bias[gcol];     v1 += bias[gcol + 1];
                        v0 = 0.5f * v0 * (1.f + erff(v0 * 0.70710678118654752f));
                        v1 = 0.5f * v1 * (1.f + erff(v1 * 0.70710678118654752f));
                    }
                    __half h0 = __float2half_rn(v0), h1 = __float2half_rn(v1);
                    *reinterpret_cast<uint32_t*>(Ch + oidx) =
                        (uint32_t)__half_as_ushort(h0) |
                        ((uint32_t)__half_as_ushort(h1) << 16);
                } else {
                    float2 xv = *reinterpret_cast<const float2*>(xres + oidx);
                    if (EPI == 2) { v0 += bias[gcol]; v1 += bias[gcol + 1]; }
                    xv.x += v0; xv.y += v1;
                    *reinterpret_cast<float2*>(xres + oidx) = xv;
                }
            }
        }
    }
}

// ====================== fp16 1-product flash attention =====================
// grid (SEQ/128, HEADS, BATCH), 256 threads (8 warps x 16 query rows).
// Q pre-scaled by 0.125*log2e; softmax in base-2 domain.
// SMEM: Q 16KB + 2 x (K 8KB + V 8KB) = 48KB.
#define ATTN_SMEM (16384 + 2*16384)
__global__ void __launch_bounds__(256, 1)
attn_mma(const __half* __restrict__ qkv, __half* __restrict__ ctx)
{
    extern __shared__ char smem[];
    const uint32_t sb = smem_u32(smem);
    const uint32_t QS = sb;
    const int tid = threadIdx.x, lane = tid & 31, wid = tid >> 5;
    const int b = blockIdx.z, h = blockIdx.y, qt = blockIdx.x;
    const int tok0 = b * SEQ + qt * 128;

    // Q tile: 128 rows x 128B (64 fp16), swizzled
#pragma unroll
    for (int i = 0; i < 4; i++) {
        const int idx = tid + i * 256;
        const int row = idx >> 3, c = idx & 7;
        const uint32_t so = (uint32_t)(row * 128 + ((c ^ (row & 7)) << 4));
        cp16(QS + so, qkv + (size_t)(tok0 + row) * QKVD + h * DHEAD + c * 8);
    }

    auto load_kv = [&](int t, int st){
        const uint32_t base = sb + 16384u + (uint32_t)st * 16384u;
        const int kv0 = b * SEQ + t * 64;
#pragma unroll
        for (int i = 0; i < 2; i++) {
            const int idx = tid + i * 256;
            const int row = idx >> 3, c = idx & 7;
            const uint32_t so = (uint32_t)(row * 128 + ((c ^ (row & 7)) << 4));
            const size_t gk = (size_t)(kv0 + row) * QKVD + INNER + h * DHEAD + c * 8;
            const size_t gv = (size_t)(kv0 + row) * QKVD + 2 * INNER + h * DHEAD + c * 8;
            cp16(base + so,         qkv + gk);
            cp16(base + 8192u + so, qkv + gv);
        }
    };
    load_kv(0, 0); CP_COMMIT();

    float O[8][4];
#pragma unroll
    for (int nt = 0; nt < 8; nt++)
#pragma unroll
        for (int q = 0; q < 4; q++) O[nt][q] = 0.f;
    float m0 = -1e30f, m1 = -1e30f, l0 = 0.f, l1 = 0.f;
    const int m0row = wid * 16;

    const int NT = SEQ / 64;
    for (int t = 0; t < NT; t++) {
        if (t + 1 < NT) { load_kv(t + 1, (t + 1) & 1); CP_COMMIT(); CP_WAIT1(); }
        else            { CP_WAIT0(); }
        __syncthreads();
        const uint32_t kb = sb + 16384u + (uint32_t)(t & 1) * 16384u;

        // ---- S = Q @ K^T (fp16 single product) ----
        float S[8][4];
#pragma unroll
        for (int nt = 0; nt < 8; nt++)
#pragma unroll
            for (int q = 0; q < 4; q++) S[nt][q] = 0.f;
#pragma unroll
        for (int ks = 0; ks < 4; ks++) {
            uint32_t qf[4];
            {
                const int r = m0row + (lane & 15);
                const int c = ks * 2 + (lane >> 4);
                const uint32_t off = (uint32_t)(r * 128 + ((c ^ (r & 7)) << 4));
                ldmx4(QS + off, qf[0], qf[1], qf[2], qf[3]);
            }
#pragma unroll
            for (int bt = 0; bt < 4; bt++) {
                const int r = bt * 16 + (lane & 7) + ((lane >> 4) << 3);
                const int c = ks * 2 + ((lane >> 3) & 1);
                const uint32_t off = (uint32_t)(r * 128 + ((c ^ (r & 7)) << 4));
                uint32_t kh[4];
                ldmx4(kb + off, kh[0], kh[1], kh[2], kh[3]);
                mma16816h(S[2*bt],   qf, kh[0], kh[1]);
                mma16816h(S[2*bt+1], qf, kh[2], kh[3]);
            }
        }

        // ---- online softmax (base-2 domain) ----
        float mt0 = -1e30f, mt1 = -1e30f;
#pragma unroll
        for (int nt = 0; nt < 8; nt++) {
            mt0 = fmaxf(mt0, fmaxf(S[nt][0], S[nt][1]));
            mt1 = fmaxf(mt1, fmaxf(S[nt][2], S[nt][3]));
        }
        mt0 = fmaxf(mt0, __shfl_xor_sync(0xffffffffu, mt0, 1));
        mt0 = fmaxf(mt0, __shfl_xor_sync(0xffffffffu, mt0, 2));
        mt1 = fmaxf(mt1, __shfl_xor_sync(0xffffffffu, mt1, 1));
        mt1 = fmaxf(mt1, __shfl_xor_sync(0xffffffffu, mt1, 2));
        const float mn0 = fmaxf(m0, mt0), mn1 = fmaxf(m1, mt1);
        const float cr0 = exp2_fast(m0 - mn0), cr1 = exp2_fast(m1 - mn1);
        m0 = mn0; m1 = mn1;

        uint32_t phi[4][4];
        float s0 = 0.f, s1 = 0.f;
#pragma unroll
        for (int nt = 0; nt < 8; nt++) {
            float p0 = exp2_fast(S[nt][0] - m0);
            float p1 = exp2_fast(S[nt][1] - m0);
            float p2 = exp2_fast(S[nt][2] - m1);
            float p3 = exp2_fast(S[nt][3] - m1);
            s0 += p0 + p1; s1 += p2 + p3;
            __half h0 = __float2half_rn(p0), h1 = __float2half_rn(p1);
            __half h2 = __float2half_rn(p2), h3 = __float2half_rn(p3);
            const int t2 = nt >> 1, o = (nt & 1) * 2;
            phi[t2][o] = (uint32_t)__half_as_ushort(h0) |
                         ((uint32_t)__half_as_ushort(h1) << 16);
            phi[t2][o+1] = (uint32_t)__half_as_ushort(h2) |
                           ((uint32_t)__half_as_ushort(h3) << 16);
        }
        s0 += __shfl_xor_sync(0xffffffffu, s0, 1);
        s0 += __shfl_xor_sync(0xffffffffu, s0, 2);
        s1 += __shfl_xor_sync(0xffffffffu, s1, 1);
        s1 += __shfl_xor_sync(0xffffffffu, s1, 2);
        l0 = l0 * cr0 + s0;
        l1 = l1 * cr1 + s1;
#pragma unroll
        for (int nt = 0; nt < 8; nt++) {
            O[nt][0] *= cr0; O[nt][1] *= cr0;
            O[nt][2] *= cr1; O[nt][3] *= cr1;
        }

        // ---- O += P @ V (fp16 single product, ldmatrix.trans on V) ----
#pragma unroll
        for (int t2 = 0; t2 < 4; t2++) {
#pragma unroll
            for (int dn = 0; dn < 4; dn++) {
                const int r = t2 * 16 + (lane & 15);
                const int c = dn * 2 + (lane >> 4);
                const uint32_t off = (uint32_t)(r * 128 + ((c ^ (r & 7)) << 4));
                uint32_t vh[4];
                ldmx4t(kb + 8192u + off, vh[0], vh[1], vh[2], vh[3]);
                mma16816h(O[2*dn],   phi[t2], vh[0], vh[1]);
                mma16816h(O[2*dn+1], phi[t2], vh[2], vh[3]);
            }
        }
        __syncthreads();
    }

    // ---- epilogue: normalize, write ctx fp16 ----
    const float i0 = 1.f / l0, i1 = 1.f / l1;
    const int r0 = tok0 + m0row + (lane >> 2);
#pragma unroll
    for (int nt = 0; nt < 8; nt++) {
        const int col = h * DHEAD + nt * 8 + (lane & 3) * 2;
#pragma unroll
        for (int hh = 0; hh < 2; hh++) {
            const float inv = hh ? i1 : i0;
            float v0 = O[nt][2*hh] * inv, v1 = O[nt][2*hh+1] * inv;
            __half h0 = __float2half_rn(v0), h1 = __float2half_rn(v1);
            const size_t oidx = (size_t)(r0 + hh * 8) * DIM + col;
            *reinterpret_cast<uint32_t*>(ctx + oidx) =
                (uint32_t)__half_as_ushort(h0) |
                ((uint32_t)__half_as_ushort(h1) << 16);
        }
    }
}

// ====================== driver =============================================
#define GEMM_SMEM (3 * 24576)

extern "C" void kernel_launch(void* const* d_in, const int* in_sizes, int n_in,
                              void* d_out, int out_size)
{
    const float* x    = (const float*)d_in[0];
    const float* ln1g = (const float*)d_in[1];
    const float* ln1b = (const float*)d_in[2];
    const float* wqkv = (const float*)d_in[3];
    const float* wout = (const float*)d_in[4];
    const float* ln2g = (const float*)d_in[5];
    const float* ln2b = (const float*)d_in[6];
    const float* w1   = (const float*)d_in[7];
    const float* b1   = (const float*)d_in[8];
    const float* w2   = (const float*)d_in[9];
    const float* b2   = (const float*)d_in[10];
    const float* fng  = (const float*)d_in[11];
    const float* fnb  = (const float*)d_in[12];

    float *px;
    __half *pqkv, *pln16, *pct16, *ph16;
    __half *qkvh, *qkvl, *outh, *outl, *w1h, *w1l, *w2h, *w2l;
    cudaGetSymbolAddress((void**)&px,    g_x);
    cudaGetSymbolAddress((void**)&pqkv,  g_qkv16);
    cudaGetSymbolAddress((void**)&pln16, g_ln16);
    cudaGetSymbolAddress((void**)&pct16, g_ct16);
    cudaGetSymbolAddress((void**)&ph16,  g_h16);
    cudaGetSymbolAddress((void**)&qkvh,  g_wqkvt_h);
    cudaGetSymbolAddress((void**)&qkvl,  g_wqkvt_l);
    cudaGetSymbolAddress((void**)&outh,  g_woutt_h);
    cudaGetSymbolAddress((void**)&outl,  g_woutt_l);
    cudaGetSymbolAddress((void**)&w1h,   g_w1t_h);
    cudaGetSymbolAddress((void**)&w1l,   g_w1t_l);
    cudaGetSymbolAddress((void**)&w2h,   g_w2t_h);
    cudaGetSymbolAddress((void**)&w2l,   g_w2t_l);

    cudaFuncSetAttribute(gemm_mma<0>, cudaFuncAttributeMaxDynamicSharedMemorySize, GEMM_SMEM);
    cudaFuncSetAttribute(gemm_mma<1>, cudaFuncAttributeMaxDynamicSharedMemorySize, GEMM_SMEM);
    cudaFuncSetAttribute(gemm_mma<2>, cudaFuncAttributeMaxDynamicSharedMemorySize, GEMM_SMEM);
    cudaFuncSetAttribute(gemm_mma<3>, cudaFuncAttributeMaxDynamicSharedMemorySize, GEMM_SMEM);
    cudaFuncSetAttribute(attn_mma, cudaFuncAttributeMaxDynamicSharedMemorySize, ATTN_SMEM);

    {
        dim3 tblk(32, 8);
        transpose_cvt<<<dim3(QKVD/32, DIM/32, DEPTH), tblk>>>(wqkv, qkvh, qkvl, DIM, QKVD);
        transpose_cvt<<<dim3(DIM/32, INNER/32, DEPTH), tblk>>>(wout, outh, outl, INNER, DIM);
        transpose_cvt<<<dim3(MLPD/32, DIM/32, DEPTH), tblk>>>(w1, w1h, w1l, DIM, MLPD);
        transpose_cvt<<<dim3(DIM/32, MLPD/32, DEPTH), tblk>>>(w2, w2h, w2l, MLPD, DIM);
    }

    cudaMemcpyAsync(px, x, sizeof(float) * (size_t)TOK * DIM,
                    cudaMemcpyDeviceToDevice, 0);

    const dim3 blk256(256);
    for (int i = 0; i < DEPTH; i++) {
        ln_kernel<true><<<TOK, blk256>>>(px, ln1g + i*DIM, ln1b + i*DIM,
                                         nullptr, pln16);
        gemm_mma<0><<<dim3(QKVD/128, TOK/128), blk256, GEMM_SMEM>>>(
            pln16,
            qkvh + (size_t)i*QKVD*DIM, qkvl + (size_t)i*QKVD*DIM,
            nullptr, nullptr, pqkv, TOK, QKVD, DIM);
        attn_mma<<<dim3(SEQ/128, HEADS, BATCH), blk256, ATTN_SMEM>>>(pqkv, pct16);
        gemm_mma<3><<<dim3(DIM/128, TOK/128), blk256, GEMM_SMEM>>>(
            pct16,
            outh + (size_t)i*DIM*INNER, outl + (size_t)i*DIM*INNER,
            nullptr, px, nullptr, TOK, DIM, INNER);

        ln_kernel<true><<<TOK, blk256>>>(px, ln2g + i*DIM, ln2b + i*DIM,
                                         nullptr, pln16);
        gemm_mma<1><<<dim3(MLPD/128, TOK/128), blk256, GEMM_SMEM>>>(
            pln16,
            w1h + (size_t)i*MLPD*DIM, w1l + (size_t)i*MLPD*DIM,
            b1 + (size_t)i*MLPD, nullptr, ph16, TOK, MLPD, DIM);
        gemm_mma<2><<<dim3(DIM/128, TOK/128), blk256, GEMM_SMEM>>>(
            ph16,
            w2h + (size_t)i*DIM*MLPD, w2l + (size_t)i*DIM*MLPD,
            b2 + (size_t)i*DIM, px, nullptr, TOK, DIM, MLPD);
    }

    ln_kernel<false><<<TOK, blk256>>>(px, fng, fnb, (float*)d_out, nullptr);
}

// round 10
// speedup vs baseline: 1.9694x; 1.3098x over previous
#include <cuda_runtime.h>
#include <cuda_bf16.h>
#include <cuda_fp16.h>
#include <math.h>
#include <stdint.h>

#define DIM    768
#define DEPTH  6
#define HEADS  12
#define DHEAD  64
#define INNER  768
#define MLPD   3072
#define BATCH  4
#define SEQ    2048
#define TOK    (BATCH*SEQ)      /* 8192 */
#define QKVD   (3*INNER)        /* 2304 */
#define QSCALE 0.18033688011112042f   /* 0.125 * log2(e) */

// ---------------- scratch (device globals; no allocations) ----------------
__device__ float  g_x   [(size_t)TOK*DIM];    // residual stream fp32
__device__ __half g_qkv16[(size_t)TOK*QKVD];  // fused qkv fp16 (Q pre-scaled)
__device__ __half g_ln16[(size_t)TOK*DIM];    // LN output fp16
__device__ __half g_ct16[(size_t)TOK*DIM];    // attention ctx fp16
__device__ __half g_h16 [(size_t)TOK*MLPD];   // mlp hidden fp16
// transposed fp16 weights [layer][N][K]
__device__ __half g_wqkvt[(size_t)DEPTH*QKVD*DIM];
__device__ __half g_woutt[(size_t)DEPTH*DIM*INNER];
__device__ __half g_w1t  [(size_t)DEPTH*MLPD*DIM];
__device__ __half g_w2t  [(size_t)DEPTH*DIM*MLPD];

// ====================== PTX helpers =======================================
__device__ __forceinline__ uint32_t smem_u32(const void* p){
    uint32_t a;
    asm("{ .reg .u64 t; cvta.to.shared.u64 t, %1; cvt.u32.u64 %0, t; }"
        : "=r"(a) : "l"(p));
    return a;
}
__device__ __forceinline__ void cp16(uint32_t s, const void* g){
    asm volatile("cp.async.cg.shared.global [%0], [%1], 16;" :: "r"(s), "l"(g));
}
#define CP_COMMIT() asm volatile("cp.async.commit_group;" ::: "memory")
#define CP_WAIT1()  asm volatile("cp.async.wait_group 1;" ::: "memory")
#define CP_WAIT0()  asm volatile("cp.async.wait_group 0;" ::: "memory")

__device__ __forceinline__ void ldmx4(uint32_t addr, uint32_t& r0, uint32_t& r1,
                                      uint32_t& r2, uint32_t& r3){
    asm volatile("ldmatrix.sync.aligned.m8n8.x4.shared.b16 {%0,%1,%2,%3}, [%4];"
        : "=r"(r0), "=r"(r1), "=r"(r2), "=r"(r3) : "r"(addr));
}
__device__ __forceinline__ void ldmx4t(uint32_t addr, uint32_t& r0, uint32_t& r1,
                                       uint32_t& r2, uint32_t& r3){
    asm volatile("ldmatrix.sync.aligned.m8n8.x4.trans.shared.b16 {%0,%1,%2,%3}, [%4];"
        : "=r"(r0), "=r"(r1), "=r"(r2), "=r"(r3) : "r"(addr));
}
// fp16 mma
__device__ __forceinline__ void mma16816h(float* c, const uint32_t* a,
                                          uint32_t b0, uint32_t b1){
    asm volatile(
        "mma.sync.aligned.m16n8k16.row.col.f32.f16.f16.f32 "
        "{%0,%1,%2,%3}, {%4,%5,%6,%7}, {%8,%9}, {%0,%1,%2,%3};"
        : "+f"(c[0]), "+f"(c[1]), "+f"(c[2]), "+f"(c[3])
        : "r"(a[0]), "r"(a[1]), "r"(a[2]), "r"(a[3]), "r"(b0), "r"(b1));
}
// FMA-pipe exp2 (degree-6 Taylor on [-0.5,0.5]); valid for t <= 0
__device__ __forceinline__ float exp2_fast(float t){
    t = fmaxf(t, -120.f);
    float n = rintf(t);
    float f = t - n;
    float p = 1.5403530e-4f;
    p = fmaf(p, f, 1.3333558e-3f);
    p = fmaf(p, f, 9.6181291e-3f);
    p = fmaf(p, f, 5.5504109e-2f);
    p = fmaf(p, f, 2.4022651e-1f);
    p = fmaf(p, f, 6.9314718e-1f);
    p = fmaf(p, f, 1.0f);
    return __int_as_float(__float_as_int(p) + (((int)n) << 23));
}

// ====================== weight transpose to fp16 ===========================
__global__ void transpose_cvt(const float* __restrict__ W,
                              __half* __restrict__ Wh, int K, int N)
{
    __shared__ float tile[32][33];
    const size_t off = (size_t)blockIdx.z * K * N;
    const int n0 = blockIdx.x * 32, k0 = blockIdx.y * 32;
    const int tx = threadIdx.x, ty = threadIdx.y;
#pragma unroll
    for (int i = 0; i < 32; i += 8)
        tile[ty + i][tx] = W[off + (size_t)(k0 + ty + i) * N + n0 + tx];
    __syncthreads();
#pragma unroll
    for (int i = 0; i < 32; i += 8) {
        size_t oidx = off + (size_t)(n0 + ty + i) * K + k0 + tx;
        Wh[oidx] = __float2half_rn(tile[tx][ty + i]);
    }
}

// ====================== LayerNorm ==========================================
template<bool HOUT>
__global__ void ln_kernel(const float* __restrict__ x, const float* __restrict__ g,
                          const float* __restrict__ b, float* __restrict__ y,
                          __half* __restrict__ yh)
{
    int t = blockIdx.x;
    const float* xp = x + (size_t)t * DIM;

    float v[3];
    float s1 = 0.f, s2 = 0.f;
#pragma unroll
    for (int i = 0; i < 3; i++) {
        v[i] = xp[threadIdx.x + i * 256];
        s1 += v[i]; s2 += v[i] * v[i];
    }
#pragma unroll
    for (int o = 16; o > 0; o >>= 1) {
        s1 += __shfl_xor_sync(0xffffffffu, s1, o);
        s2 += __shfl_xor_sync(0xffffffffu, s2, o);
    }
    __shared__ float r1[8], r2[8];
    if ((threadIdx.x & 31) == 0) { r1[threadIdx.x >> 5] = s1; r2[threadIdx.x >> 5] = s2; }
    __syncthreads();
    s1 = 0.f; s2 = 0.f;
#pragma unroll
    for (int i = 0; i < 8; i++) { s1 += r1[i]; s2 += r2[i]; }

    float mu  = s1 * (1.f / DIM);
    float var = s2 * (1.f / DIM) - mu * mu;
    float rs  = rsqrtf(var + 1e-5f);
#pragma unroll
    for (int i = 0; i < 3; i++) {
        int d = threadIdx.x + i * 256;
        float yy = (v[i] - mu) * rs * g[d] + b[d];
        if (HOUT) yh[(size_t)t * DIM + d] = __float2half_rn(yy);
        else      y[(size_t)t * DIM + d] = yy;
    }
}

// ====================== fp16 1-product GEMM ================================
// C[M,N] = A[M,K] @ B[N,K]^T; fp16 in, fp32 accum.
// CTA 128x128, warp 32x64, BK=32, 3-stage cp.async.
// Stage: [A 8K][B 8K] = 16KB.
// EPI: 0 = qkv out (scale Q cols, fp16); 1 = +bias, gelu, fp16 out;
//      2 = +bias += xres; 3 = += xres.
#define STAGE_SZ 16384u
template<int EPI>
__global__ void __launch_bounds__(256, 1)
gemm_mma(const __half* __restrict__ Ah, const __half* __restrict__ Bh,
         const float* __restrict__ bias, float* __restrict__ xres,
         __half* __restrict__ Ch, int M, int N, int K)
{
    extern __shared__ char smem[];
    const uint32_t sb0 = smem_u32(smem);
    const int tid  = threadIdx.x;
    const int lane = tid & 31, warp = tid >> 5;
    const int wm = warp >> 1, wn = warp & 1;
    const int bn = blockIdx.x, bm = blockIdx.y;
    const int nkt = K >> 5;

    auto load_stage = [&](int kt, int st){
        const uint32_t base = sb0 + (uint32_t)st * STAGE_SZ;
        const size_t kof = (size_t)kt * 32;
#pragma unroll
        for (int i = 0; i < 2; i++) {
            const int idx = tid + i * 256;
            const int row = idx >> 2, c = idx & 3;
            const uint32_t so = (uint32_t)(row * 64 + ((c ^ ((row >> 1) & 3)) << 4));
            const size_t ga = (size_t)(bm * 128 + row) * K + kof + c * 8;
            const size_t gb = (size_t)(bn * 128 + row) * K + kof + c * 8;
            cp16(base + so,         Ah + ga);
            cp16(base + 8192u + so, Bh + gb);
        }
    };

    float acc[2][8][4];
#pragma unroll
    for (int mt = 0; mt < 2; mt++)
#pragma unroll
        for (int nt = 0; nt < 8; nt++)
#pragma unroll
            for (int q = 0; q < 4; q++) acc[mt][nt][q] = 0.f;

    load_stage(0, 0); CP_COMMIT();
    load_stage(1, 1); CP_COMMIT();

    const int arow = wm * 32 + (lane & 15);
    const int acs  = lane >> 4;
    const int brow = wn * 64 + (lane & 7) + ((lane >> 4) << 3);
    const int bcs  = (lane >> 3) & 1;

    for (int kt = 0; kt < nkt; kt++) {
        if (kt == nkt - 1) { CP_WAIT0(); } else { CP_WAIT1(); }
        __syncthreads();
        if (kt + 2 < nkt) { load_stage(kt + 2, (kt + 2) % 3); CP_COMMIT(); }

        const uint32_t base = sb0 + (uint32_t)(kt % 3) * STAGE_SZ;
#pragma unroll
        for (int ks = 0; ks < 2; ks++) {
            uint32_t ah[2][4];
#pragma unroll
            for (int mt = 0; mt < 2; mt++) {
                const int r = arow + mt * 16;
                const int c = ks * 2 + acs;
                const uint32_t off = (uint32_t)(r * 64 + ((c ^ ((r >> 1) & 3)) << 4));
                ldmx4(base + off, ah[mt][0], ah[mt][1], ah[mt][2], ah[mt][3]);
            }
#pragma unroll
            for (int bt = 0; bt < 4; bt++) {
                const int r = brow + bt * 16;
                const int c = ks * 2 + bcs;
                const uint32_t off = (uint32_t)(r * 64 + ((c ^ ((r >> 1) & 3)) << 4));
                uint32_t bh[4];
                ldmx4(base + 8192u + off, bh[0], bh[1], bh[2], bh[3]);
#pragma unroll
                for (int mt = 0; mt < 2; mt++) {
                    mma16816h(acc[mt][2*bt],   ah[mt], bh[0], bh[1]);
                    mma16816h(acc[mt][2*bt+1], ah[mt], bh[2], bh[3]);
                }
            }
        }
        __syncthreads();
    }

    const int rbase = bm * 128 + wm * 32 + (lane >> 2);
    const int cbase = bn * 128 + wn * 64 + (lane & 3) * 2;
#pragma unroll
    for (int mt = 0; mt < 2; mt++) {
#pragma unroll
        for (int nt = 0; nt < 8; nt++) {
            const int gcol = cbase + nt * 8;
#pragma unroll
            for (int h = 0; h < 2; h++) {
                const int grow = rbase + mt * 16 + h * 8;
                float v0 = acc[mt][nt][2*h], v1 = acc[mt][nt][2*h+1];
                const size_t oidx = (size_t)grow * N + gcol;
                if (EPI == 0 || EPI == 1) {
                    if (EPI == 0) {
                        const float sc = (gcol < INNER) ? QSCALE : 1.f;
                        v0 *= sc; v1 *= sc;
                    } else {
                        v0 += bias[gcol];     v1 += bias[gcol + 1];
                        v0 = 0.5f * v0 * (1.f + erff(v0 * 0.70710678118654752f));
                        v1 = 0.5f * v1 * (1.f + erff(v1 * 0.70710678118654752f));
                    }
                    __half h0 = __float2half_rn(v0), h1 = __float2half_rn(v1);
                    *reinterpret_cast<uint32_t*>(Ch + oidx) =
                        (uint32_t)__half_as_ushort(h0) |
                        ((uint32_t)__half_as_ushort(h1) << 16);
                } else {
                    float2 xv = *reinterpret_cast<const float2*>(xres + oidx);
                    if (EPI == 2) { v0 += bias[gcol]; v1 += bias[gcol + 1]; }
                    xv.x += v0; xv.y += v1;
                    *reinterpret_cast<float2*>(xres + oidx) = xv;
                }
            }
        }
    }
}

// ====================== fp16 1-product flash attention =====================
// grid (SEQ/128, HEADS, BATCH), 256 threads (8 warps x 16 query rows).
#define ATTN_SMEM (16384 + 2*16384)
__global__ void __launch_bounds__(256, 1)
attn_mma(const __half* __restrict__ qkv, __half* __restrict__ ctx)
{
    extern __shared__ char smem[];
    const uint32_t sb = smem_u32(smem);
    const uint32_t QS = sb;
    const int tid = threadIdx.x, lane = tid & 31, wid = tid >> 5;
    const int b = blockIdx.z, h = blockIdx.y, qt = blockIdx.x;
    const int tok0 = b * SEQ + qt * 128;

#pragma unroll
    for (int i = 0; i < 4; i++) {
        const int idx = tid + i * 256;
        const int row = idx >> 3, c = idx & 7;
        const uint32_t so = (uint32_t)(row * 128 + ((c ^ (row & 7)) << 4));
        cp16(QS + so, qkv + (size_t)(tok0 + row) * QKVD + h * DHEAD + c * 8);
    }

    auto load_kv = [&](int t, int st){
        const uint32_t base = sb + 16384u + (uint32_t)st * 16384u;
        const int kv0 = b * SEQ + t * 64;
#pragma unroll
        for (int i = 0; i < 2; i++) {
            const int idx = tid + i * 256;
            const int row = idx >> 3, c = idx & 7;
            const uint32_t so = (uint32_t)(row * 128 + ((c ^ (row & 7)) << 4));
            const size_t gk = (size_t)(kv0 + row) * QKVD + INNER + h * DHEAD + c * 8;
            const size_t gv = (size_t)(kv0 + row) * QKVD + 2 * INNER + h * DHEAD + c * 8;
            cp16(base + so,         qkv + gk);
            cp16(base + 8192u + so, qkv + gv);
        }
    };
    load_kv(0, 0); CP_COMMIT();

    float O[8][4];
#pragma unroll
    for (int nt = 0; nt < 8; nt++)
#pragma unroll
        for (int q = 0; q < 4; q++) O[nt][q] = 0.f;
    float m0 = -1e30f, m1 = -1e30f, l0 = 0.f, l1 = 0.f;
    const int m0row = wid * 16;

    const int NT = SEQ / 64;
    for (int t = 0; t < NT; t++) {
        if (t + 1 < NT) { load_kv(t + 1, (t + 1) & 1); CP_COMMIT(); CP_WAIT1(); }
        else            { CP_WAIT0(); }
        __syncthreads();
        const uint32_t kb = sb + 16384u + (uint32_t)(t & 1) * 16384u;

        float S[8][4];
#pragma unroll
        for (int nt = 0; nt < 8; nt++)
#pragma unroll
            for (int q = 0; q < 4; q++) S[nt][q] = 0.f;
#pragma unroll
        for (int ks = 0; ks < 4; ks++) {
            uint32_t qf[4];
            {
                const int r = m0row + (lane & 15);
                const int c = ks * 2 + (lane >> 4);
                const uint32_t off = (uint32_t)(r * 128 + ((c ^ (r & 7)) << 4));
                ldmx4(QS + off, qf[0], qf[1], qf[2], qf[3]);
            }
#pragma unroll
            for (int bt = 0; bt < 4; bt++) {
                const int r = bt * 16 + (lane & 7) + ((lane >> 4) << 3);
                const int c = ks * 2 + ((lane >> 3) & 1);
                const uint32_t off = (uint32_t)(r * 128 + ((c ^ (r & 7)) << 4));
                uint32_t kh[4];
                ldmx4(kb + off, kh[0], kh[1], kh[2], kh[3]);
                mma16816h(S[2*bt],   qf, kh[0], kh[1]);
                mma16816h(S[2*bt+1], qf, kh[2], kh[3]);
            }
        }

        float mt0 = -1e30f, mt1 = -1e30f;
#pragma unroll
        for (int nt = 0; nt < 8; nt++) {
            mt0 = fmaxf(mt0, fmaxf(S[nt][0], S[nt][1]));
            mt1 = fmaxf(mt1, fmaxf(S[nt][2], S[nt][3]));
        }
        mt0 = fmaxf(mt0, __shfl_xor_sync(0xffffffffu, mt0, 1));
        mt0 = fmaxf(mt0, __shfl_xor_sync(0xffffffffu, mt0, 2));
        mt1 = fmaxf(mt1, __shfl_xor_sync(0xffffffffu, mt1, 1));
        mt1 = fmaxf(mt1, __shfl_xor_sync(0xffffffffu, mt1, 2));
        const float mn0 = fmaxf(m0, mt0), mn1 = fmaxf(m1, mt1);
        const float cr0 = exp2_fast(m0 - mn0), cr1 = exp2_fast(m1 - mn1);
        m0 = mn0; m1 = mn1;

        uint32_t phi[4][4];
        float s0 = 0.f, s1 = 0.f;
#pragma unroll
        for (int nt = 0; nt < 8; nt++) {
            float p0 = exp2_fast(S[nt][0] - m0);
            float p1 = exp2_fast(S[nt][1] - m0);
            float p2 = exp2_fast(S[nt][2] - m1);
            float p3 = exp2_fast(S[nt][3] - m1);
            s0 += p0 + p1; s1 += p2 + p3;
            __half h0 = __float2half_rn(p0), h1 = __float2half_rn(p1);
            __half h2 = __float2half_rn(p2), h3 = __float2half_rn(p3);
            const int t2 = nt >> 1, o = (nt & 1) * 2;
            phi[t2][o] = (uint32_t)__half_as_ushort(h0) |
                         ((uint32_t)__half_as_ushort(h1) << 16);
            phi[t2][o+1] = (uint32_t)__half_as_ushort(h2) |
                           ((uint32_t)__half_as_ushort(h3) << 16);
        }
        s0 += __shfl_xor_sync(0xffffffffu, s0, 1);
        s0 += __shfl_xor_sync(0xffffffffu, s0, 2);
        s1 += __shfl_xor_sync(0xffffffffu, s1, 1);
        s1 += __shfl_xor_sync(0xffffffffu, s1, 2);
        l0 = l0 * cr0 + s0;
        l1 = l1 * cr1 + s1;
#pragma unroll
        for (int nt = 0; nt < 8; nt++) {
            O[nt][0] *= cr0; O[nt][1] *= cr0;
            O[nt][2] *= cr1; O[nt][3] *= cr1;
        }

#pragma unroll
        for (int t2 = 0; t2 < 4; t2++) {
#pragma unroll
            for (int dn = 0; dn < 4; dn++) {
                const int r = t2 * 16 + (lane & 15);
                const int c = dn * 2 + (lane >> 4);
                const uint32_t off = (uint32_t)(r * 128 + ((c ^ (r & 7)) << 4));
                uint32_t vh[4];
                ldmx4t(kb + 8192u + off, vh[0], vh[1], vh[2], vh[3]);
                mma16816h(O[2*dn],   phi[t2], vh[0], vh[1]);
                mma16816h(O[2*dn+1], phi[t2], vh[2], vh[3]);
            }
        }
        __syncthreads();
    }

    const float i0 = 1.f / l0, i1 = 1.f / l1;
    const int r0 = tok0 + m0row + (lane >> 2);
#pragma unroll
    for (int nt = 0; nt < 8; nt++) {
        const int col = h * DHEAD + nt * 8 + (lane & 3) * 2;
#pragma unroll
        for (int hh = 0; hh < 2; hh++) {
            const float inv = hh ? i1 : i0;
            float v0 = O[nt][2*hh] * inv, v1 = O[nt][2*hh+1] * inv;
            __half h0 = __float2half_rn(v0), h1 = __float2half_rn(v1);
            const size_t oidx = (size_t)(r0 + hh * 8) * DIM + col;
            *reinterpret_cast<uint32_t*>(ctx + oidx) =
                (uint32_t)__half_as_ushort(h0) |
                ((uint32_t)__half_as_ushort(h1) << 16);
        }
    }
}

// ====================== driver =============================================
#define GEMM_SMEM (3 * 16384)

extern "C" void kernel_launch(void* const* d_in, const int* in_sizes, int n_in,
                              void* d_out, int out_size)
{
    const float* x    = (const float*)d_in[0];
    const float* ln1g = (const float*)d_in[1];
    const float* ln1b = (const float*)d_in[2];
    const float* wqkv = (const float*)d_in[3];
    const float* wout = (const float*)d_in[4];
    const float* ln2g = (const float*)d_in[5];
    const float* ln2b = (const float*)d_in[6];
    const float* w1   = (const float*)d_in[7];
    const float* b1   = (const float*)d_in[8];
    const float* w2   = (const float*)d_in[9];
    const float* b2   = (const float*)d_in[10];
    const float* fng  = (const float*)d_in[11];
    const float* fnb  = (const float*)d_in[12];

    float *px;
    __half *pqkv, *pln16, *pct16, *ph16;
    __half *qkvt, *outt, *w1t, *w2t;
    cudaGetSymbolAddress((void**)&px,    g_x);
    cudaGetSymbolAddress((void**)&pqkv,  g_qkv16);
    cudaGetSymbolAddress((void**)&pln16, g_ln16);
    cudaGetSymbolAddress((void**)&pct16, g_ct16);
    cudaGetSymbolAddress((void**)&ph16,  g_h16);
    cudaGetSymbolAddress((void**)&qkvt,  g_wqkvt);
    cudaGetSymbolAddress((void**)&outt,  g_woutt);
    cudaGetSymbolAddress((void**)&w1t,   g_w1t);
    cudaGetSymbolAddress((void**)&w2t,   g_w2t);

    cudaFuncSetAttribute(gemm_mma<0>, cudaFuncAttributeMaxDynamicSharedMemorySize, GEMM_SMEM);
    cudaFuncSetAttribute(gemm_mma<1>, cudaFuncAttributeMaxDynamicSharedMemorySize, GEMM_SMEM);
    cudaFuncSetAttribute(gemm_mma<2>, cudaFuncAttributeMaxDynamicSharedMemorySize, GEMM_SMEM);
    cudaFuncSetAttribute(gemm_mma<3>, cudaFuncAttributeMaxDynamicSharedMemorySize, GEMM_SMEM);
    cudaFuncSetAttribute(attn_mma, cudaFuncAttributeMaxDynamicSharedMemorySize, ATTN_SMEM);

    {
        dim3 tblk(32, 8);
        transpose_cvt<<<dim3(QKVD/32, DIM/32, DEPTH), tblk>>>(wqkv, qkvt, DIM, QKVD);
        transpose_cvt<<<dim3(DIM/32, INNER/32, DEPTH), tblk>>>(wout, outt, INNER, DIM);
        transpose_cvt<<<dim3(MLPD/32, DIM/32, DEPTH), tblk>>>(w1, w1t, DIM, MLPD);
        transpose_cvt<<<dim3(DIM/32, MLPD/32, DEPTH), tblk>>>(w2, w2t, MLPD, DIM);
    }

    cudaMemcpyAsync(px, x, sizeof(float) * (size_t)TOK * DIM,
                    cudaMemcpyDeviceToDevice, 0);

    const dim3 blk256(256);
    for (int i = 0; i < DEPTH; i++) {
        ln_kernel<true><<<TOK, blk256>>>(px, ln1g + i*DIM, ln1b + i*DIM,
                                         nullptr, pln16);
        gemm_mma<0><<<dim3(QKVD/128, TOK/128), blk256, GEMM_SMEM>>>(
            pln16, qkvt + (size_t)i*QKVD*DIM,
            nullptr, nullptr, pqkv, TOK, QKVD, DIM);
        attn_mma<<<dim3(SEQ/128, HEADS, BATCH), blk256, ATTN_SMEM>>>(pqkv, pct16);
        gemm_mma<3><<<dim3(DIM/128, TOK/128), blk256, GEMM_SMEM>>>(
            pct16, outt + (size_t)i*DIM*INNER,
            nullptr, px, nullptr, TOK, DIM, INNER);

        ln_kernel<true><<<TOK, blk256>>>(px, ln2g + i*DIM, ln2b + i*DIM,
                                         nullptr, pln16);
        gemm_mma<1><<<dim3(MLPD/128, TOK/128), blk256, GEMM_SMEM>>>(
            pln16, w1t + (size_t)i*MLPD*DIM,
            b1 + (size_t)i*MLPD, nullptr, ph16, TOK, MLPD, DIM);
        gemm_mma<2><<<dim3(DIM/128, TOK/128), blk256, GEMM_SMEM>>>(
            ph16, w2t + (size_t)i*DIM*MLPD,
            b2 + (size_t)i*DIM, px, nullptr, TOK, DIM, MLPD);
    }

    ln_kernel<false><<<TOK, blk256>>>(px, fng, fnb, (float*)d_out, nullptr);
}

// round 11
// speedup vs baseline: 2.5178x; 1.2784x over previous
#include <cuda_runtime.h>
#include <cuda_bf16.h>
#include <cuda_fp16.h>
#include <math.h>
#include <stdint.h>

#define DIM    768
#define DEPTH  6
#define HEADS  12
#define DHEAD  64
#define INNER  768
#define MLPD   3072
#define BATCH  4
#define SEQ    2048
#define TOK    (BATCH*SEQ)      /* 8192 */
#define QKVD   (3*INNER)        /* 2304 */
#define QSCALE 0.18033688011112042f   /* 0.125 * log2(e) */

// ---------------- scratch (device globals; no allocations) ----------------
__device__ float  g_x   [(size_t)TOK*DIM];    // residual stream fp32
__device__ __half g_qkv16[(size_t)TOK*QKVD];  // fused qkv fp16 (Q pre-scaled)
__device__ __half g_ln16[(size_t)TOK*DIM];    // LN output fp16
__device__ __half g_ct16[(size_t)TOK*DIM];    // attention ctx fp16
__device__ __half g_h16 [(size_t)TOK*MLPD];   // mlp hidden fp16
// transposed fp16 weights [layer][N][K]
__device__ __half g_wqkvt[(size_t)DEPTH*QKVD*DIM];
__device__ __half g_woutt[(size_t)DEPTH*DIM*INNER];
__device__ __half g_w1t  [(size_t)DEPTH*MLPD*DIM];
__device__ __half g_w2t  [(size_t)DEPTH*DIM*MLPD];

// ====================== PTX helpers =======================================
__device__ __forceinline__ uint32_t smem_u32(const void* p){
    uint32_t a;
    asm("{ .reg .u64 t; cvta.to.shared.u64 t, %1; cvt.u32.u64 %0, t; }"
        : "=r"(a) : "l"(p));
    return a;
}
__device__ __forceinline__ void cp16(uint32_t s, const void* g){
    asm volatile("cp.async.cg.shared.global [%0], [%1], 16;" :: "r"(s), "l"(g));
}
#define CP_COMMIT() asm volatile("cp.async.commit_group;" ::: "memory")
#define CP_WAIT1()  asm volatile("cp.async.wait_group 1;" ::: "memory")
#define CP_WAIT0()  asm volatile("cp.async.wait_group 0;" ::: "memory")

__device__ __forceinline__ void ldmx4(uint32_t addr, uint32_t& r0, uint32_t& r1,
                                      uint32_t& r2, uint32_t& r3){
    asm volatile("ldmatrix.sync.aligned.m8n8.x4.shared.b16 {%0,%1,%2,%3}, [%4];"
        : "=r"(r0), "=r"(r1), "=r"(r2), "=r"(r3) : "r"(addr));
}
__device__ __forceinline__ void ldmx4t(uint32_t addr, uint32_t& r0, uint32_t& r1,
                                       uint32_t& r2, uint32_t& r3){
    asm volatile("ldmatrix.sync.aligned.m8n8.x4.trans.shared.b16 {%0,%1,%2,%3}, [%4];"
        : "=r"(r0), "=r"(r1), "=r"(r2), "=r"(r3) : "r"(addr));
}
// fp16 mma
__device__ __forceinline__ void mma16816h(float* c, const uint32_t* a,
                                          uint32_t b0, uint32_t b1){
    asm volatile(
        "mma.sync.aligned.m16n8k16.row.col.f32.f16.f16.f32 "
        "{%0,%1,%2,%3}, {%4,%5,%6,%7}, {%8,%9}, {%0,%1,%2,%3};"
        : "+f"(c[0]), "+f"(c[1]), "+f"(c[2]), "+f"(c[3])
        : "r"(a[0]), "r"(a[1]), "r"(a[2]), "r"(a[3]), "r"(b0), "r"(b1));
}
// FMA-pipe exp2 (degree-6 Taylor on [-0.5,0.5]); valid for t <= 0
__device__ __forceinline__ float exp2_fast(float t){
    t = fmaxf(t, -120.f);
    float n = rintf(t);
    float f = t - n;
    float p = 1.5403530e-4f;
    p = fmaf(p, f, 1.3333558e-3f);
    p = fmaf(p, f, 9.6181291e-3f);
    p = fmaf(p, f, 5.5504109e-2f);
    p = fmaf(p, f, 2.4022651e-1f);
    p = fmaf(p, f, 6.9314718e-1f);
    p = fmaf(p, f, 1.0f);
    return __int_as_float(__float_as_int(p) + (((int)n) << 23));
}

// ====================== weight transpose to fp16 ===========================
__global__ void transpose_cvt(const float* __restrict__ W,
                              __half* __restrict__ Wh, int K, int N)
{
    __shared__ float tile[32][33];
    const size_t off = (size_t)blockIdx.z * K * N;
    const int n0 = blockIdx.x * 32, k0 = blockIdx.y * 32;
    const int tx = threadIdx.x, ty = threadIdx.y;
#pragma unroll
    for (int i = 0; i < 32; i += 8)
        tile[ty + i][tx] = W[off + (size_t)(k0 + ty + i) * N + n0 + tx];
    __syncthreads();
#pragma unroll
    for (int i = 0; i < 32; i += 8) {
        size_t oidx = off + (size_t)(n0 + ty + i) * K + k0 + tx;
        Wh[oidx] = __float2half_rn(tile[tx][ty + i]);
    }
}

// ====================== LayerNorm ==========================================
template<bool HOUT>
__global__ void ln_kernel(const float* __restrict__ x, const float* __restrict__ g,
                          const float* __restrict__ b, float* __restrict__ y,
                          __half* __restrict__ yh)
{
    int t = blockIdx.x;
    const float* xp = x + (size_t)t * DIM;

    float v[3];
    float s1 = 0.f, s2 = 0.f;
#pragma unroll
    for (int i = 0; i < 3; i++) {
        v[i] = xp[threadIdx.x + i * 256];
        s1 += v[i]; s2 += v[i] * v[i];
    }
#pragma unroll
    for (int o = 16; o > 0; o >>= 1) {
        s1 += __shfl_xor_sync(0xffffffffu, s1, o);
        s2 += __shfl_xor_sync(0xffffffffu, s2, o);
    }
    __shared__ float r1[8], r2[8];
    if ((threadIdx.x & 31) == 0) { r1[threadIdx.x >> 5] = s1; r2[threadIdx.x >> 5] = s2; }
    __syncthreads();
    s1 = 0.f; s2 = 0.f;
#pragma unroll
    for (int i = 0; i < 8; i++) { s1 += r1[i]; s2 += r2[i]; }

    float mu  = s1 * (1.f / DIM);
    float var = s2 * (1.f / DIM) - mu * mu;
    float rs  = rsqrtf(var + 1e-5f);
#pragma unroll
    for (int i = 0; i < 3; i++) {
        int d = threadIdx.x + i * 256;
        float yy = (v[i] - mu) * rs * g[d] + b[d];
        if (HOUT) yh[(size_t)t * DIM + d] = __float2half_rn(yy);
        else      y[(size_t)t * DIM + d] = yy;
    }
}

// ====================== fp16 1-product GEMM (2 CTAs/SM) ====================
// C[M,N] = A[M,K] @ B[N,K]^T; fp16 in, fp32 accum.
// CTA 128x128, warp 32x64, BK=32, 3-stage cp.async, 48KB smem -> 2 CTAs/SM.
// EPI: 0 = qkv out (scale Q cols, fp16); 1 = +bias, gelu, fp16 out;
//      2 = +bias += xres; 3 = += xres.
#define STAGE_SZ 16384u
template<int EPI>
__global__ void __launch_bounds__(256, 2)
gemm_mma(const __half* __restrict__ Ah, const __half* __restrict__ Bh,
         const float* __restrict__ bias, float* __restrict__ xres,
         __half* __restrict__ Ch, int M, int N, int K)
{
    extern __shared__ char smem[];
    const uint32_t sb0 = smem_u32(smem);
    const int tid  = threadIdx.x;
    const int lane = tid & 31, warp = tid >> 5;
    const int wm = warp >> 1, wn = warp & 1;
    const int bn = blockIdx.x, bm = blockIdx.y;
    const int nkt = K >> 5;

    auto load_stage = [&](int kt, int st){
        const uint32_t base = sb0 + (uint32_t)st * STAGE_SZ;
        const size_t kof = (size_t)kt * 32;
#pragma unroll
        for (int i = 0; i < 2; i++) {
            const int idx = tid + i * 256;
            const int row = idx >> 2, c = idx & 3;
            const uint32_t so = (uint32_t)(row * 64 + ((c ^ ((row >> 1) & 3)) << 4));
            const size_t ga = (size_t)(bm * 128 + row) * K + kof + c * 8;
            const size_t gb = (size_t)(bn * 128 + row) * K + kof + c * 8;
            cp16(base + so,         Ah + ga);
            cp16(base + 8192u + so, Bh + gb);
        }
    };

    float acc[2][8][4];
#pragma unroll
    for (int mt = 0; mt < 2; mt++)
#pragma unroll
        for (int nt = 0; nt < 8; nt++)
#pragma unroll
            for (int q = 0; q < 4; q++) acc[mt][nt][q] = 0.f;

    load_stage(0, 0); CP_COMMIT();
    load_stage(1, 1); CP_COMMIT();

    const int arow = wm * 32 + (lane & 15);
    const int acs  = lane >> 4;
    const int brow = wn * 64 + (lane & 7) + ((lane >> 4) << 3);
    const int bcs  = (lane >> 3) & 1;

    for (int kt = 0; kt < nkt; kt++) {
        if (kt == nkt - 1) { CP_WAIT0(); } else { CP_WAIT1(); }
        __syncthreads();
        if (kt + 2 < nkt) { load_stage(kt + 2, (kt + 2) % 3); CP_COMMIT(); }

        const uint32_t base = sb0 + (uint32_t)(kt % 3) * STAGE_SZ;
#pragma unroll
        for (int ks = 0; ks < 2; ks++) {
            uint32_t ah[2][4];
#pragma unroll
            for (int mt = 0; mt < 2; mt++) {
                const int r = arow + mt * 16;
                const int c = ks * 2 + acs;
                const uint32_t off = (uint32_t)(r * 64 + ((c ^ ((r >> 1) & 3)) << 4));
                ldmx4(base + off, ah[mt][0], ah[mt][1], ah[mt][2], ah[mt][3]);
            }
#pragma unroll
            for (int bt = 0; bt < 4; bt++) {
                const int r = brow + bt * 16;
                const int c = ks * 2 + bcs;
                const uint32_t off = (uint32_t)(r * 64 + ((c ^ ((r >> 1) & 3)) << 4));
                uint32_t bh[4];
                ldmx4(base + 8192u + off, bh[0], bh[1], bh[2], bh[3]);
#pragma unroll
                for (int mt = 0; mt < 2; mt++) {
                    mma16816h(acc[mt][2*bt],   ah[mt], bh[0], bh[1]);
                    mma16816h(acc[mt][2*bt+1], ah[mt], bh[2], bh[3]);
                }
            }
        }
        __syncthreads();
    }

    const int rbase = bm * 128 + wm * 32 + (lane >> 2);
    const int cbase = bn * 128 + wn * 64 + (lane & 3) * 2;
#pragma unroll
    for (int mt = 0; mt < 2; mt++) {
#pragma unroll
        for (int nt = 0; nt < 8; nt++) {
            const int gcol = cbase + nt * 8;
#pragma unroll
            for (int h = 0; h < 2; h++) {
                const int grow = rbase + mt * 16 + h * 8;
                float v0 = acc[mt][nt][2*h], v1 = acc[mt][nt][2*h+1];
                const size_t oidx = (size_t)grow * N + gcol;
                if (EPI == 0 || EPI == 1) {
                    if (EPI == 0) {
                        const float sc = (gcol < INNER) ? QSCALE : 1.f;
                        v0 *= sc; v1 *= sc;
                    } else {
                        v0 += bias[gcol];     v1 += bias[gcol + 1];
                        v0 = 0.5f * v0 * (1.f + erff(v0 * 0.70710678118654752f));
                        v1 = 0.5f * v1 * (1.f + erff(v1 * 0.70710678118654752f));
                    }
                    __half h0 = __float2half_rn(v0), h1 = __float2half_rn(v1);
                    *reinterpret_cast<uint32_t*>(Ch + oidx) =
                        (uint32_t)__half_as_ushort(h0) |
                        ((uint32_t)__half_as_ushort(h1) << 16);
                } else {
                    float2 xv = *reinterpret_cast<const float2*>(xres + oidx);
                    if (EPI == 2) { v0 += bias[gcol]; v1 += bias[gcol + 1]; }
                    xv.x += v0; xv.y += v1;
                    *reinterpret_cast<float2*>(xres + oidx) = xv;
                }
            }
        }
    }
}

// ====================== fp16 1-product flash attention (2 CTAs/SM) =========
// grid (SEQ/128, HEADS, BATCH), 256 threads (8 warps x 16 query rows).
#define ATTN_SMEM (16384 + 2*16384)
__global__ void __launch_bounds__(256, 2)
attn_mma(const __half* __restrict__ qkv, __half* __restrict__ ctx)
{
    extern __shared__ char smem[];
    const uint32_t sb = smem_u32(smem);
    const uint32_t QS = sb;
    const int tid = threadIdx.x, lane = tid & 31, wid = tid >> 5;
    const int b = blockIdx.z, h = blockIdx.y, qt = blockIdx.x;
    const int tok0 = b * SEQ + qt * 128;

#pragma unroll
    for (int i = 0; i < 4; i++) {
        const int idx = tid + i * 256;
        const int row = idx >> 3, c = idx & 7;
        const uint32_t so = (uint32_t)(row * 128 + ((c ^ (row & 7)) << 4));
        cp16(QS + so, qkv + (size_t)(tok0 + row) * QKVD + h * DHEAD + c * 8);
    }

    auto load_kv = [&](int t, int st){
        const uint32_t base = sb + 16384u + (uint32_t)st * 16384u;
        const int kv0 = b * SEQ + t * 64;
#pragma unroll
        for (int i = 0; i < 2; i++) {
            const int idx = tid + i * 256;
            const int row = idx >> 3, c = idx & 7;
            const uint32_t so = (uint32_t)(row * 128 + ((c ^ (row & 7)) << 4));
            const size_t gk = (size_t)(kv0 + row) * QKVD + INNER + h * DHEAD + c * 8;
            const size_t gv = (size_t)(kv0 + row) * QKVD + 2 * INNER + h * DHEAD + c * 8;
            cp16(base + so,         qkv + gk);
            cp16(base + 8192u + so, qkv + gv);
        }
    };
    load_kv(0, 0); CP_COMMIT();

    float O[8][4];
#pragma unroll
    for (int nt = 0; nt < 8; nt++)
#pragma unroll
        for (int q = 0; q < 4; q++) O[nt][q] = 0.f;
    float m0 = -1e30f, m1 = -1e30f, l0 = 0.f, l1 = 0.f;
    const int m0row = wid * 16;

    const int NT = SEQ / 64;
    for (int t = 0; t < NT; t++) {
        if (t + 1 < NT) { load_kv(t + 1, (t + 1) & 1); CP_COMMIT(); CP_WAIT1(); }
        else            { CP_WAIT0(); }
        __syncthreads();
        const uint32_t kb = sb + 16384u + (uint32_t)(t & 1) * 16384u;

        float S[8][4];
#pragma unroll
        for (int nt = 0; nt < 8; nt++)
#pragma unroll
            for (int q = 0; q < 4; q++) S[nt][q] = 0.f;
#pragma unroll
        for (int ks = 0; ks < 4; ks++) {
            uint32_t qf[4];
            {
                const int r = m0row + (lane & 15);
                const int c = ks * 2 + (lane >> 4);
                const uint32_t off = (uint32_t)(r * 128 + ((c ^ (r & 7)) << 4));
                ldmx4(QS + off, qf[0], qf[1], qf[2], qf[3]);
            }
#pragma unroll
            for (int bt = 0; bt < 4; bt++) {
                const int r = bt * 16 + (lane & 7) + ((lane >> 4) << 3);
                const int c = ks * 2 + ((lane >> 3) & 1);
                const uint32_t off = (uint32_t)(r * 128 + ((c ^ (r & 7)) << 4));
                uint32_t kh[4];
                ldmx4(kb + off, kh[0], kh[1], kh[2], kh[3]);
                mma16816h(S[2*bt],   qf, kh[0], kh[1]);
                mma16816h(S[2*bt+1], qf, kh[2], kh[3]);
            }
        }

        float mt0 = -1e30f, mt1 = -1e30f;
#pragma unroll
        for (int nt = 0; nt < 8; nt++) {
            mt0 = fmaxf(mt0, fmaxf(S[nt][0], S[nt][1]));
            mt1 = fmaxf(mt1, fmaxf(S[nt][2], S[nt][3]));
        }
        mt0 = fmaxf(mt0, __shfl_xor_sync(0xffffffffu, mt0, 1));
        mt0 = fmaxf(mt0, __shfl_xor_sync(0xffffffffu, mt0, 2));
        mt1 = fmaxf(mt1, __shfl_xor_sync(0xffffffffu, mt1, 1));
        mt1 = fmaxf(mt1, __shfl_xor_sync(0xffffffffu, mt1, 2));
        const float mn0 = fmaxf(m0, mt0), mn1 = fmaxf(m1, mt1);
        const float cr0 = exp2_fast(m0 - mn0), cr1 = exp2_fast(m1 - mn1);
        m0 = mn0; m1 = mn1;

        uint32_t phi[4][4];
        float s0 = 0.f, s1 = 0.f;
#pragma unroll
        for (int nt = 0; nt < 8; nt++) {
            float p0 = exp2_fast(S[nt][0] - m0);
            float p1 = exp2_fast(S[nt][1] - m0);
            float p2 = exp2_fast(S[nt][2] - m1);
            float p3 = exp2_fast(S[nt][3] - m1);
            s0 += p0 + p1; s1 += p2 + p3;
            __half h0 = __float2half_rn(p0), h1 = __float2half_rn(p1);
            __half h2 = __float2half_rn(p2), h3 = __float2half_rn(p3);
            const int t2 = nt >> 1, o = (nt & 1) * 2;
            phi[t2][o] = (uint32_t)__half_as_ushort(h0) |
                         ((uint32_t)__half_as_ushort(h1) << 16);
            phi[t2][o+1] = (uint32_t)__half_as_ushort(h2) |
                           ((uint32_t)__half_as_ushort(h3) << 16);
        }
        s0 += __shfl_xor_sync(0xffffffffu, s0, 1);
        s0 += __shfl_xor_sync(0xffffffffu, s0, 2);
        s1 += __shfl_xor_sync(0xffffffffu, s1, 1);
        s1 += __shfl_xor_sync(0xffffffffu, s1, 2);
        l0 = l0 * cr0 + s0;
        l1 = l1 * cr1 + s1;
#pragma unroll
        for (int nt = 0; nt < 8; nt++) {
            O[nt][0] *= cr0; O[nt][1] *= cr0;
            O[nt][2] *= cr1; O[nt][3] *= cr1;
        }

#pragma unroll
        for (int t2 = 0; t2 < 4; t2++) {
#pragma unroll
            for (int dn = 0; dn < 4; dn++) {
                const int r = t2 * 16 + (lane & 15);
                const int c = dn * 2 + (lane >> 4);
                const uint32_t off = (uint32_t)(r * 128 + ((c ^ (r & 7)) << 4));
                uint32_t vh[4];
                ldmx4t(kb + 8192u + off, vh[0], vh[1], vh[2], vh[3]);
                mma16816h(O[2*dn],   phi[t2], vh[0], vh[1]);
                mma16816h(O[2*dn+1], phi[t2], vh[2], vh[3]);
            }
        }
        __syncthreads();
    }

    const float i0 = 1.f / l0, i1 = 1.f / l1;
    const int r0 = tok0 + m0row + (lane >> 2);
#pragma unroll
    for (int nt = 0; nt < 8; nt++) {
        const int col = h * DHEAD + nt * 8 + (lane & 3) * 2;
#pragma unroll
        for (int hh = 0; hh < 2; hh++) {
            const float inv = hh ? i1 : i0;
            float v0 = O[nt][2*hh] * inv, v1 = O[nt][2*hh+1] * inv;
            __half h0 = __float2half_rn(v0), h1 = __float2half_rn(v1);
            const size_t oidx = (size_t)(r0 + hh * 8) * DIM + col;
            *reinterpret_cast<uint32_t*>(ctx + oidx) =
                (uint32_t)__half_as_ushort(h0) |
                ((uint32_t)__half_as_ushort(h1) << 16);
        }
    }
}

// ====================== driver =============================================
#define GEMM_SMEM (3 * 16384)

extern "C" void kernel_launch(void* const* d_in, const int* in_sizes, int n_in,
                              void* d_out, int out_size)
{
    const float* x    = (const float*)d_in[0];
    const float* ln1g = (const float*)d_in[1];
    const float* ln1b = (const float*)d_in[2];
    const float* wqkv = (const float*)d_in[3];
    const float* wout = (const float*)d_in[4];
    const float* ln2g = (const float*)d_in[5];
    const float* ln2b = (const float*)d_in[6];
    const float* w1   = (const float*)d_in[7];
    const float* b1   = (const float*)d_in[8];
    const float* w2   = (const float*)d_in[9];
    const float* b2   = (const float*)d_in[10];
    const float* fng  = (const float*)d_in[11];
    const float* fnb  = (const float*)d_in[12];

    float *px;
    __half *pqkv, *pln16, *pct16, *ph16;
    __half *qkvt, *outt, *w1t, *w2t;
    cudaGetSymbolAddress((void**)&px,    g_x);
    cudaGetSymbolAddress((void**)&pqkv,  g_qkv16);
    cudaGetSymbolAddress((void**)&pln16, g_ln16);
    cudaGetSymbolAddress((void**)&pct16, g_ct16);
    cudaGetSymbolAddress((void**)&ph16,  g_h16);
    cudaGetSymbolAddress((void**)&qkvt,  g_wqkvt);
    cudaGetSymbolAddress((void**)&outt,  g_woutt);
    cudaGetSymbolAddress((void**)&w1t,   g_w1t);
    cudaGetSymbolAddress((void**)&w2t,   g_w2t);

    cudaFuncSetAttribute(gemm_mma<0>, cudaFuncAttributeMaxDynamicSharedMemorySize, GEMM_SMEM);
    cudaFuncSetAttribute(gemm_mma<1>, cudaFuncAttributeMaxDynamicSharedMemorySize, GEMM_SMEM);
    cudaFuncSetAttribute(gemm_mma<2>, cudaFuncAttributeMaxDynamicSharedMemorySize, GEMM_SMEM);
    cudaFuncSetAttribute(gemm_mma<3>, cudaFuncAttributeMaxDynamicSharedMemorySize, GEMM_SMEM);
    cudaFuncSetAttribute(attn_mma, cudaFuncAttributeMaxDynamicSharedMemorySize, ATTN_SMEM);

    {
        dim3 tblk(32, 8);
        transpose_cvt<<<dim3(QKVD/32, DIM/32, DEPTH), tblk>>>(wqkv, qkvt, DIM, QKVD);
        transpose_cvt<<<dim3(DIM/32, INNER/32, DEPTH), tblk>>>(wout, outt, INNER, DIM);
        transpose_cvt<<<dim3(MLPD/32, DIM/32, DEPTH), tblk>>>(w1, w1t, DIM, MLPD);
        transpose_cvt<<<dim3(DIM/32, MLPD/32, DEPTH), tblk>>>(w2, w2t, MLPD, DIM);
    }

    cudaMemcpyAsync(px, x, sizeof(float) * (size_t)TOK * DIM,
                    cudaMemcpyDeviceToDevice, 0);

    const dim3 blk256(256);
    for (int i = 0; i < DEPTH; i++) {
        ln_kernel<true><<<TOK, blk256>>>(px, ln1g + i*DIM, ln1b + i*DIM,
                                         nullptr, pln16);
        gemm_mma<0><<<dim3(QKVD/128, TOK/128), blk256, GEMM_SMEM>>>(
            pln16, qkvt + (size_t)i*QKVD*DIM,
            nullptr, nullptr, pqkv, TOK, QKVD, DIM);
        attn_mma<<<dim3(SEQ/128, HEADS, BATCH), blk256, ATTN_SMEM>>>(pqkv, pct16);
        gemm_mma<3><<<dim3(DIM/128, TOK/128), blk256, GEMM_SMEM>>>(
            pct16, outt + (size_t)i*DIM*INNER,
            nullptr, px, nullptr, TOK, DIM, INNER);

        ln_kernel<true><<<TOK, blk256>>>(px, ln2g + i*DIM, ln2b + i*DIM,
                                         nullptr, pln16);
        gemm_mma<1><<<dim3(MLPD/128, TOK/128), blk256, GEMM_SMEM>>>(
            pln16, w1t + (size_t)i*MLPD*DIM,
            b1 + (size_t)i*MLPD, nullptr, ph16, TOK, MLPD, DIM);
        gemm_mma<2><<<dim3(DIM/128, TOK/128), blk256, GEMM_SMEM>>>(
            ph16, w2t + (size_t)i*DIM*MLPD,
            b2 + (size_t)i*DIM, px, nullptr, TOK, DIM, MLPD);
    }

    ln_kernel<false><<<TOK, blk256>>>(px, fng, fnb, (float*)d_out, nullptr);
}

// round 12
// speedup vs baseline: 2.6862x; 1.0669x over previous
#include <cuda_runtime.h>
#include <cuda_bf16.h>
#include <cuda_fp16.h>
#include <math.h>
#include <stdint.h>

#define DIM    768
#define DEPTH  6
#define HEADS  12
#define DHEAD  64
#define INNER  768
#define MLPD   3072
#define BATCH  4
#define SEQ    2048
#define TOK    (BATCH*SEQ)      /* 8192 */
#define QKVD   (3*INNER)        /* 2304 */
#define QSCALE 0.18033688011112042f   /* 0.125 * log2(e) */

// ---------------- scratch (device globals; no allocations) ----------------
__device__ float  g_x   [(size_t)TOK*DIM];    // residual stream fp32
__device__ __half g_qkv16[(size_t)TOK*QKVD];  // fused qkv fp16 (Q pre-scaled)
__device__ __half g_ln16[(size_t)TOK*DIM];    // LN output fp16
__device__ __half g_ct16[(size_t)TOK*DIM];    // attention ctx fp16
__device__ __half g_h16 [(size_t)TOK*MLPD];   // mlp hidden fp16
// transposed fp16 weights [layer][N][K]
__device__ __half g_wqkvt[(size_t)DEPTH*QKVD*DIM];
__device__ __half g_woutt[(size_t)DEPTH*DIM*INNER];
__device__ __half g_w1t  [(size_t)DEPTH*MLPD*DIM];
__device__ __half g_w2t  [(size_t)DEPTH*DIM*MLPD];

// ====================== PTX helpers =======================================
__device__ __forceinline__ uint32_t smem_u32(const void* p){
    uint32_t a;
    asm("{ .reg .u64 t; cvta.to.shared.u64 t, %1; cvt.u32.u64 %0, t; }"
        : "=r"(a) : "l"(p));
    return a;
}
__device__ __forceinline__ void cp16(uint32_t s, const void* g){
    asm volatile("cp.async.cg.shared.global [%0], [%1], 16;" :: "r"(s), "l"(g));
}
#define CP_COMMIT() asm volatile("cp.async.commit_group;" ::: "memory")
#define CP_WAIT1()  asm volatile("cp.async.wait_group 1;" ::: "memory")
#define CP_WAIT0()  asm volatile("cp.async.wait_group 0;" ::: "memory")

__device__ __forceinline__ void ldmx4(uint32_t addr, uint32_t& r0, uint32_t& r1,
                                      uint32_t& r2, uint32_t& r3){
    asm volatile("ldmatrix.sync.aligned.m8n8.x4.shared.b16 {%0,%1,%2,%3}, [%4];"
        : "=r"(r0), "=r"(r1), "=r"(r2), "=r"(r3) : "r"(addr));
}
__device__ __forceinline__ void ldmx4t(uint32_t addr, uint32_t& r0, uint32_t& r1,
                                       uint32_t& r2, uint32_t& r3){
    asm volatile("ldmatrix.sync.aligned.m8n8.x4.trans.shared.b16 {%0,%1,%2,%3}, [%4];"
        : "=r"(r0), "=r"(r1), "=r"(r2), "=r"(r3) : "r"(addr));
}
// fp16 mma
__device__ __forceinline__ void mma16816h(float* c, const uint32_t* a,
                                          uint32_t b0, uint32_t b1){
    asm volatile(
        "mma.sync.aligned.m16n8k16.row.col.f32.f16.f16.f32 "
        "{%0,%1,%2,%3}, {%4,%5,%6,%7}, {%8,%9}, {%0,%1,%2,%3};"
        : "+f"(c[0]), "+f"(c[1]), "+f"(c[2]), "+f"(c[3])
        : "r"(a[0]), "r"(a[1]), "r"(a[2]), "r"(a[3]), "r"(b0), "r"(b1));
}
// FMA-pipe exp2 (degree-6 Taylor on [-0.5,0.5]); valid for t <= 0
__device__ __forceinline__ float exp2_fast(float t){
    t = fmaxf(t, -120.f);
    float n = rintf(t);
    float f = t - n;
    float p = 1.5403530e-4f;
    p = fmaf(p, f, 1.3333558e-3f);
    p = fmaf(p, f, 9.6181291e-3f);
    p = fmaf(p, f, 5.5504109e-2f);
    p = fmaf(p, f, 2.4022651e-1f);
    p = fmaf(p, f, 6.9314718e-1f);
    p = fmaf(p, f, 1.0f);
    return __int_as_float(__float_as_int(p) + (((int)n) << 23));
}

// ====================== weight transpose to fp16 ===========================
__global__ void transpose_cvt(const float* __restrict__ W,
                              __half* __restrict__ Wh, int K, int N)
{
    __shared__ float tile[32][33];
    const size_t off = (size_t)blockIdx.z * K * N;
    const int n0 = blockIdx.x * 32, k0 = blockIdx.y * 32;
    const int tx = threadIdx.x, ty = threadIdx.y;
#pragma unroll
    for (int i = 0; i < 32; i += 8)
        tile[ty + i][tx] = W[off + (size_t)(k0 + ty + i) * N + n0 + tx];
    __syncthreads();
#pragma unroll
    for (int i = 0; i < 32; i += 8) {
        size_t oidx = off + (size_t)(n0 + ty + i) * K + k0 + tx;
        Wh[oidx] = __float2half_rn(tile[tx][ty + i]);
    }
}

// ====================== LayerNorm ==========================================
template<bool HOUT>
__global__ void ln_kernel(const float* __restrict__ x, const float* __restrict__ g,
                          const float* __restrict__ b, float* __restrict__ y,
                          __half* __restrict__ yh)
{
    int t = blockIdx.x;
    const float* xp = x + (size_t)t * DIM;

    float v[3];
    float s1 = 0.f, s2 = 0.f;
#pragma unroll
    for (int i = 0; i < 3; i++) {
        v[i] = xp[threadIdx.x + i * 256];
        s1 += v[i]; s2 += v[i] * v[i];
    }
#pragma unroll
    for (int o = 16; o > 0; o >>= 1) {
        s1 += __shfl_xor_sync(0xffffffffu, s1, o);
        s2 += __shfl_xor_sync(0xffffffffu, s2, o);
    }
    __shared__ float r1[8], r2[8];
    if ((threadIdx.x & 31) == 0) { r1[threadIdx.x >> 5] = s1; r2[threadIdx.x >> 5] = s2; }
    __syncthreads();
    s1 = 0.f; s2 = 0.f;
#pragma unroll
    for (int i = 0; i < 8; i++) { s1 += r1[i]; s2 += r2[i]; }

    float mu  = s1 * (1.f / DIM);
    float var = s2 * (1.f / DIM) - mu * mu;
    float rs  = rsqrtf(var + 1e-5f);
#pragma unroll
    for (int i = 0; i < 3; i++) {
        int d = threadIdx.x + i * 256;
        float yy = (v[i] - mu) * rs * g[d] + b[d];
        if (HOUT) yh[(size_t)t * DIM + d] = __float2half_rn(yy);
        else      y[(size_t)t * DIM + d] = yy;
    }
}

// ====================== fp16 1-product GEMM (BK=64, 2-stage, 2 CTAs/SM) ====
// C[M,N] = A[M,K] @ B[N,K]^T; fp16 in, fp32 accum.
// CTA 128x128, warp 32x64, BK=64, 2-stage cp.async, 64KB smem -> 2 CTAs/SM.
// Stage: [A 16K][B 16K] = 32KB, 128B swizzled rows.
// EPI: 0 = qkv out (scale Q cols, fp16); 1 = +bias, gelu, fp16 out;
//      2 = +bias += xres; 3 = += xres.
#define STAGE_SZ 32768u
template<int EPI>
__global__ void __launch_bounds__(256, 2)
gemm_mma(const __half* __restrict__ Ah, const __half* __restrict__ Bh,
         const float* __restrict__ bias, float* __restrict__ xres,
         __half* __restrict__ Ch, int M, int N, int K)
{
    extern __shared__ char smem[];
    const uint32_t sb0 = smem_u32(smem);
    const int tid  = threadIdx.x;
    const int lane = tid & 31, warp = tid >> 5;
    const int wm = warp >> 1, wn = warp & 1;
    const int bn = blockIdx.x, bm = blockIdx.y;
    const int nkt = K >> 6;

    // 128 rows x 128B per matrix; 8 chunks/row; 4 chunks per thread per matrix
    auto load_stage = [&](int kt, int st){
        const uint32_t base = sb0 + (uint32_t)st * STAGE_SZ;
        const size_t kof = (size_t)kt * 64;
#pragma unroll
        for (int i = 0; i < 4; i++) {
            const int idx = tid + i * 256;
            const int row = idx >> 3, c = idx & 7;
            const uint32_t so = (uint32_t)(row * 128 + ((c ^ (row & 7)) << 4));
            const size_t ga = (size_t)(bm * 128 + row) * K + kof + c * 8;
            const size_t gb = (size_t)(bn * 128 + row) * K + kof + c * 8;
            cp16(base + so,          Ah + ga);
            cp16(base + 16384u + so, Bh + gb);
        }
    };

    float acc[2][8][4];
#pragma unroll
    for (int mt = 0; mt < 2; mt++)
#pragma unroll
        for (int nt = 0; nt < 8; nt++)
#pragma unroll
            for (int q = 0; q < 4; q++) acc[mt][nt][q] = 0.f;

    load_stage(0, 0); CP_COMMIT();

    const int arow = wm * 32 + (lane & 15);
    const int acs  = lane >> 4;
    const int brow = wn * 64 + (lane & 7) + ((lane >> 4) << 3);
    const int bcs  = (lane >> 3) & 1;

    for (int kt = 0; kt < nkt; kt++) {
        if (kt + 1 < nkt) { load_stage(kt + 1, (kt + 1) & 1); CP_COMMIT(); CP_WAIT1(); }
        else              { CP_WAIT0(); }
        __syncthreads();

        const uint32_t base = sb0 + (uint32_t)(kt & 1) * STAGE_SZ;
#pragma unroll
        for (int ks = 0; ks < 4; ks++) {
            uint32_t ah[2][4];
#pragma unroll
            for (int mt = 0; mt < 2; mt++) {
                const int r = arow + mt * 16;
                const int c = ks * 2 + acs;
                const uint32_t off = (uint32_t)(r * 128 + ((c ^ (r & 7)) << 4));
                ldmx4(base + off, ah[mt][0], ah[mt][1], ah[mt][2], ah[mt][3]);
            }
#pragma unroll
            for (int bt = 0; bt < 4; bt++) {
                const int r = brow + bt * 16;
                const int c = ks * 2 + bcs;
                const uint32_t off = (uint32_t)(r * 128 + ((c ^ (r & 7)) << 4));
                uint32_t bh[4];
                ldmx4(base + 16384u + off, bh[0], bh[1], bh[2], bh[3]);
#pragma unroll
                for (int mt = 0; mt < 2; mt++) {
                    mma16816h(acc[mt][2*bt],   ah[mt], bh[0], bh[1]);
                    mma16816h(acc[mt][2*bt+1], ah[mt], bh[2], bh[3]);
                }
            }
        }
        __syncthreads();
    }

    const int rbase = bm * 128 + wm * 32 + (lane >> 2);
    const int cbase = bn * 128 + wn * 64 + (lane & 3) * 2;
#pragma unroll
    for (int mt = 0; mt < 2; mt++) {
#pragma unroll
        for (int nt = 0; nt < 8; nt++) {
            const int gcol = cbase + nt * 8;
#pragma unroll
            for (int h = 0; h < 2; h++) {
                const int grow = rbase + mt * 16 + h * 8;
                float v0 = acc[mt][nt][2*h], v1 = acc[mt][nt][2*h+1];
                const size_t oidx = (size_t)grow * N + gcol;
                if (EPI == 0 || EPI == 1) {
                    if (EPI == 0) {
                        const float sc = (gcol < INNER) ? QSCALE : 1.f;
                        v0 *= sc; v1 *= sc;
                    } else {
                        v0 += bias[gcol];     v1 += bias[gcol + 1];
                        v0 = 0.5f * v0 * (1.f + erff(v0 * 0.70710678118654752f));
                        v1 = 0.5f * v1 * (1.f + erff(v1 * 0.70710678118654752f));
                    }
                    __half h0 = __float2half_rn(v0), h1 = __float2half_rn(v1);
                    *reinterpret_cast<uint32_t*>(Ch + oidx) =
                        (uint32_t)__half_as_ushort(h0) |
                        ((uint32_t)__half_as_ushort(h1) << 16);
                } else {
                    float2 xv = *reinterpret_cast<const float2*>(xres + oidx);
                    if (EPI == 2) { v0 += bias[gcol]; v1 += bias[gcol + 1]; }
                    xv.x += v0; xv.y += v1;
                    *reinterpret_cast<float2*>(xres + oidx) = xv;
                }
            }
        }
    }
}

// ====================== fp16 1-product flash attention (2 CTAs/SM) =========
// grid (SEQ/128, HEADS, BATCH), 256 threads (8 warps x 16 query rows).
#define ATTN_SMEM (16384 + 2*16384)
__global__ void __launch_bounds__(256, 2)
attn_mma(const __half* __restrict__ qkv, __half* __restrict__ ctx)
{
    extern __shared__ char smem[];
    const uint32_t sb = smem_u32(smem);
    const uint32_t QS = sb;
    const int tid = threadIdx.x, lane = tid & 31, wid = tid >> 5;
    const int b = blockIdx.z, h = blockIdx.y, qt = blockIdx.x;
    const int tok0 = b * SEQ + qt * 128;

#pragma unroll
    for (int i = 0; i < 4; i++) {
        const int idx = tid + i * 256;
        const int row = idx >> 3, c = idx & 7;
        const uint32_t so = (uint32_t)(row * 128 + ((c ^ (row & 7)) << 4));
        cp16(QS + so, qkv + (size_t)(tok0 + row) * QKVD + h * DHEAD + c * 8);
    }

    auto load_kv = [&](int t, int st){
        const uint32_t base = sb + 16384u + (uint32_t)st * 16384u;
        const int kv0 = b * SEQ + t * 64;
#pragma unroll
        for (int i = 0; i < 2; i++) {
            const int idx = tid + i * 256;
            const int row = idx >> 3, c = idx & 7;
            const uint32_t so = (uint32_t)(row * 128 + ((c ^ (row & 7)) << 4));
            const size_t gk = (size_t)(kv0 + row) * QKVD + INNER + h * DHEAD + c * 8;
            const size_t gv = (size_t)(kv0 + row) * QKVD + 2 * INNER + h * DHEAD + c * 8;
            cp16(base + so,         qkv + gk);
            cp16(base + 8192u + so, qkv + gv);
        }
    };
    load_kv(0, 0); CP_COMMIT();

    float O[8][4];
#pragma unroll
    for (int nt = 0; nt < 8; nt++)
#pragma unroll
        for (int q = 0; q < 4; q++) O[nt][q] = 0.f;
    float m0 = -1e30f, m1 = -1e30f, l0 = 0.f, l1 = 0.f;
    const int m0row = wid * 16;

    const int NT = SEQ / 64;
    for (int t = 0; t < NT; t++) {
        if (t + 1 < NT) { load_kv(t + 1, (t + 1) & 1); CP_COMMIT(); CP_WAIT1(); }
        else            { CP_WAIT0(); }
        __syncthreads();
        const uint32_t kb = sb + 16384u + (uint32_t)(t & 1) * 16384u;

        float S[8][4];
#pragma unroll
        for (int nt = 0; nt < 8; nt++)
#pragma unroll
            for (int q = 0; q < 4; q++) S[nt][q] = 0.f;
#pragma unroll
        for (int ks = 0; ks < 4; ks++) {
            uint32_t qf[4];
            {
                const int r = m0row + (lane & 15);
                const int c = ks * 2 + (lane >> 4);
                const uint32_t off = (uint32_t)(r * 128 + ((c ^ (r & 7)) << 4));
                ldmx4(QS + off, qf[0], qf[1], qf[2], qf[3]);
            }
#pragma unroll
            for (int bt = 0; bt < 4; bt++) {
                const int r = bt * 16 + (lane & 7) + ((lane >> 4) << 3);
                const int c = ks * 2 + ((lane >> 3) & 1);
                const uint32_t off = (uint32_t)(r * 128 + ((c ^ (r & 7)) << 4));
                uint32_t kh[4];
                ldmx4(kb + off, kh[0], kh[1], kh[2], kh[3]);
                mma16816h(S[2*bt],   qf, kh[0], kh[1]);
                mma16816h(S[2*bt+1], qf, kh[2], kh[3]);
            }
        }

        float mt0 = -1e30f, mt1 = -1e30f;
#pragma unroll
        for (int nt = 0; nt < 8; nt++) {
            mt0 = fmaxf(mt0, fmaxf(S[nt][0], S[nt][1]));
            mt1 = fmaxf(mt1, fmaxf(S[nt][2], S[nt][3]));
        }
        mt0 = fmaxf(mt0, __shfl_xor_sync(0xffffffffu, mt0, 1));
        mt0 = fmaxf(mt0, __shfl_xor_sync(0xffffffffu, mt0, 2));
        mt1 = fmaxf(mt1, __shfl_xor_sync(0xffffffffu, mt1, 1));
        mt1 = fmaxf(mt1, __shfl_xor_sync(0xffffffffu, mt1, 2));
        const float mn0 = fmaxf(m0, mt0), mn1 = fmaxf(m1, mt1);
        const float cr0 = exp2_fast(m0 - mn0), cr1 = exp2_fast(m1 - mn1);
        m0 = mn0; m1 = mn1;

        uint32_t phi[4][4];
        float s0 = 0.f, s1 = 0.f;
#pragma unroll
        for (int nt = 0; nt < 8; nt++) {
            float p0 = exp2_fast(S[nt][0] - m0);
            float p1 = exp2_fast(S[nt][1] - m0);
            float p2 = exp2_fast(S[nt][2] - m1);
            float p3 = exp2_fast(S[nt][3] - m1);
            s0 += p0 + p1; s1 += p2 + p3;
            __half h0 = __float2half_rn(p0), h1 = __float2half_rn(p1);
            __half h2 = __float2half_rn(p2), h3 = __float2half_rn(p3);
            const int t2 = nt >> 1, o = (nt & 1) * 2;
            phi[t2][o] = (uint32_t)__half_as_ushort(h0) |
                         ((uint32_t)__half_as_ushort(h1) << 16);
            phi[t2][o+1] = (uint32_t)__half_as_ushort(h2) |
                           ((uint32_t)__half_as_ushort(h3) << 16);
        }
        s0 += __shfl_xor_sync(0xffffffffu, s0, 1);
        s0 += __shfl_xor_sync(0xffffffffu, s0, 2);
        s1 += __shfl_xor_sync(0xffffffffu, s1, 1);
        s1 += __shfl_xor_sync(0xffffffffu, s1, 2);
        l0 = l0 * cr0 + s0;
        l1 = l1 * cr1 + s1;
#pragma unroll
        for (int nt = 0; nt < 8; nt++) {
            O[nt][0] *= cr0; O[nt][1] *= cr0;
            O[nt][2] *= cr1; O[nt][3] *= cr1;
        }

#pragma unroll
        for (int t2 = 0; t2 < 4; t2++) {
#pragma unroll
            for (int dn = 0; dn < 4; dn++) {
                const int r = t2 * 16 + (lane & 15);
                const int c = dn * 2 + (lane >> 4);
                const uint32_t off = (uint32_t)(r * 128 + ((c ^ (r & 7)) << 4));
                uint32_t vh[4];
                ldmx4t(kb + 8192u + off, vh[0], vh[1], vh[2], vh[3]);
                mma16816h(O[2*dn],   phi[t2], vh[0], vh[1]);
                mma16816h(O[2*dn+1], phi[t2], vh[2], vh[3]);
            }
        }
        __syncthreads();
    }

    const float i0 = 1.f / l0, i1 = 1.f / l1;
    const int r0 = tok0 + m0row + (lane >> 2);
#pragma unroll
    for (int nt = 0; nt < 8; nt++) {
        const int col = h * DHEAD + nt * 8 + (lane & 3) * 2;
#pragma unroll
        for (int hh = 0; hh < 2; hh++) {
            const float inv = hh ? i1 : i0;
            float v0 = O[nt][2*hh] * inv, v1 = O[nt][2*hh+1] * inv;
            __half h0 = __float2half_rn(v0), h1 = __float2half_rn(v1);
            const size_t oidx = (size_t)(r0 + hh * 8) * DIM + col;
            *reinterpret_cast<uint32_t*>(ctx + oidx) =
                (uint32_t)__half_as_ushort(h0) |
                ((uint32_t)__half_as_ushort(h1) << 16);
        }
    }
}

// ====================== driver =============================================
#define GEMM_SMEM (2 * 32768)

extern "C" void kernel_launch(void* const* d_in, const int* in_sizes, int n_in,
                              void* d_out, int out_size)
{
    const float* x    = (const float*)d_in[0];
    const float* ln1g = (const float*)d_in[1];
    const float* ln1b = (const float*)d_in[2];
    const float* wqkv = (const float*)d_in[3];
    const float* wout = (const float*)d_in[4];
    const float* ln2g = (const float*)d_in[5];
    const float* ln2b = (const float*)d_in[6];
    const float* w1   = (const float*)d_in[7];
    const float* b1   = (const float*)d_in[8];
    const float* w2   = (const float*)d_in[9];
    const float* b2   = (const float*)d_in[10];
    const float* fng  = (const float*)d_in[11];
    const float* fnb  = (const float*)d_in[12];

    float *px;
    __half *pqkv, *pln16, *pct16, *ph16;
    __half *qkvt, *outt, *w1t, *w2t;
    cudaGetSymbolAddress((void**)&px,    g_x);
    cudaGetSymbolAddress((void**)&pqkv,  g_qkv16);
    cudaGetSymbolAddress((void**)&pln16, g_ln16);
    cudaGetSymbolAddress((void**)&pct16, g_ct16);
    cudaGetSymbolAddress((void**)&ph16,  g_h16);
    cudaGetSymbolAddress((void**)&qkvt,  g_wqkvt);
    cudaGetSymbolAddress((void**)&outt,  g_woutt);
    cudaGetSymbolAddress((void**)&w1t,   g_w1t);
    cudaGetSymbolAddress((void**)&w2t,   g_w2t);

    cudaFuncSetAttribute(gemm_mma<0>, cudaFuncAttributeMaxDynamicSharedMemorySize, GEMM_SMEM);
    cudaFuncSetAttribute(gemm_mma<1>, cudaFuncAttributeMaxDynamicSharedMemorySize, GEMM_SMEM);
    cudaFuncSetAttribute(gemm_mma<2>, cudaFuncAttributeMaxDynamicSharedMemorySize, GEMM_SMEM);
    cudaFuncSetAttribute(gemm_mma<3>, cudaFuncAttributeMaxDynamicSharedMemorySize, GEMM_SMEM);
    cudaFuncSetAttribute(attn_mma, cudaFuncAttributeMaxDynamicSharedMemorySize, ATTN_SMEM);

    {
        dim3 tblk(32, 8);
        transpose_cvt<<<dim3(QKVD/32, DIM/32, DEPTH), tblk>>>(wqkv, qkvt, DIM, QKVD);
        transpose_cvt<<<dim3(DIM/32, INNER/32, DEPTH), tblk>>>(wout, outt, INNER, DIM);
        transpose_cvt<<<dim3(MLPD/32, DIM/32, DEPTH), tblk>>>(w1, w1t, DIM, MLPD);
        transpose_cvt<<<dim3(DIM/32, MLPD/32, DEPTH), tblk>>>(w2, w2t, MLPD, DIM);
    }

    cudaMemcpyAsync(px, x, sizeof(float) * (size_t)TOK * DIM,
                    cudaMemcpyDeviceToDevice, 0);

    const dim3 blk256(256);
    for (int i = 0; i < DEPTH; i++) {
        ln_kernel<true><<<TOK, blk256>>>(px, ln1g + i*DIM, ln1b + i*DIM,
                                         nullptr, pln16);
        gemm_mma<0><<<dim3(QKVD/128, TOK/128), blk256, GEMM_SMEM>>>(
            pln16, qkvt + (size_t)i*QKVD*DIM,
            nullptr, nullptr, pqkv, TOK, QKVD, DIM);
        attn_mma<<<dim3(SEQ/128, HEADS, BATCH), blk256, ATTN_SMEM>>>(pqkv, pct16);
        gemm_mma<3><<<dim3(DIM/128, TOK/128), blk256, GEMM_SMEM>>>(
            pct16, outt + (size_t)i*DIM*INNER,
            nullptr, px, nullptr, TOK, DIM, INNER);

        ln_kernel<true><<<TOK, blk256>>>(px, ln2g + i*DIM, ln2b + i*DIM,
                                         nullptr, pln16);
        gemm_mma<1><<<dim3(MLPD/128, TOK/128), blk256, GEMM_SMEM>>>(
            pln16, w1t + (size_t)i*MLPD*DIM,
            b1 + (size_t)i*MLPD, nullptr, ph16, TOK, MLPD, DIM);
        gemm_mma<2><<<dim3(DIM/128, TOK/128), blk256, GEMM_SMEM>>>(
            ph16, w2t + (size_t)i*DIM*MLPD,
            b2 + (size_t)i*DIM, px, nullptr, TOK, DIM, MLPD);
    }

    ln_kernel<false><<<TOK, blk256>>>(px, fng, fnb, (float*)d_out, nullptr);
}

// round 13
// speedup vs baseline: 2.6932x; 1.0026x over previous
#include <cuda_runtime.h>
#include <cuda_bf16.h>
#include <cuda_fp16.h>
#include <math.h>
#include <stdint.h>

#define DIM    768
#define DEPTH  6
#define HEADS  12
#define DHEAD  64
#define INNER  768
#define MLPD   3072
#define BATCH  4
#define SEQ    2048
#define TOK    (BATCH*SEQ)      /* 8192 */
#define QKVD   (3*INNER)        /* 2304 */
#define QSCALE 0.18033688011112042f   /* 0.125 * log2(e) */

// ---------------- scratch (device globals; no allocations) ----------------
__device__ float  g_x   [(size_t)TOK*DIM];    // residual stream fp32
__device__ __half g_qkv16[(size_t)TOK*QKVD];  // fused qkv fp16 (Q pre-scaled)
__device__ __half g_ln16[(size_t)TOK*DIM];    // LN output fp16
__device__ __half g_ct16[(size_t)TOK*DIM];    // attention ctx fp16
__device__ __half g_h16 [(size_t)TOK*MLPD];   // mlp hidden fp16
// transposed fp16 weights [layer][N][K]
__device__ __half g_wqkvt[(size_t)DEPTH*QKVD*DIM];
__device__ __half g_woutt[(size_t)DEPTH*DIM*INNER];
__device__ __half g_w1t  [(size_t)DEPTH*MLPD*DIM];
__device__ __half g_w2t  [(size_t)DEPTH*DIM*MLPD];

// ====================== PTX helpers =======================================
__device__ __forceinline__ uint32_t smem_u32(const void* p){
    uint32_t a;
    asm("{ .reg .u64 t; cvta.to.shared.u64 t, %1; cvt.u32.u64 %0, t; }"
        : "=r"(a) : "l"(p));
    return a;
}
__device__ __forceinline__ void cp16(uint32_t s, const void* g){
    asm volatile("cp.async.cg.shared.global [%0], [%1], 16;" :: "r"(s), "l"(g));
}
#define CP_COMMIT() asm volatile("cp.async.commit_group;" ::: "memory")
#define CP_WAIT1()  asm volatile("cp.async.wait_group 1;" ::: "memory")
#define CP_WAIT0()  asm volatile("cp.async.wait_group 0;" ::: "memory")

__device__ __forceinline__ void ldmx4(uint32_t addr, uint32_t& r0, uint32_t& r1,
                                      uint32_t& r2, uint32_t& r3){
    asm volatile("ldmatrix.sync.aligned.m8n8.x4.shared.b16 {%0,%1,%2,%3}, [%4];"
        : "=r"(r0), "=r"(r1), "=r"(r2), "=r"(r3) : "r"(addr));
}
__device__ __forceinline__ void ldmx4t(uint32_t addr, uint32_t& r0, uint32_t& r1,
                                       uint32_t& r2, uint32_t& r3){
    asm volatile("ldmatrix.sync.aligned.m8n8.x4.trans.shared.b16 {%0,%1,%2,%3}, [%4];"
        : "=r"(r0), "=r"(r1), "=r"(r2), "=r"(r3) : "r"(addr));
}
// fp16 mma
__device__ __forceinline__ void mma16816h(float* c, const uint32_t* a,
                                          uint32_t b0, uint32_t b1){
    asm volatile(
        "mma.sync.aligned.m16n8k16.row.col.f32.f16.f16.f32 "
        "{%0,%1,%2,%3}, {%4,%5,%6,%7}, {%8,%9}, {%0,%1,%2,%3};"
        : "+f"(c[0]), "+f"(c[1]), "+f"(c[2]), "+f"(c[3])
        : "r"(a[0]), "r"(a[1]), "r"(a[2]), "r"(a[3]), "r"(b0), "r"(b1));
}
// FMA-pipe exp2 (degree-6 Taylor on [-0.5,0.5]); valid for t <= 0
__device__ __forceinline__ float exp2_fast(float t){
    t = fmaxf(t, -120.f);
    float n = rintf(t);
    float f = t - n;
    float p = 1.5403530e-4f;
    p = fmaf(p, f, 1.3333558e-3f);
    p = fmaf(p, f, 9.6181291e-3f);
    p = fmaf(p, f, 5.5504109e-2f);
    p = fmaf(p, f, 2.4022651e-1f);
    p = fmaf(p, f, 6.9314718e-1f);
    p = fmaf(p, f, 1.0f);
    return __int_as_float(__float_as_int(p) + (((int)n) << 23));
}

// ====================== weight transpose to fp16 ===========================
__global__ void transpose_cvt(const float* __restrict__ W,
                              __half* __restrict__ Wh, int K, int N)
{
    __shared__ float tile[32][33];
    const size_t off = (size_t)blockIdx.z * K * N;
    const int n0 = blockIdx.x * 32, k0 = blockIdx.y * 32;
    const int tx = threadIdx.x, ty = threadIdx.y;
#pragma unroll
    for (int i = 0; i < 32; i += 8)
        tile[ty + i][tx] = W[off + (size_t)(k0 + ty + i) * N + n0 + tx];
    __syncthreads();
#pragma unroll
    for (int i = 0; i < 32; i += 8) {
        size_t oidx = off + (size_t)(n0 + ty + i) * K + k0 + tx;
        Wh[oidx] = __float2half_rn(tile[tx][ty + i]);
    }
}

// ====================== LayerNorm: 1 warp / token, 8 tokens / block ========
template<bool HOUT>
__global__ void ln_kernel(const float* __restrict__ x, const float* __restrict__ g,
                          const float* __restrict__ b, float* __restrict__ y,
                          __half* __restrict__ yh)
{
    const int warp = threadIdx.x >> 5, lane = threadIdx.x & 31;
    const int t = blockIdx.x * 8 + warp;
    const float* xp = x + (size_t)t * DIM;

    float v[24];
    float s1 = 0.f, s2 = 0.f;
#pragma unroll
    for (int i = 0; i < 6; i++) {
        float4 f = *reinterpret_cast<const float4*>(xp + i * 128 + lane * 4);
        v[i*4+0] = f.x; v[i*4+1] = f.y; v[i*4+2] = f.z; v[i*4+3] = f.w;
        s1 += f.x + f.y + f.z + f.w;
        s2 += f.x*f.x + f.y*f.y + f.z*f.z + f.w*f.w;
    }
#pragma unroll
    for (int o = 16; o > 0; o >>= 1) {
        s1 += __shfl_xor_sync(0xffffffffu, s1, o);
        s2 += __shfl_xor_sync(0xffffffffu, s2, o);
    }
    const float mu  = s1 * (1.f / DIM);
    const float var = s2 * (1.f / DIM) - mu * mu;
    const float rs  = rsqrtf(var + 1e-5f);

#pragma unroll
    for (int i = 0; i < 6; i++) {
        const int d = i * 128 + lane * 4;
        float4 gg = *reinterpret_cast<const float4*>(g + d);
        float4 bb = *reinterpret_cast<const float4*>(b + d);
        float y0 = (v[i*4+0] - mu) * rs * gg.x + bb.x;
        float y1 = (v[i*4+1] - mu) * rs * gg.y + bb.y;
        float y2 = (v[i*4+2] - mu) * rs * gg.z + bb.z;
        float y3 = (v[i*4+3] - mu) * rs * gg.w + bb.w;
        if (HOUT) {
            uint2 pk;
            __half h0 = __float2half_rn(y0), h1 = __float2half_rn(y1);
            __half h2 = __float2half_rn(y2), h3 = __float2half_rn(y3);
            pk.x = (uint32_t)__half_as_ushort(h0) | ((uint32_t)__half_as_ushort(h1) << 16);
            pk.y = (uint32_t)__half_as_ushort(h2) | ((uint32_t)__half_as_ushort(h3) << 16);
            *reinterpret_cast<uint2*>(yh + (size_t)t * DIM + d) = pk;
        } else {
            *reinterpret_cast<float4*>(y + (size_t)t * DIM + d) =
                make_float4(y0, y1, y2, y3);
        }
    }
}

// ====================== fp16 1-product GEMM (BK=64, 3-stage, 2 CTAs/SM) ====
// C[M,N] = A[M,K] @ B[N,K]^T; fp16 in, fp32 accum.
// CTA 128x128, warp 32x64, BK=64, 3-stage cp.async, 96KB smem -> 2 CTAs/SM.
// Stage: [A 16K][B 16K] = 32KB, 128B swizzled rows.
// EPI: 0 = qkv out (scale Q cols, fp16); 1 = +bias, gelu, fp16 out;
//      2 = +bias += xres; 3 = += xres.
#define STAGE_SZ 32768u
template<int EPI>
__global__ void __launch_bounds__(256, 2)
gemm_mma(const __half* __restrict__ Ah, const __half* __restrict__ Bh,
         const float* __restrict__ bias, float* __restrict__ xres,
         __half* __restrict__ Ch, int M, int N, int K)
{
    extern __shared__ char smem[];
    const uint32_t sb0 = smem_u32(smem);
    const int tid  = threadIdx.x;
    const int lane = tid & 31, warp = tid >> 5;
    const int wm = warp >> 1, wn = warp & 1;
    const int bn = blockIdx.x, bm = blockIdx.y;
    const int nkt = K >> 6;

    auto load_stage = [&](int kt, int st){
        const uint32_t base = sb0 + (uint32_t)st * STAGE_SZ;
        const size_t kof = (size_t)kt * 64;
#pragma unroll
        for (int i = 0; i < 4; i++) {
            const int idx = tid + i * 256;
            const int row = idx >> 3, c = idx & 7;
            const uint32_t so = (uint32_t)(row * 128 + ((c ^ (row & 7)) << 4));
            const size_t ga = (size_t)(bm * 128 + row) * K + kof + c * 8;
            const size_t gb = (size_t)(bn * 128 + row) * K + kof + c * 8;
            cp16(base + so,          Ah + ga);
            cp16(base + 16384u + so, Bh + gb);
        }
    };

    float acc[2][8][4];
#pragma unroll
    for (int mt = 0; mt < 2; mt++)
#pragma unroll
        for (int nt = 0; nt < 8; nt++)
#pragma unroll
            for (int q = 0; q < 4; q++) acc[mt][nt][q] = 0.f;

    load_stage(0, 0); CP_COMMIT();
    load_stage(1, 1); CP_COMMIT();

    const int arow = wm * 32 + (lane & 15);
    const int acs  = lane >> 4;
    const int brow = wn * 64 + (lane & 7) + ((lane >> 4) << 3);
    const int bcs  = (lane >> 3) & 1;

    for (int kt = 0; kt < nkt; kt++) {
        if (kt == nkt - 1) { CP_WAIT0(); } else { CP_WAIT1(); }
        __syncthreads();
        if (kt + 2 < nkt) { load_stage(kt + 2, (kt + 2) % 3); CP_COMMIT(); }

        const uint32_t base = sb0 + (uint32_t)(kt % 3) * STAGE_SZ;
#pragma unroll
        for (int ks = 0; ks < 4; ks++) {
            uint32_t ah[2][4];
#pragma unroll
            for (int mt = 0; mt < 2; mt++) {
                const int r = arow + mt * 16;
                const int c = ks * 2 + acs;
                const uint32_t off = (uint32_t)(r * 128 + ((c ^ (r & 7)) << 4));
                ldmx4(base + off, ah[mt][0], ah[mt][1], ah[mt][2], ah[mt][3]);
            }
#pragma unroll
            for (int bt = 0; bt < 4; bt++) {
                const int r = brow + bt * 16;
                const int c = ks * 2 + bcs;
                const uint32_t off = (uint32_t)(r * 128 + ((c ^ (r & 7)) << 4));
                uint32_t bh[4];
                ldmx4(base + 16384u + off, bh[0], bh[1], bh[2], bh[3]);
#pragma unroll
                for (int mt = 0; mt < 2; mt++) {
                    mma16816h(acc[mt][2*bt],   ah[mt], bh[0], bh[1]);
                    mma16816h(acc[mt][2*bt+1], ah[mt], bh[2], bh[3]);
                }
            }
        }
        __syncthreads();
    }

    const int rbase = bm * 128 + wm * 32 + (lane >> 2);
    const int cbase = bn * 128 + wn * 64 + (lane & 3) * 2;
#pragma unroll
    for (int mt = 0; mt < 2; mt++) {
#pragma unroll
        for (int nt = 0; nt < 8; nt++) {
            const int gcol = cbase + nt * 8;
#pragma unroll
            for (int h = 0; h < 2; h++) {
                const int grow = rbase + mt * 16 + h * 8;
                float v0 = acc[mt][nt][2*h], v1 = acc[mt][nt][2*h+1];
                const size_t oidx = (size_t)grow * N + gcol;
                if (EPI == 0 || EPI == 1) {
                    if (EPI == 0) {
                        const float sc = (gcol < INNER) ? QSCALE : 1.f;
                        v0 *= sc; v1 *= sc;
                    } else {
                        v0 += bias[gcol];     v1 += bias[gcol + 1];
                        v0 = 0.5f * v0 * (1.f + erff(v0 * 0.70710678118654752f));
                        v1 = 0.5f * v1 * (1.f + erff(v1 * 0.70710678118654752f));
                    }
                    __half h0 = __float2half_rn(v0), h1 = __float2half_rn(v1);
                    *reinterpret_cast<uint32_t*>(Ch + oidx) =
                        (uint32_t)__half_as_ushort(h0) |
                        ((uint32_t)__half_as_ushort(h1) << 16);
                } else {
                    float2 xv = *reinterpret_cast<const float2*>(xres + oidx);
                    if (EPI == 2) { v0 += bias[gcol]; v1 += bias[gcol + 1]; }
                    xv.x += v0; xv.y += v1;
                    *reinterpret_cast<float2*>(xres + oidx) = xv;
                }
            }
        }
    }
}

// ====================== fp16 1-product flash attention (2 CTAs/SM) =========
// grid (SEQ/128, HEADS, BATCH), 256 threads (8 warps x 16 query rows).
#define ATTN_SMEM (16384 + 2*16384)
__global__ void __launch_bounds__(256, 2)
attn_mma(const __half* __restrict__ qkv, __half* __restrict__ ctx)
{
    extern __shared__ char smem[];
    const uint32_t sb = smem_u32(smem);
    const uint32_t QS = sb;
    const int tid = threadIdx.x, lane = tid & 31, wid = tid >> 5;
    const int b = blockIdx.z, h = blockIdx.y, qt = blockIdx.x;
    const int tok0 = b * SEQ + qt * 128;

#pragma unroll
    for (int i = 0; i < 4; i++) {
        const int idx = tid + i * 256;
        const int row = idx >> 3, c = idx & 7;
        const uint32_t so = (uint32_t)(row * 128 + ((c ^ (row & 7)) << 4));
        cp16(QS + so, qkv + (size_t)(tok0 + row) * QKVD + h * DHEAD + c * 8);
    }

    auto load_kv = [&](int t, int st){
        const uint32_t base = sb + 16384u + (uint32_t)st * 16384u;
        const int kv0 = b * SEQ + t * 64;
#pragma unroll
        for (int i = 0; i < 2; i++) {
            const int idx = tid + i * 256;
            const int row = idx >> 3, c = idx & 7;
            const uint32_t so = (uint32_t)(row * 128 + ((c ^ (row & 7)) << 4));
            const size_t gk = (size_t)(kv0 + row) * QKVD + INNER + h * DHEAD + c * 8;
            const size_t gv = (size_t)(kv0 + row) * QKVD + 2 * INNER + h * DHEAD + c * 8;
            cp16(base + so,         qkv + gk);
            cp16(base + 8192u + so, qkv + gv);
        }
    };
    load_kv(0, 0); CP_COMMIT();

    float O[8][4];
#pragma unroll
    for (int nt = 0; nt < 8; nt++)
#pragma unroll
        for (int q = 0; q < 4; q++) O[nt][q] = 0.f;
    float m0 = -1e30f, m1 = -1e30f, l0 = 0.f, l1 = 0.f;
    const int m0row = wid * 16;

    const int NT = SEQ / 64;
    for (int t = 0; t < NT; t++) {
        if (t + 1 < NT) { load_kv(t + 1, (t + 1) & 1); CP_COMMIT(); CP_WAIT1(); }
        else            { CP_WAIT0(); }
        __syncthreads();
        const uint32_t kb = sb + 16384u + (uint32_t)(t & 1) * 16384u;

        float S[8][4];
#pragma unroll
        for (int nt = 0; nt < 8; nt++)
#pragma unroll
            for (int q = 0; q < 4; q++) S[nt][q] = 0.f;
#pragma unroll
        for (int ks = 0; ks < 4; ks++) {
            uint32_t qf[4];
            {
                const int r = m0row + (lane & 15);
                const int c = ks * 2 + (lane >> 4);
                const uint32_t off = (uint32_t)(r * 128 + ((c ^ (r & 7)) << 4));
                ldmx4(QS + off, qf[0], qf[1], qf[2], qf[3]);
            }
#pragma unroll
            for (int bt = 0; bt < 4; bt++) {
                const int r = bt * 16 + (lane & 7) + ((lane >> 4) << 3);
                const int c = ks * 2 + ((lane >> 3) & 1);
                const uint32_t off = (uint32_t)(r * 128 + ((c ^ (r & 7)) << 4));
                uint32_t kh[4];
                ldmx4(kb + off, kh[0], kh[1], kh[2], kh[3]);
                mma16816h(S[2*bt],   qf, kh[0], kh[1]);
                mma16816h(S[2*bt+1], qf, kh[2], kh[3]);
            }
        }

        float mt0 = -1e30f, mt1 = -1e30f;
#pragma unroll
        for (int nt = 0; nt < 8; nt++) {
            mt0 = fmaxf(mt0, fmaxf(S[nt][0], S[nt][1]));
            mt1 = fmaxf(mt1, fmaxf(S[nt][2], S[nt][3]));
        }
        mt0 = fmaxf(mt0, __shfl_xor_sync(0xffffffffu, mt0, 1));
        mt0 = fmaxf(mt0, __shfl_xor_sync(0xffffffffu, mt0, 2));
        mt1 = fmaxf(mt1, __shfl_xor_sync(0xffffffffu, mt1, 1));
        mt1 = fmaxf(mt1, __shfl_xor_sync(0xffffffffu, mt1, 2));
        const float mn0 = fmaxf(m0, mt0), mn1 = fmaxf(m1, mt1);
        const float cr0 = exp2_fast(m0 - mn0), cr1 = exp2_fast(m1 - mn1);
        m0 = mn0; m1 = mn1;

        uint32_t phi[4][4];
        float s0 = 0.f, s1 = 0.f;
#pragma unroll
        for (int nt = 0; nt < 8; nt++) {
            float p0 = exp2_fast(S[nt][0] - m0);
            float p1 = exp2_fast(S[nt][1] - m0);
            float p2 = exp2_fast(S[nt][2] - m1);
            float p3 = exp2_fast(S[nt][3] - m1);
            s0 += p0 + p1; s1 += p2 + p3;
            __half h0 = __float2half_rn(p0), h1 = __float2half_rn(p1);
            __half h2 = __float2half_rn(p2), h3 = __float2half_rn(p3);
            const int t2 = nt >> 1, o = (nt & 1) * 2;
            phi[t2][o] = (uint32_t)__half_as_ushort(h0) |
                         ((uint32_t)__half_as_ushort(h1) << 16);
            phi[t2][o+1] = (uint32_t)__half_as_ushort(h2) |
                           ((uint32_t)__half_as_ushort(h3) << 16);
        }
        s0 += __shfl_xor_sync(0xffffffffu, s0, 1);
        s0 += __shfl_xor_sync(0xffffffffu, s0, 2);
        s1 += __shfl_xor_sync(0xffffffffu, s1, 1);
        s1 += __shfl_xor_sync(0xffffffffu, s1, 2);
        l0 = l0 * cr0 + s0;
        l1 = l1 * cr1 + s1;
#pragma unroll
        for (int nt = 0; nt < 8; nt++) {
            O[nt][0] *= cr0; O[nt][1] *= cr0;
            O[nt][2] *= cr1; O[nt][3] *= cr1;
        }

#pragma unroll
        for (int t2 = 0; t2 < 4; t2++) {
#pragma unroll
            for (int dn = 0; dn < 4; dn++) {
                const int r = t2 * 16 + (lane & 15);
                const int c = dn * 2 + (lane >> 4);
                const uint32_t off = (uint32_t)(r * 128 + ((c ^ (r & 7)) << 4));
                uint32_t vh[4];
                ldmx4t(kb + 8192u + off, vh[0], vh[1], vh[2], vh[3]);
                mma16816h(O[2*dn],   phi[t2], vh[0], vh[1]);
                mma16816h(O[2*dn+1], phi[t2], vh[2], vh[3]);
            }
        }
        __syncthreads();
    }

    const float i0 = 1.f / l0, i1 = 1.f / l1;
    const int r0 = tok0 + m0row + (lane >> 2);
#pragma unroll
    for (int nt = 0; nt < 8; nt++) {
        const int col = h * DHEAD + nt * 8 + (lane & 3) * 2;
#pragma unroll
        for (int hh = 0; hh < 2; hh++) {
            const float inv = hh ? i1 : i0;
            float v0 = O[nt][2*hh] * inv, v1 = O[nt][2*hh+1] * inv;
            __half h0 = __float2half_rn(v0), h1 = __float2half_rn(v1);
            const size_t oidx = (size_t)(r0 + hh * 8) * DIM + col;
            *reinterpret_cast<uint32_t*>(ctx + oidx) =
                (uint32_t)__half_as_ushort(h0) |
                ((uint32_t)__half_as_ushort(h1) << 16);
        }
    }
}

// ====================== driver =============================================
#define GEMM_SMEM (3 * 32768)

extern "C" void kernel_launch(void* const* d_in, const int* in_sizes, int n_in,
                              void* d_out, int out_size)
{
    const float* x    = (const float*)d_in[0];
    const float* ln1g = (const float*)d_in[1];
    const float* ln1b = (const float*)d_in[2];
    const float* wqkv = (const float*)d_in[3];
    const float* wout = (const float*)d_in[4];
    const float* ln2g = (const float*)d_in[5];
    const float* ln2b = (const float*)d_in[6];
    const float* w1   = (const float*)d_in[7];
    const float* b1   = (const float*)d_in[8];
    const float* w2   = (const float*)d_in[9];
    const float* b2   = (const float*)d_in[10];
    const float* fng  = (const float*)d_in[11];
    const float* fnb  = (const float*)d_in[12];

    float *px;
    __half *pqkv, *pln16, *pct16, *ph16;
    __half *qkvt, *outt, *w1t, *w2t;
    cudaGetSymbolAddress((void**)&px,    g_x);
    cudaGetSymbolAddress((void**)&pqkv,  g_qkv16);
    cudaGetSymbolAddress((void**)&pln16, g_ln16);
    cudaGetSymbolAddress((void**)&pct16, g_ct16);
    cudaGetSymbolAddress((void**)&ph16,  g_h16);
    cudaGetSymbolAddress((void**)&qkvt,  g_wqkvt);
    cudaGetSymbolAddress((void**)&outt,  g_woutt);
    cudaGetSymbolAddress((void**)&w1t,   g_w1t);
    cudaGetSymbolAddress((void**)&w2t,   g_w2t);

    cudaFuncSetAttribute(gemm_mma<0>, cudaFuncAttributeMaxDynamicSharedMemorySize, GEMM_SMEM);
    cudaFuncSetAttribute(gemm_mma<1>, cudaFuncAttributeMaxDynamicSharedMemorySize, GEMM_SMEM);
    cudaFuncSetAttribute(gemm_mma<2>, cudaFuncAttributeMaxDynamicSharedMemorySize, GEMM_SMEM);
    cudaFuncSetAttribute(gemm_mma<3>, cudaFuncAttributeMaxDynamicSharedMemorySize, GEMM_SMEM);
    cudaFuncSetAttribute(attn_mma, cudaFuncAttributeMaxDynamicSharedMemorySize, ATTN_SMEM);

    {
        dim3 tblk(32, 8);
        transpose_cvt<<<dim3(QKVD/32, DIM/32, DEPTH), tblk>>>(wqkv, qkvt, DIM, QKVD);
        transpose_cvt<<<dim3(DIM/32, INNER/32, DEPTH), tblk>>>(wout, outt, INNER, DIM);
        transpose_cvt<<<dim3(MLPD/32, DIM/32, DEPTH), tblk>>>(w1, w1t, DIM, MLPD);
        transpose_cvt<<<dim3(DIM/32, MLPD/32, DEPTH), tblk>>>(w2, w2t, MLPD, DIM);
    }

    cudaMemcpyAsync(px, x, sizeof(float) * (size_t)TOK * DIM,
                    cudaMemcpyDeviceToDevice, 0);

    const dim3 blk256(256);
    for (int i = 0; i < DEPTH; i++) {
        ln_kernel<true><<<TOK/8, blk256>>>(px, ln1g + i*DIM, ln1b + i*DIM,
                                           nullptr, pln16);
        gemm_mma<0><<<dim3(QKVD/128, TOK/128), blk256, GEMM_SMEM>>>(
            pln16, qkvt + (size_t)i*QKVD*DIM,
            nullptr, nullptr, pqkv, TOK, QKVD, DIM);
        attn_mma<<<dim3(SEQ/128, HEADS, BATCH), blk256, ATTN_SMEM>>>(pqkv, pct16);
        gemm_mma<3><<<dim3(DIM/128, TOK/128), blk256, GEMM_SMEM>>>(
            pct16, outt + (size_t)i*DIM*INNER,
            nullptr, px, nullptr, TOK, DIM, INNER);

        ln_kernel<true><<<TOK/8, blk256>>>(px, ln2g + i*DIM, ln2b + i*DIM,
                                           nullptr, pln16);
        gemm_mma<1><<<dim3(MLPD/128, TOK/128), blk256, GEMM_SMEM>>>(
            pln16, w1t + (size_t)i*MLPD*DIM,
            b1 + (size_t)i*MLPD, nullptr, ph16, TOK, MLPD, DIM);
        gemm_mma<2><<<dim3(DIM/128, TOK/128), blk256, GEMM_SMEM>>>(
            ph16, w2t + (size_t)i*DIM*MLPD,
            b2 + (size_t)i*DIM, px, nullptr, TOK, DIM, MLPD);
    }

    ln_kernel<false><<<TOK/8, blk256>>>(px, fng, fnb, (float*)d_out, nullptr);
}

// round 14
// speedup vs baseline: 2.7050x; 1.0044x over previous
#include <cuda_runtime.h>
#include <cuda_bf16.h>
#include <cuda_fp16.h>
#include <math.h>
#include <stdint.h>

#define DIM    768
#define DEPTH  6
#define HEADS  12
#define DHEAD  64
#define INNER  768
#define MLPD   3072
#define BATCH  4
#define SEQ    2048
#define TOK    (BATCH*SEQ)      /* 8192 */
#define QKVD   (3*INNER)        /* 2304 */
#define QSCALE 0.18033688011112042f   /* 0.125 * log2(e) */

// ---------------- scratch (device globals; no allocations) ----------------
__device__ float  g_x   [(size_t)TOK*DIM];    // residual stream fp32
__device__ __half g_qkv16[(size_t)TOK*QKVD];  // fused qkv fp16 (Q pre-scaled)
__device__ __half g_ln16[(size_t)TOK*DIM];    // LN output fp16
__device__ __half g_ct16[(size_t)TOK*DIM];    // attention ctx fp16
__device__ __half g_h16 [(size_t)TOK*MLPD];   // mlp hidden fp16
// transposed fp16 weights [layer][N][K]
__device__ __half g_wqkvt[(size_t)DEPTH*QKVD*DIM];
__device__ __half g_woutt[(size_t)DEPTH*DIM*INNER];
__device__ __half g_w1t  [(size_t)DEPTH*MLPD*DIM];
__device__ __half g_w2t  [(size_t)DEPTH*DIM*MLPD];

// ====================== PTX helpers =======================================
__device__ __forceinline__ uint32_t smem_u32(const void* p){
    uint32_t a;
    asm("{ .reg .u64 t; cvta.to.shared.u64 t, %1; cvt.u32.u64 %0, t; }"
        : "=r"(a) : "l"(p));
    return a;
}
__device__ __forceinline__ void cp16(uint32_t s, const void* g){
    asm volatile("cp.async.cg.shared.global [%0], [%1], 16;" :: "r"(s), "l"(g));
}
#define CP_COMMIT() asm volatile("cp.async.commit_group;" ::: "memory")
#define CP_WAIT1()  asm volatile("cp.async.wait_group 1;" ::: "memory")
#define CP_WAIT0()  asm volatile("cp.async.wait_group 0;" ::: "memory")

__device__ __forceinline__ void ldmx4(uint32_t addr, uint32_t& r0, uint32_t& r1,
                                      uint32_t& r2, uint32_t& r3){
    asm volatile("ldmatrix.sync.aligned.m8n8.x4.shared.b16 {%0,%1,%2,%3}, [%4];"
        : "=r"(r0), "=r"(r1), "=r"(r2), "=r"(r3) : "r"(addr));
}
__device__ __forceinline__ void ldmx4t(uint32_t addr, uint32_t& r0, uint32_t& r1,
                                       uint32_t& r2, uint32_t& r3){
    asm volatile("ldmatrix.sync.aligned.m8n8.x4.trans.shared.b16 {%0,%1,%2,%3}, [%4];"
        : "=r"(r0), "=r"(r1), "=r"(r2), "=r"(r3) : "r"(addr));
}
// fp16 mma
__device__ __forceinline__ void mma16816h(float* c, const uint32_t* a,
                                          uint32_t b0, uint32_t b1){
    asm volatile(
        "mma.sync.aligned.m16n8k16.row.col.f32.f16.f16.f32 "
        "{%0,%1,%2,%3}, {%4,%5,%6,%7}, {%8,%9}, {%0,%1,%2,%3};"
        : "+f"(c[0]), "+f"(c[1]), "+f"(c[2]), "+f"(c[3])
        : "r"(a[0]), "r"(a[1]), "r"(a[2]), "r"(a[3]), "r"(b0), "r"(b1));
}
// FMA-pipe exp2 (degree-6 Taylor on [-0.5,0.5]); valid for t <= 0
__device__ __forceinline__ float exp2_fast(float t){
    t = fmaxf(t, -120.f);
    float n = rintf(t);
    float f = t - n;
    float p = 1.5403530e-4f;
    p = fmaf(p, f, 1.3333558e-3f);
    p = fmaf(p, f, 9.6181291e-3f);
    p = fmaf(p, f, 5.5504109e-2f);
    p = fmaf(p, f, 2.4022651e-1f);
    p = fmaf(p, f, 6.9314718e-1f);
    p = fmaf(p, f, 1.0f);
    return __int_as_float(__float_as_int(p) + (((int)n) << 23));
}

// ====================== weight transpose to fp16 ===========================
__global__ void transpose_cvt(const float* __restrict__ W,
                              __half* __restrict__ Wh, int K, int N)
{
    __shared__ float tile[32][33];
    const size_t off = (size_t)blockIdx.z * K * N;
    const int n0 = blockIdx.x * 32, k0 = blockIdx.y * 32;
    const int tx = threadIdx.x, ty = threadIdx.y;
#pragma unroll
    for (int i = 0; i < 32; i += 8)
        tile[ty + i][tx] = W[off + (size_t)(k0 + ty + i) * N + n0 + tx];
    __syncthreads();
#pragma unroll
    for (int i = 0; i < 32; i += 8) {
        size_t oidx = off + (size_t)(n0 + ty + i) * K + k0 + tx;
        Wh[oidx] = __float2half_rn(tile[tx][ty + i]);
    }
}

// ====================== LayerNorm: 1 warp / token, 8 tokens / block ========
template<bool HOUT>
__global__ void ln_kernel(const float* __restrict__ x, const float* __restrict__ g,
                          const float* __restrict__ b, float* __restrict__ y,
                          __half* __restrict__ yh)
{
    const int warp = threadIdx.x >> 5, lane = threadIdx.x & 31;
    const int t = blockIdx.x * 8 + warp;
    const float* xp = x + (size_t)t * DIM;

    float v[24];
    float s1 = 0.f, s2 = 0.f;
#pragma unroll
    for (int i = 0; i < 6; i++) {
        float4 f = *reinterpret_cast<const float4*>(xp + i * 128 + lane * 4);
        v[i*4+0] = f.x; v[i*4+1] = f.y; v[i*4+2] = f.z; v[i*4+3] = f.w;
        s1 += f.x + f.y + f.z + f.w;
        s2 += f.x*f.x + f.y*f.y + f.z*f.z + f.w*f.w;
    }
#pragma unroll
    for (int o = 16; o > 0; o >>= 1) {
        s1 += __shfl_xor_sync(0xffffffffu, s1, o);
        s2 += __shfl_xor_sync(0xffffffffu, s2, o);
    }
    const float mu  = s1 * (1.f / DIM);
    const float var = s2 * (1.f / DIM) - mu * mu;
    const float rs  = rsqrtf(var + 1e-5f);

#pragma unroll
    for (int i = 0; i < 6; i++) {
        const int d = i * 128 + lane * 4;
        float4 gg = *reinterpret_cast<const float4*>(g + d);
        float4 bb = *reinterpret_cast<const float4*>(b + d);
        float y0 = (v[i*4+0] - mu) * rs * gg.x + bb.x;
        float y1 = (v[i*4+1] - mu) * rs * gg.y + bb.y;
        float y2 = (v[i*4+2] - mu) * rs * gg.z + bb.z;
        float y3 = (v[i*4+3] - mu) * rs * gg.w + bb.w;
        if (HOUT) {
            uint2 pk;
            __half h0 = __float2half_rn(y0), h1 = __float2half_rn(y1);
            __half h2 = __float2half_rn(y2), h3 = __float2half_rn(y3);
            pk.x = (uint32_t)__half_as_ushort(h0) | ((uint32_t)__half_as_ushort(h1) << 16);
            pk.y = (uint32_t)__half_as_ushort(h2) | ((uint32_t)__half_as_ushort(h3) << 16);
            *reinterpret_cast<uint2*>(yh + (size_t)t * DIM + d) = pk;
        } else {
            *reinterpret_cast<float4*>(y + (size_t)t * DIM + d) =
                make_float4(y0, y1, y2, y3);
        }
    }
}

// ====================== fp16 1-product GEMM (BK=64, 3-stage, 2 CTAs/SM) ====
// C[M,N] = A[M,K] @ B[N,K]^T; fp16 in, fp32 accum.
// CTA 128x128, warp 32x64, BK=64, 3-stage cp.async.
// Split-K via gridDim.z: each z-slice handles K/gridDim.z contraction range.
// EPI: 0 = qkv out (scale Q cols, fp16); 1 = +bias, gelu, fp16 out;
//      2 = +bias (z==0) atomic += xres; 3 = atomic += xres.
#define STAGE_SZ 32768u
template<int EPI>
__global__ void __launch_bounds__(256, 2)
gemm_mma(const __half* __restrict__ Ah, const __half* __restrict__ Bh,
         const float* __restrict__ bias, float* __restrict__ xres,
         __half* __restrict__ Ch, int M, int N, int K)
{
    extern __shared__ char smem[];
    const uint32_t sb0 = smem_u32(smem);
    const int tid  = threadIdx.x;
    const int lane = tid & 31, warp = tid >> 5;
    const int wm = warp >> 1, wn = warp & 1;
    const int bn = blockIdx.x, bm = blockIdx.y;
    const int ksp   = K / (int)gridDim.z;          // per-split K
    const int kbase = blockIdx.z * ksp;
    const int nkt   = ksp >> 6;

    auto load_stage = [&](int kt, int st){
        const uint32_t base = sb0 + (uint32_t)st * STAGE_SZ;
        const size_t kof = (size_t)kbase + (size_t)kt * 64;
#pragma unroll
        for (int i = 0; i < 4; i++) {
            const int idx = tid + i * 256;
            const int row = idx >> 3, c = idx & 7;
            const uint32_t so = (uint32_t)(row * 128 + ((c ^ (row & 7)) << 4));
            const size_t ga = (size_t)(bm * 128 + row) * K + kof + c * 8;
            const size_t gb = (size_t)(bn * 128 + row) * K + kof + c * 8;
            cp16(base + so,          Ah + ga);
            cp16(base + 16384u + so, Bh + gb);
        }
    };

    float acc[2][8][4];
#pragma unroll
    for (int mt = 0; mt < 2; mt++)
#pragma unroll
        for (int nt = 0; nt < 8; nt++)
#pragma unroll
            for (int q = 0; q < 4; q++) acc[mt][nt][q] = 0.f;

    load_stage(0, 0); CP_COMMIT();
    load_stage(1, 1); CP_COMMIT();

    const int arow = wm * 32 + (lane & 15);
    const int acs  = lane >> 4;
    const int brow = wn * 64 + (lane & 7) + ((lane >> 4) << 3);
    const int bcs  = (lane >> 3) & 1;

    for (int kt = 0; kt < nkt; kt++) {
        if (kt == nkt - 1) { CP_WAIT0(); } else { CP_WAIT1(); }
        __syncthreads();
        if (kt + 2 < nkt) { load_stage(kt + 2, (kt + 2) % 3); CP_COMMIT(); }

        const uint32_t base = sb0 + (uint32_t)(kt % 3) * STAGE_SZ;
#pragma unroll
        for (int ks = 0; ks < 4; ks++) {
            uint32_t ah[2][4];
#pragma unroll
            for (int mt = 0; mt < 2; mt++) {
                const int r = arow + mt * 16;
                const int c = ks * 2 + acs;
                const uint32_t off = (uint32_t)(r * 128 + ((c ^ (r & 7)) << 4));
                ldmx4(base + off, ah[mt][0], ah[mt][1], ah[mt][2], ah[mt][3]);
            }
#pragma unroll
            for (int bt = 0; bt < 4; bt++) {
                const int r = brow + bt * 16;
                const int c = ks * 2 + bcs;
                const uint32_t off = (uint32_t)(r * 128 + ((c ^ (r & 7)) << 4));
                uint32_t bh[4];
                ldmx4(base + 16384u + off, bh[0], bh[1], bh[2], bh[3]);
#pragma unroll
                for (int mt = 0; mt < 2; mt++) {
                    mma16816h(acc[mt][2*bt],   ah[mt], bh[0], bh[1]);
                    mma16816h(acc[mt][2*bt+1], ah[mt], bh[2], bh[3]);
                }
            }
        }
        __syncthreads();
    }

    const int rbase = bm * 128 + wm * 32 + (lane >> 2);
    const int cbase = bn * 128 + wn * 64 + (lane & 3) * 2;
    const bool z0 = (blockIdx.z == 0);
#pragma unroll
    for (int mt = 0; mt < 2; mt++) {
#pragma unroll
        for (int nt = 0; nt < 8; nt++) {
            const int gcol = cbase + nt * 8;
#pragma unroll
            for (int h = 0; h < 2; h++) {
                const int grow = rbase + mt * 16 + h * 8;
                float v0 = acc[mt][nt][2*h], v1 = acc[mt][nt][2*h+1];
                const size_t oidx = (size_t)grow * N + gcol;
                if (EPI == 0 || EPI == 1) {
                    if (EPI == 0) {
                        const float sc = (gcol < INNER) ? QSCALE : 1.f;
                        v0 *= sc; v1 *= sc;
                    } else {
                        v0 += bias[gcol];     v1 += bias[gcol + 1];
                        v0 = 0.5f * v0 * (1.f + erff(v0 * 0.70710678118654752f));
                        v1 = 0.5f * v1 * (1.f + erff(v1 * 0.70710678118654752f));
                    }
                    __half h0 = __float2half_rn(v0), h1 = __float2half_rn(v1);
                    *reinterpret_cast<uint32_t*>(Ch + oidx) =
                        (uint32_t)__half_as_ushort(h0) |
                        ((uint32_t)__half_as_ushort(h1) << 16);
                } else {
                    if (EPI == 2 && z0) { v0 += bias[gcol]; v1 += bias[gcol + 1]; }
                    atomicAdd(xres + oidx,     v0);
                    atomicAdd(xres + oidx + 1, v1);
                }
            }
        }
    }
}

// ====================== fp16 1-product flash attention (2 CTAs/SM) =========
// grid (SEQ/128, HEADS, BATCH), 256 threads (8 warps x 16 query rows).
#define ATTN_SMEM (16384 + 2*16384)
__global__ void __launch_bounds__(256, 2)
attn_mma(const __half* __restrict__ qkv, __half* __restrict__ ctx)
{
    extern __shared__ char smem[];
    const uint32_t sb = smem_u32(smem);
    const uint32_t QS = sb;
    const int tid = threadIdx.x, lane = tid & 31, wid = tid >> 5;
    const int b = blockIdx.z, h = blockIdx.y, qt = blockIdx.x;
    const int tok0 = b * SEQ + qt * 128;

#pragma unroll
    for (int i = 0; i < 4; i++) {
        const int idx = tid + i * 256;
        const int row = idx >> 3, c = idx & 7;
        const uint32_t so = (uint32_t)(row * 128 + ((c ^ (row & 7)) << 4));
        cp16(QS + so, qkv + (size_t)(tok0 + row) * QKVD + h * DHEAD + c * 8);
    }

    auto load_kv = [&](int t, int st){
        const uint32_t base = sb + 16384u + (uint32_t)st * 16384u;
        const int kv0 = b * SEQ + t * 64;
#pragma unroll
        for (int i = 0; i < 2; i++) {
            const int idx = tid + i * 256;
            const int row = idx >> 3, c = idx & 7;
            const uint32_t so = (uint32_t)(row * 128 + ((c ^ (row & 7)) << 4));
            const size_t gk = (size_t)(kv0 + row) * QKVD + INNER + h * DHEAD + c * 8;
            const size_t gv = (size_t)(kv0 + row) * QKVD + 2 * INNER + h * DHEAD + c * 8;
            cp16(base + so,         qkv + gk);
            cp16(base + 8192u + so, qkv + gv);
        }
    };
    load_kv(0, 0); CP_COMMIT();

    float O[8][4];
#pragma unroll
    for (int nt = 0; nt < 8; nt++)
#pragma unroll
        for (int q = 0; q < 4; q++) O[nt][q] = 0.f;
    float m0 = -1e30f, m1 = -1e30f, l0 = 0.f, l1 = 0.f;
    const int m0row = wid * 16;

    const int NT = SEQ / 64;
    for (int t = 0; t < NT; t++) {
        if (t + 1 < NT) { load_kv(t + 1, (t + 1) & 1); CP_COMMIT(); CP_WAIT1(); }
        else            { CP_WAIT0(); }
        __syncthreads();
        const uint32_t kb = sb + 16384u + (uint32_t)(t & 1) * 16384u;

        float S[8][4];
#pragma unroll
        for (int nt = 0; nt < 8; nt++)
#pragma unroll
            for (int q = 0; q < 4; q++) S[nt][q] = 0.f;
#pragma unroll
        for (int ks = 0; ks < 4; ks++) {
            uint32_t qf[4];
            {
                const int r = m0row + (lane & 15);
                const int c = ks * 2 + (lane >> 4);
                const uint32_t off = (uint32_t)(r * 128 + ((c ^ (r & 7)) << 4));
                ldmx4(QS + off, qf[0], qf[1], qf[2], qf[3]);
            }
#pragma unroll
            for (int bt = 0; bt < 4; bt++) {
                const int r = bt * 16 + (lane & 7) + ((lane >> 4) << 3);
                const int c = ks * 2 + ((lane >> 3) & 1);
                const uint32_t off = (uint32_t)(r * 128 + ((c ^ (r & 7)) << 4));
                uint32_t kh[4];
                ldmx4(kb + off, kh[0], kh[1], kh[2], kh[3]);
                mma16816h(S[2*bt],   qf, kh[0], kh[1]);
                mma16816h(S[2*bt+1], qf, kh[2], kh[3]);
            }
        }

        float mt0 = -1e30f, mt1 = -1e30f;
#pragma unroll
        for (int nt = 0; nt < 8; nt++) {
            mt0 = fmaxf(mt0, fmaxf(S[nt][0], S[nt][1]));
            mt1 = fmaxf(mt1, fmaxf(S[nt][2], S[nt][3]));
        }
        mt0 = fmaxf(mt0, __shfl_xor_sync(0xffffffffu, mt0, 1));
        mt0 = fmaxf(mt0, __shfl_xor_sync(0xffffffffu, mt0, 2));
        mt1 = fmaxf(mt1, __shfl_xor_sync(0xffffffffu, mt1, 1));
        mt1 = fmaxf(mt1, __shfl_xor_sync(0xffffffffu, mt1, 2));
        const float mn0 = fmaxf(m0, mt0), mn1 = fmaxf(m1, mt1);
        const float cr0 = exp2_fast(m0 - mn0), cr1 = exp2_fast(m1 - mn1);
        m0 = mn0; m1 = mn1;

        uint32_t phi[4][4];
        float s0 = 0.f, s1 = 0.f;
#pragma unroll
        for (int nt = 0; nt < 8; nt++) {
            float p0 = exp2_fast(S[nt][0] - m0);
            float p1 = exp2_fast(S[nt][1] - m0);
            float p2 = exp2_fast(S[nt][2] - m1);
            float p3 = exp2_fast(S[nt][3] - m1);
            s0 += p0 + p1; s1 += p2 + p3;
            __half h0 = __float2half_rn(p0), h1 = __float2half_rn(p1);
            __half h2 = __float2half_rn(p2), h3 = __float2half_rn(p3);
            const int t2 = nt >> 1, o = (nt & 1) * 2;
            phi[t2][o] = (uint32_t)__half_as_ushort(h0) |
                         ((uint32_t)__half_as_ushort(h1) << 16);
            phi[t2][o+1] = (uint32_t)__half_as_ushort(h2) |
                           ((uint32_t)__half_as_ushort(h3) << 16);
        }
        s0 += __shfl_xor_sync(0xffffffffu, s0, 1);
        s0 += __shfl_xor_sync(0xffffffffu, s0, 2);
        s1 += __shfl_xor_sync(0xffffffffu, s1, 1);
        s1 += __shfl_xor_sync(0xffffffffu, s1, 2);
        l0 = l0 * cr0 + s0;
        l1 = l1 * cr1 + s1;
#pragma unroll
        for (int nt = 0; nt < 8; nt++) {
            O[nt][0] *= cr0; O[nt][1] *= cr0;
            O[nt][2] *= cr1; O[nt][3] *= cr1;
        }

#pragma unroll
        for (int t2 = 0; t2 < 4; t2++) {
#pragma unroll
            for (int dn = 0; dn < 4; dn++) {
                const int r = t2 * 16 + (lane & 15);
                const int c = dn * 2 + (lane >> 4);
                const uint32_t off = (uint32_t)(r * 128 + ((c ^ (r & 7)) << 4));
                uint32_t vh[4];
                ldmx4t(kb + 8192u + off, vh[0], vh[1], vh[2], vh[3]);
                mma16816h(O[2*dn],   phi[t2], vh[0], vh[1]);
                mma16816h(O[2*dn+1], phi[t2], vh[2], vh[3]);
            }
        }
        __syncthreads();
    }

    const float i0 = 1.f / l0, i1 = 1.f / l1;
    const int r0 = tok0 + m0row + (lane >> 2);
#pragma unroll
    for (int nt = 0; nt < 8; nt++) {
        const int col = h * DHEAD + nt * 8 + (lane & 3) * 2;
#pragma unroll
        for (int hh = 0; hh < 2; hh++) {
            const float inv = hh ? i1 : i0;
            float v0 = O[nt][2*hh] * inv, v1 = O[nt][2*hh+1] * inv;
            __half h0 = __float2half_rn(v0), h1 = __float2half_rn(v1);
            const size_t oidx = (size_t)(r0 + hh * 8) * DIM + col;
            *reinterpret_cast<uint32_t*>(ctx + oidx) =
                (uint32_t)__half_as_ushort(h0) |
                ((uint32_t)__half_as_ushort(h1) << 16);
        }
    }
}

// ====================== driver =============================================
#define GEMM_SMEM (3 * 32768)

extern "C" void kernel_launch(void* const* d_in, const int* in_sizes, int n_in,
                              void* d_out, int out_size)
{
    const float* x    = (const float*)d_in[0];
    const float* ln1g = (const float*)d_in[1];
    const float* ln1b = (const float*)d_in[2];
    const float* wqkv = (const float*)d_in[3];
    const float* wout = (const float*)d_in[4];
    const float* ln2g = (const float*)d_in[5];
    const float* ln2b = (const float*)d_in[6];
    const float* w1   = (const float*)d_in[7];
    const float* b1   = (const float*)d_in[8];
    const float* w2   = (const float*)d_in[9];
    const float* b2   = (const float*)d_in[10];
    const float* fng  = (const float*)d_in[11];
    const float* fnb  = (const float*)d_in[12];

    float *px;
    __half *pqkv, *pln16, *pct16, *ph16;
    __half *qkvt, *outt, *w1t, *w2t;
    cudaGetSymbolAddress((void**)&px,    g_x);
    cudaGetSymbolAddress((void**)&pqkv,  g_qkv16);
    cudaGetSymbolAddress((void**)&pln16, g_ln16);
    cudaGetSymbolAddress((void**)&pct16, g_ct16);
    cudaGetSymbolAddress((void**)&ph16,  g_h16);
    cudaGetSymbolAddress((void**)&qkvt,  g_wqkvt);
    cudaGetSymbolAddress((void**)&outt,  g_woutt);
    cudaGetSymbolAddress((void**)&w1t,   g_w1t);
    cudaGetSymbolAddress((void**)&w2t,   g_w2t);

    cudaFuncSetAttribute(gemm_mma<0>, cudaFuncAttributeMaxDynamicSharedMemorySize, GEMM_SMEM);
    cudaFuncSetAttribute(gemm_mma<1>, cudaFuncAttributeMaxDynamicSharedMemorySize, GEMM_SMEM);
    cudaFuncSetAttribute(gemm_mma<2>, cudaFuncAttributeMaxDynamicSharedMemorySize, GEMM_SMEM);
    cudaFuncSetAttribute(gemm_mma<3>, cudaFuncAttributeMaxDynamicSharedMemorySize, GEMM_SMEM);
    cudaFuncSetAttribute(attn_mma, cudaFuncAttributeMaxDynamicSharedMemorySize, ATTN_SMEM);

    {
        dim3 tblk(32, 8);
        transpose_cvt<<<dim3(QKVD/32, DIM/32, DEPTH), tblk>>>(wqkv, qkvt, DIM, QKVD);
        transpose_cvt<<<dim3(DIM/32, INNER/32, DEPTH), tblk>>>(wout, outt, INNER, DIM);
        transpose_cvt<<<dim3(MLPD/32, DIM/32, DEPTH), tblk>>>(w1, w1t, DIM, MLPD);
        transpose_cvt<<<dim3(DIM/32, MLPD/32, DEPTH), tblk>>>(w2, w2t, MLPD, DIM);
    }

    cudaMemcpyAsync(px, x, sizeof(float) * (size_t)TOK * DIM,
                    cudaMemcpyDeviceToDevice, 0);

    const dim3 blk256(256);
    for (int i = 0; i < DEPTH; i++) {
        ln_kernel<true><<<TOK/8, blk256>>>(px, ln1g + i*DIM, ln1b + i*DIM,
                                           nullptr, pln16);
        gemm_mma<0><<<dim3(QKVD/128, TOK/128), blk256, GEMM_SMEM>>>(
            pln16, qkvt + (size_t)i*QKVD*DIM,
            nullptr, nullptr, pqkv, TOK, QKVD, DIM);
        attn_mma<<<dim3(SEQ/128, HEADS, BATCH), blk256, ATTN_SMEM>>>(pqkv, pct16);
        gemm_mma<3><<<dim3(DIM/128, TOK/128, 2), blk256, GEMM_SMEM>>>(
            pct16, outt + (size_t)i*DIM*INNER,
            nullptr, px, nullptr, TOK, DIM, INNER);

        ln_kernel<true><<<TOK/8, blk256>>>(px, ln2g + i*DIM, ln2b + i*DIM,
                                           nullptr, pln16);
        gemm_mma<1><<<dim3(MLPD/128, TOK/128), blk256, GEMM_SMEM>>>(
            pln16, w1t + (size_t)i*MLPD*DIM,
            b1 + (size_t)i*MLPD, nullptr, ph16, TOK, MLPD, DIM);
        gemm_mma<2><<<dim3(DIM/128, TOK/128, 2), blk256, GEMM_SMEM>>>(
            ph16, w2t + (size_t)i*DIM*MLPD,
            b2 + (size_t)i*DIM, px, nullptr, TOK, DIM, MLPD);
    }

    ln_kernel<false><<<TOK/8, blk256>>>(px, fng, fnb, (float*)d_out, nullptr);
}

// round 15
// speedup vs baseline: 2.7621x; 1.0211x over previous
#include <cuda_runtime.h>
#include <cuda_bf16.h>
#include <cuda_fp16.h>
#include <math.h>
#include <stdint.h>

#define DIM    768
#define DEPTH  6
#define HEADS  12
#define DHEAD  64
#define INNER  768
#define MLPD   3072
#define BATCH  4
#define SEQ    2048
#define TOK    (BATCH*SEQ)      /* 8192 */
#define QKVD   (3*INNER)        /* 2304 */
#define QSCALE 0.18033688011112042f   /* 0.125 * log2(e) */

// ---------------- scratch (device globals; no allocations) ----------------
__device__ float  g_x   [(size_t)TOK*DIM];    // residual stream fp32
__device__ __half g_qkv16[(size_t)TOK*QKVD];  // fused qkv fp16 (Q pre-scaled)
__device__ __half g_ln16[(size_t)TOK*DIM];    // LN output fp16
__device__ __half g_ct16[(size_t)TOK*DIM];    // attention ctx fp16
__device__ __half g_h16 [(size_t)TOK*MLPD];   // mlp hidden fp16
// transposed fp16 weights [layer][N][K]
__device__ __half g_wqkvt[(size_t)DEPTH*QKVD*DIM];
__device__ __half g_woutt[(size_t)DEPTH*DIM*INNER];
__device__ __half g_w1t  [(size_t)DEPTH*MLPD*DIM];
__device__ __half g_w2t  [(size_t)DEPTH*DIM*MLPD];

// ====================== PTX helpers =======================================
__device__ __forceinline__ uint32_t smem_u32(const void* p){
    uint32_t a;
    asm("{ .reg .u64 t; cvta.to.shared.u64 t, %1; cvt.u32.u64 %0, t; }"
        : "=r"(a) : "l"(p));
    return a;
}
__device__ __forceinline__ void cp16(uint32_t s, const void* g){
    asm volatile("cp.async.cg.shared.global [%0], [%1], 16;" :: "r"(s), "l"(g));
}
#define CP_COMMIT() asm volatile("cp.async.commit_group;" ::: "memory")
#define CP_WAIT1()  asm volatile("cp.async.wait_group 1;" ::: "memory")
#define CP_WAIT0()  asm volatile("cp.async.wait_group 0;" ::: "memory")

__device__ __forceinline__ void ldmx4(uint32_t addr, uint32_t& r0, uint32_t& r1,
                                      uint32_t& r2, uint32_t& r3){
    asm volatile("ldmatrix.sync.aligned.m8n8.x4.shared.b16 {%0,%1,%2,%3}, [%4];"
        : "=r"(r0), "=r"(r1), "=r"(r2), "=r"(r3) : "r"(addr));
}
__device__ __forceinline__ void ldmx4t(uint32_t addr, uint32_t& r0, uint32_t& r1,
                                       uint32_t& r2, uint32_t& r3){
    asm volatile("ldmatrix.sync.aligned.m8n8.x4.trans.shared.b16 {%0,%1,%2,%3}, [%4];"
        : "=r"(r0), "=r"(r1), "=r"(r2), "=r"(r3) : "r"(addr));
}
// fp16 mma
__device__ __forceinline__ void mma16816h(float* c, const uint32_t* a,
                                          uint32_t b0, uint32_t b1){
    asm volatile(
        "mma.sync.aligned.m16n8k16.row.col.f32.f16.f16.f32 "
        "{%0,%1,%2,%3}, {%4,%5,%6,%7}, {%8,%9}, {%0,%1,%2,%3};"
        : "+f"(c[0]), "+f"(c[1]), "+f"(c[2]), "+f"(c[3])
        : "r"(a[0]), "r"(a[1]), "r"(a[2]), "r"(a[3]), "r"(b0), "r"(b1));
}
// FMA-pipe exp2; degree-6 (accurate) for GEMM-side uses if any
__device__ __forceinline__ float exp2_fast(float t){
    t = fmaxf(t, -120.f);
    float n = rintf(t);
    float f = t - n;
    float p = 1.5403530e-4f;
    p = fmaf(p, f, 1.3333558e-3f);
    p = fmaf(p, f, 9.6181291e-3f);
    p = fmaf(p, f, 5.5504109e-2f);
    p = fmaf(p, f, 2.4022651e-1f);
    p = fmaf(p, f, 6.9314718e-1f);
    p = fmaf(p, f, 1.0f);
    return __int_as_float(__float_as_int(p) + (((int)n) << 23));
}
// degree-4 exp2 for softmax probabilities (rel err ~4e-5)
__device__ __forceinline__ float exp2_p4(float t){
    t = fmaxf(t, -120.f);
    float n = rintf(t);
    float f = t - n;
    float p = 9.6181291e-3f;
    p = fmaf(p, f, 5.5504109e-2f);
    p = fmaf(p, f, 2.4022651e-1f);
    p = fmaf(p, f, 6.9314718e-1f);
    p = fmaf(p, f, 1.0f);
    return __int_as_float(__float_as_int(p) + (((int)n) << 23));
}

// ====================== weight transpose to fp16 ===========================
__global__ void transpose_cvt(const float* __restrict__ W,
                              __half* __restrict__ Wh, int K, int N)
{
    __shared__ float tile[32][33];
    const size_t off = (size_t)blockIdx.z * K * N;
    const int n0 = blockIdx.x * 32, k0 = blockIdx.y * 32;
    const int tx = threadIdx.x, ty = threadIdx.y;
#pragma unroll
    for (int i = 0; i < 32; i += 8)
        tile[ty + i][tx] = W[off + (size_t)(k0 + ty + i) * N + n0 + tx];
    __syncthreads();
#pragma unroll
    for (int i = 0; i < 32; i += 8) {
        size_t oidx = off + (size_t)(n0 + ty + i) * K + k0 + tx;
        Wh[oidx] = __float2half_rn(tile[tx][ty + i]);
    }
}

// ====================== LayerNorm: 1 warp / token, 8 tokens / block ========
template<bool HOUT>
__global__ void ln_kernel(const float* __restrict__ x, const float* __restrict__ g,
                          const float* __restrict__ b, float* __restrict__ y,
                          __half* __restrict__ yh)
{
    const int warp = threadIdx.x >> 5, lane = threadIdx.x & 31;
    const int t = blockIdx.x * 8 + warp;
    const float* xp = x + (size_t)t * DIM;

    float v[24];
    float s1 = 0.f, s2 = 0.f;
#pragma unroll
    for (int i = 0; i < 6; i++) {
        float4 f = *reinterpret_cast<const float4*>(xp + i * 128 + lane * 4);
        v[i*4+0] = f.x; v[i*4+1] = f.y; v[i*4+2] = f.z; v[i*4+3] = f.w;
        s1 += f.x + f.y + f.z + f.w;
        s2 += f.x*f.x + f.y*f.y + f.z*f.z + f.w*f.w;
    }
#pragma unroll
    for (int o = 16; o > 0; o >>= 1) {
        s1 += __shfl_xor_sync(0xffffffffu, s1, o);
        s2 += __shfl_xor_sync(0xffffffffu, s2, o);
    }
    const float mu  = s1 * (1.f / DIM);
    const float var = s2 * (1.f / DIM) - mu * mu;
    const float rs  = rsqrtf(var + 1e-5f);

#pragma unroll
    for (int i = 0; i < 6; i++) {
        const int d = i * 128 + lane * 4;
        float4 gg = *reinterpret_cast<const float4*>(g + d);
        float4 bb = *reinterpret_cast<const float4*>(b + d);
        float y0 = (v[i*4+0] - mu) * rs * gg.x + bb.x;
        float y1 = (v[i*4+1] - mu) * rs * gg.y + bb.y;
        float y2 = (v[i*4+2] - mu) * rs * gg.z + bb.z;
        float y3 = (v[i*4+3] - mu) * rs * gg.w + bb.w;
        if (HOUT) {
            uint2 pk;
            __half h0 = __float2half_rn(y0), h1 = __float2half_rn(y1);
            __half h2 = __float2half_rn(y2), h3 = __float2half_rn(y3);
            pk.x = (uint32_t)__half_as_ushort(h0) | ((uint32_t)__half_as_ushort(h1) << 16);
            pk.y = (uint32_t)__half_as_ushort(h2) | ((uint32_t)__half_as_ushort(h3) << 16);
            *reinterpret_cast<uint2*>(yh + (size_t)t * DIM + d) = pk;
        } else {
            *reinterpret_cast<float4*>(y + (size_t)t * DIM + d) =
                make_float4(y0, y1, y2, y3);
        }
    }
}

// ====================== fp16 1-product GEMM (BK=64, 3-stage, 2 CTAs/SM) ====
// Split-K via gridDim.z.  EPI: 0 = qkv out; 1 = +bias,gelu,fp16;
// 2 = +bias(z0) atomic += xres; 3 = atomic += xres.
#define STAGE_SZ 32768u
template<int EPI>
__global__ void __launch_bounds__(256, 2)
gemm_mma(const __half* __restrict__ Ah, const __half* __restrict__ Bh,
         const float* __restrict__ bias, float* __restrict__ xres,
         __half* __restrict__ Ch, int M, int N, int K)
{
    extern __shared__ char smem[];
    const uint32_t sb0 = smem_u32(smem);
    const int tid  = threadIdx.x;
    const int lane = tid & 31, warp = tid >> 5;
    const int wm = warp >> 1, wn = warp & 1;
    const int bn = blockIdx.x, bm = blockIdx.y;
    const int ksp   = K / (int)gridDim.z;
    const int kbase = blockIdx.z * ksp;
    const int nkt   = ksp >> 6;

    auto load_stage = [&](int kt, int st){
        const uint32_t base = sb0 + (uint32_t)st * STAGE_SZ;
        const size_t kof = (size_t)kbase + (size_t)kt * 64;
#pragma unroll
        for (int i = 0; i < 4; i++) {
            const int idx = tid + i * 256;
            const int row = idx >> 3, c = idx & 7;
            const uint32_t so = (uint32_t)(row * 128 + ((c ^ (row & 7)) << 4));
            const size_t ga = (size_t)(bm * 128 + row) * K + kof + c * 8;
            const size_t gb = (size_t)(bn * 128 + row) * K + kof + c * 8;
            cp16(base + so,          Ah + ga);
            cp16(base + 16384u + so, Bh + gb);
        }
    };

    float acc[2][8][4];
#pragma unroll
    for (int mt = 0; mt < 2; mt++)
#pragma unroll
        for (int nt = 0; nt < 8; nt++)
#pragma unroll
            for (int q = 0; q < 4; q++) acc[mt][nt][q] = 0.f;

    load_stage(0, 0); CP_COMMIT();
    load_stage(1, 1); CP_COMMIT();

    const int arow = wm * 32 + (lane & 15);
    const int acs  = lane >> 4;
    const int brow = wn * 64 + (lane & 7) + ((lane >> 4) << 3);
    const int bcs  = (lane >> 3) & 1;

    for (int kt = 0; kt < nkt; kt++) {
        if (kt == nkt - 1) { CP_WAIT0(); } else { CP_WAIT1(); }
        __syncthreads();
        if (kt + 2 < nkt) { load_stage(kt + 2, (kt + 2) % 3); CP_COMMIT(); }

        const uint32_t base = sb0 + (uint32_t)(kt % 3) * STAGE_SZ;
#pragma unroll
        for (int ks = 0; ks < 4; ks++) {
            uint32_t ah[2][4];
#pragma unroll
            for (int mt = 0; mt < 2; mt++) {
                const int r = arow + mt * 16;
                const int c = ks * 2 + acs;
                const uint32_t off = (uint32_t)(r * 128 + ((c ^ (r & 7)) << 4));
                ldmx4(base + off, ah[mt][0], ah[mt][1], ah[mt][2], ah[mt][3]);
            }
#pragma unroll
            for (int bt = 0; bt < 4; bt++) {
                const int r = brow + bt * 16;
                const int c = ks * 2 + bcs;
                const uint32_t off = (uint32_t)(r * 128 + ((c ^ (r & 7)) << 4));
                uint32_t bh[4];
                ldmx4(base + 16384u + off, bh[0], bh[1], bh[2], bh[3]);
#pragma unroll
                for (int mt = 0; mt < 2; mt++) {
                    mma16816h(acc[mt][2*bt],   ah[mt], bh[0], bh[1]);
                    mma16816h(acc[mt][2*bt+1], ah[mt], bh[2], bh[3]);
                }
            }
        }
        __syncthreads();
    }

    const int rbase = bm * 128 + wm * 32 + (lane >> 2);
    const int cbase = bn * 128 + wn * 64 + (lane & 3) * 2;
    const bool z0 = (blockIdx.z == 0);
#pragma unroll
    for (int mt = 0; mt < 2; mt++) {
#pragma unroll
        for (int nt = 0; nt < 8; nt++) {
            const int gcol = cbase + nt * 8;
#pragma unroll
            for (int h = 0; h < 2; h++) {
                const int grow = rbase + mt * 16 + h * 8;
                float v0 = acc[mt][nt][2*h], v1 = acc[mt][nt][2*h+1];
                const size_t oidx = (size_t)grow * N + gcol;
                if (EPI == 0 || EPI == 1) {
                    if (EPI == 0) {
                        const float sc = (gcol < INNER) ? QSCALE : 1.f;
                        v0 *= sc; v1 *= sc;
                    } else {
                        v0 += bias[gcol];     v1 += bias[gcol + 1];
                        v0 = 0.5f * v0 * (1.f + erff(v0 * 0.70710678118654752f));
                        v1 = 0.5f * v1 * (1.f + erff(v1 * 0.70710678118654752f));
                    }
                    __half h0 = __float2half_rn(v0), h1 = __float2half_rn(v1);
                    *reinterpret_cast<uint32_t*>(Ch + oidx) =
                        (uint32_t)__half_as_ushort(h0) |
                        ((uint32_t)__half_as_ushort(h1) << 16);
                } else {
                    if (EPI == 2 && z0) { v0 += bias[gcol]; v1 += bias[gcol + 1]; }
                    atomicAdd(xres + oidx,     v0);
                    atomicAdd(xres + oidx + 1, v1);
                }
            }
        }
    }
}

// ====================== fp16 1-product flash attention (2 CTAs/SM) =========
// grid (SEQ/128, HEADS, BATCH), 256 threads (8 warps x 16 query rows).
// Softmax: base-2 domain, skip-rescale when warp-wide max unchanged.
#define ATTN_SMEM (16384 + 2*16384)
__global__ void __launch_bounds__(256, 2)
attn_mma(const __half* __restrict__ qkv, __half* __restrict__ ctx)
{
    extern __shared__ char smem[];
    const uint32_t sb = smem_u32(smem);
    const uint32_t QS = sb;
    const int tid = threadIdx.x, lane = tid & 31, wid = tid >> 5;
    const int b = blockIdx.z, h = blockIdx.y, qt = blockIdx.x;
    const int tok0 = b * SEQ + qt * 128;

#pragma unroll
    for (int i = 0; i < 4; i++) {
        const int idx = tid + i * 256;
        const int row = idx >> 3, c = idx & 7;
        const uint32_t so = (uint32_t)(row * 128 + ((c ^ (row & 7)) << 4));
        cp16(QS + so, qkv + (size_t)(tok0 + row) * QKVD + h * DHEAD + c * 8);
    }

    auto load_kv = [&](int t, int st){
        const uint32_t base = sb + 16384u + (uint32_t)st * 16384u;
        const int kv0 = b * SEQ + t * 64;
#pragma unroll
        for (int i = 0; i < 2; i++) {
            const int idx = tid + i * 256;
            const int row = idx >> 3, c = idx & 7;
            const uint32_t so = (uint32_t)(row * 128 + ((c ^ (row & 7)) << 4));
            const size_t gk = (size_t)(kv0 + row) * QKVD + INNER + h * DHEAD + c * 8;
            const size_t gv = (size_t)(kv0 + row) * QKVD + 2 * INNER + h * DHEAD + c * 8;
            cp16(base + so,         qkv + gk);
            cp16(base + 8192u + so, qkv + gv);
        }
    };
    load_kv(0, 0); CP_COMMIT();

    float O[8][4];
#pragma unroll
    for (int nt = 0; nt < 8; nt++)
#pragma unroll
        for (int q = 0; q < 4; q++) O[nt][q] = 0.f;
    float m0 = -1e30f, m1 = -1e30f, l0 = 0.f, l1 = 0.f;
    const int m0row = wid * 16;

    const int NT = SEQ / 64;
    for (int t = 0; t < NT; t++) {
        if (t + 1 < NT) { load_kv(t + 1, (t + 1) & 1); CP_COMMIT(); CP_WAIT1(); }
        else            { CP_WAIT0(); }
        __syncthreads();
        const uint32_t kb = sb + 16384u + (uint32_t)(t & 1) * 16384u;

        float S[8][4];
#pragma unroll
        for (int nt = 0; nt < 8; nt++)
#pragma unroll
            for (int q = 0; q < 4; q++) S[nt][q] = 0.f;
#pragma unroll
        for (int ks = 0; ks < 4; ks++) {
            uint32_t qf[4];
            {
                const int r = m0row + (lane & 15);
                const int c = ks * 2 + (lane >> 4);
                const uint32_t off = (uint32_t)(r * 128 + ((c ^ (r & 7)) << 4));
                ldmx4(QS + off, qf[0], qf[1], qf[2], qf[3]);
            }
#pragma unroll
            for (int bt = 0; bt < 4; bt++) {
                const int r = bt * 16 + (lane & 7) + ((lane >> 4) << 3);
                const int c = ks * 2 + ((lane >> 3) & 1);
                const uint32_t off = (uint32_t)(r * 128 + ((c ^ (r & 7)) << 4));
                uint32_t kh[4];
                ldmx4(kb + off, kh[0], kh[1], kh[2], kh[3]);
                mma16816h(S[2*bt],   qf, kh[0], kh[1]);
                mma16816h(S[2*bt+1], qf, kh[2], kh[3]);
            }
        }

        // ---- online softmax with skip-rescale ----
        float mt0 = -1e30f, mt1 = -1e30f;
#pragma unroll
        for (int nt = 0; nt < 8; nt++) {
            mt0 = fmaxf(mt0, fmaxf(S[nt][0], S[nt][1]));
            mt1 = fmaxf(mt1, fmaxf(S[nt][2], S[nt][3]));
        }
        mt0 = fmaxf(mt0, __shfl_xor_sync(0xffffffffu, mt0, 1));
        mt0 = fmaxf(mt0, __shfl_xor_sync(0xffffffffu, mt0, 2));
        mt1 = fmaxf(mt1, __shfl_xor_sync(0xffffffffu, mt1, 1));
        mt1 = fmaxf(mt1, __shfl_xor_sync(0xffffffffu, mt1, 2));

        const bool chg = __any_sync(0xffffffffu, (mt0 > m0) | (mt1 > m1));
        if (chg) {
            const float mn0 = fmaxf(m0, mt0), mn1 = fmaxf(m1, mt1);
            const float cr0 = exp2_fast(m0 - mn0), cr1 = exp2_fast(m1 - mn1);
            m0 = mn0; m1 = mn1;
            l0 *= cr0; l1 *= cr1;
#pragma unroll
            for (int nt = 0; nt < 8; nt++) {
                O[nt][0] *= cr0; O[nt][1] *= cr0;
                O[nt][2] *= cr1; O[nt][3] *= cr1;
            }
        }

        uint32_t phi[4][4];
        float s0 = 0.f, s1 = 0.f;
#pragma unroll
        for (int nt = 0; nt < 8; nt++) {
            float p0 = exp2_p4(S[nt][0] - m0);
            float p1 = exp2_p4(S[nt][1] - m0);
            float p2 = exp2_p4(S[nt][2] - m1);
            float p3 = exp2_p4(S[nt][3] - m1);
            s0 += p0 + p1; s1 += p2 + p3;
            __half h0 = __float2half_rn(p0), h1 = __float2half_rn(p1);
            __half h2 = __float2half_rn(p2), h3 = __float2half_rn(p3);
            const int t2 = nt >> 1, o = (nt & 1) * 2;
            phi[t2][o] = (uint32_t)__half_as_ushort(h0) |
                         ((uint32_t)__half_as_ushort(h1) << 16);
            phi[t2][o+1] = (uint32_t)__half_as_ushort(h2) |
                           ((uint32_t)__half_as_ushort(h3) << 16);
        }
        s0 += __shfl_xor_sync(0xffffffffu, s0, 1);
        s0 += __shfl_xor_sync(0xffffffffu, s0, 2);
        s1 += __shfl_xor_sync(0xffffffffu, s1, 1);
        s1 += __shfl_xor_sync(0xffffffffu, s1, 2);
        l0 += s0;
        l1 += s1;

#pragma unroll
        for (int t2 = 0; t2 < 4; t2++) {
#pragma unroll
            for (int dn = 0; dn < 4; dn++) {
                const int r = t2 * 16 + (lane & 15);
                const int c = dn * 2 + (lane >> 4);
                const uint32_t off = (uint32_t)(r * 128 + ((c ^ (r & 7)) << 4));
                uint32_t vh[4];
                ldmx4t(kb + 8192u + off, vh[0], vh[1], vh[2], vh[3]);
                mma16816h(O[2*dn],   phi[t2], vh[0], vh[1]);
                mma16816h(O[2*dn+1], phi[t2], vh[2], vh[3]);
            }
        }
        __syncthreads();
    }

    const float i0 = 1.f / l0, i1 = 1.f / l1;
    const int r0 = tok0 + m0row + (lane >> 2);
#pragma unroll
    for (int nt = 0; nt < 8; nt++) {
        const int col = h * DHEAD + nt * 8 + (lane & 3) * 2;
#pragma unroll
        for (int hh = 0; hh < 2; hh++) {
            const float inv = hh ? i1 : i0;
            float v0 = O[nt][2*hh] * inv, v1 = O[nt][2*hh+1] * inv;
            __half h0 = __float2half_rn(v0), h1 = __float2half_rn(v1);
            const size_t oidx = (size_t)(r0 + hh * 8) * DIM + col;
            *reinterpret_cast<uint32_t*>(ctx + oidx) =
                (uint32_t)__half_as_ushort(h0) |
                ((uint32_t)__half_as_ushort(h1) << 16);
        }
    }
}

// ====================== driver =============================================
#define GEMM_SMEM (3 * 32768)

extern "C" void kernel_launch(void* const* d_in, const int* in_sizes, int n_in,
                              void* d_out, int out_size)
{
    const float* x    = (const float*)d_in[0];
    const float* ln1g = (const float*)d_in[1];
    const float* ln1b = (const float*)d_in[2];
    const float* wqkv = (const float*)d_in[3];
    const float* wout = (const float*)d_in[4];
    const float* ln2g = (const float*)d_in[5];
    const float* ln2b = (const float*)d_in[6];
    const float* w1   = (const float*)d_in[7];
    const float* b1   = (const float*)d_in[8];
    const float* w2   = (const float*)d_in[9];
    const float* b2   = (const float*)d_in[10];
    const float* fng  = (const float*)d_in[11];
    const float* fnb  = (const float*)d_in[12];

    float *px;
    __half *pqkv, *pln16, *pct16, *ph16;
    __half *qkvt, *outt, *w1t, *w2t;
    cudaGetSymbolAddress((void**)&px,    g_x);
    cudaGetSymbolAddress((void**)&pqkv,  g_qkv16);
    cudaGetSymbolAddress((void**)&pln16, g_ln16);
    cudaGetSymbolAddress((void**)&pct16, g_ct16);
    cudaGetSymbolAddress((void**)&ph16,  g_h16);
    cudaGetSymbolAddress((void**)&qkvt,  g_wqkvt);
    cudaGetSymbolAddress((void**)&outt,  g_woutt);
    cudaGetSymbolAddress((void**)&w1t,   g_w1t);
    cudaGetSymbolAddress((void**)&w2t,   g_w2t);

    cudaFuncSetAttribute(gemm_mma<0>, cudaFuncAttributeMaxDynamicSharedMemorySize, GEMM_SMEM);
    cudaFuncSetAttribute(gemm_mma<1>, cudaFuncAttributeMaxDynamicSharedMemorySize, GEMM_SMEM);
    cudaFuncSetAttribute(gemm_mma<2>, cudaFuncAttributeMaxDynamicSharedMemorySize, GEMM_SMEM);
    cudaFuncSetAttribute(gemm_mma<3>, cudaFuncAttributeMaxDynamicSharedMemorySize, GEMM_SMEM);
    cudaFuncSetAttribute(attn_mma, cudaFuncAttributeMaxDynamicSharedMemorySize, ATTN_SMEM);

    {
        dim3 tblk(32, 8);
        transpose_cvt<<<dim3(QKVD/32, DIM/32, DEPTH), tblk>>>(wqkv, qkvt, DIM, QKVD);
        transpose_cvt<<<dim3(DIM/32, INNER/32, DEPTH), tblk>>>(wout, outt, INNER, DIM);
        transpose_cvt<<<dim3(MLPD/32, DIM/32, DEPTH), tblk>>>(w1, w1t, DIM, MLPD);
        transpose_cvt<<<dim3(DIM/32, MLPD/32, DEPTH), tblk>>>(w2, w2t, MLPD, DIM);
    }

    cudaMemcpyAsync(px, x, sizeof(float) * (size_t)TOK * DIM,
                    cudaMemcpyDeviceToDevice, 0);

    const dim3 blk256(256);
    for (int i = 0; i < DEPTH; i++) {
        ln_kernel<true><<<TOK/8, blk256>>>(px, ln1g + i*DIM, ln1b + i*DIM,
                                           nullptr, pln16);
        gemm_mma<0><<<dim3(QKVD/128, TOK/128), blk256, GEMM_SMEM>>>(
            pln16, qkvt + (size_t)i*QKVD*DIM,
            nullptr, nullptr, pqkv, TOK, QKVD, DIM);
        attn_mma<<<dim3(SEQ/128, HEADS, BATCH), blk256, ATTN_SMEM>>>(pqkv, pct16);
        gemm_mma<3><<<dim3(DIM/128, TOK/128, 2), blk256, GEMM_SMEM>>>(
            pct16, outt + (size_t)i*DIM*INNER,
            nullptr, px, nullptr, TOK, DIM, INNER);

        ln_kernel<true><<<TOK/8, blk256>>>(px, ln2g + i*DIM, ln2b + i*DIM,
                                           nullptr, pln16);
        gemm_mma<1><<<dim3(MLPD/128, TOK/128), blk256, GEMM_SMEM>>>(
            pln16, w1t + (size_t)i*MLPD*DIM,
            b1 + (size_t)i*MLPD, nullptr, ph16, TOK, MLPD, DIM);
        gemm_mma<2><<<dim3(DIM/128, TOK/128, 2), blk256, GEMM_SMEM>>>(
            ph16, w2t + (size_t)i*DIM*MLPD,
            b2 + (size_t)i*DIM, px, nullptr, TOK, DIM, MLPD);
    }

    ln_kernel<false><<<TOK/8, blk256>>>(px, fng, fnb, (float*)d_out, nullptr);
}